// round 13
// baseline (speedup 1.0000x reference)
#include <cuda_runtime.h>
#include <cuda_bf16.h>
#include <math.h>

// ---------------- problem constants ----------------
#define BATCH   32
#define NTOK    196
#define DMODEL  128
#define ROWS    (BATCH*NTOK) // 6272
#define PDIM    768
#define DEPTH   7
#define KNN_LAYER 6
#define MKEYS   8192
#define TOPK    32
#define FFH     512
#define NCLS    1000
#define SCALE   0.08838834764831845f
#define LNEPS   1e-5f

// ---------------- device scratch ----------------
__device__ float g_p   [ (long)ROWS*PDIM ];
__device__ float g_h   [ (long)ROWS*DMODEL ];
__device__ float g_qkv [ (long)ROWS*3*DMODEL ];
__device__ float g_att [ (long)BATCH*NTOK*NTOK ];
__device__ float g_msim[ (long)BATCH*NTOK*MKEYS ];
__device__ float g_o   [ (long)ROWS*DMODEL ];
__device__ float g_ff  [ (long)ROWS*FFH ];
__device__ float g_part[ (long)6*ROWS*DMODEL ];
__device__ float g_mv  [ (long)ROWS*TOPK ];
__device__ int   g_mi  [ (long)ROWS*TOPK ];
__device__ float g_feats[ BATCH*DMODEL ];
__device__ float g_mu  [ ROWS ];
__device__ float g_rs  [ ROWS ];

// ---------------- helpers ----------------
__device__ __forceinline__ float gelu_tanh(float v) {
    const float c = 0.7978845608028654f;
    float t = tanhf(c * (v + 0.044715f * v * v * v));
    return 0.5f * v * (1.f + t);
}
__device__ __forceinline__ void split_bf16(float v, unsigned short& h, unsigned short& l) {
    __nv_bfloat16 hb = __float2bfloat16_rn(v);
    h = __bfloat16_as_ushort(hb);
    l = __bfloat16_as_ushort(__float2bfloat16_rn(v - __bfloat162float(hb)));
}
__device__ __forceinline__ unsigned f2tf32(float f) {
    unsigned u;
    asm("cvt.rna.tf32.f32 %0, %1;" : "=r"(u) : "f"(f));
    return u;
}
#define MMA_BF16(ACC, A, B)                                                 \
    asm volatile(                                                           \
        "mma.sync.aligned.m16n8k16.row.col.f32.bf16.bf16.f32 "              \
        "{%0,%1,%2,%3}, {%4,%5,%6,%7}, {%8,%9}, {%0,%1,%2,%3};"             \
        : "+f"((ACC)[0]), "+f"((ACC)[1]), "+f"((ACC)[2]), "+f"((ACC)[3])    \
        : "r"((A)[0]), "r"((A)[1]), "r"((A)[2]), "r"((A)[3]),               \
          "r"((B)[0]), "r"((B)[1]))
#define MMA_TF32(ACC, AF, BF)                                              \
    asm volatile(                                                          \
        "mma.sync.aligned.m16n8k8.row.col.f32.tf32.tf32.f32 "              \
        "{%0,%1,%2,%3}, {%4,%5,%6,%7}, {%8,%9}, {%0,%1,%2,%3};"            \
        : "+f"((ACC)[0]), "+f"((ACC)[1]), "+f"((ACC)[2]), "+f"((ACC)[3])   \
        : "r"((AF)[0]), "r"((AF)[1]), "r"((AF)[2]), "r"((AF)[3]),          \
          "r"((BF)[0]), "r"((BF)[1]))
#define LDSM4(R0,R1,R2,R3, ADDR)                                            \
    asm volatile("ldmatrix.sync.aligned.m8n8.x4.shared.b16 {%0,%1,%2,%3}, [%4];" \
        : "=r"(R0), "=r"(R1), "=r"(R2), "=r"(R3) : "r"(ADDR))
#define LDSM4T(R0,R1,R2,R3, ADDR)                                           \
    asm volatile("ldmatrix.sync.aligned.m8n8.x4.trans.shared.b16 {%0,%1,%2,%3}, [%4];" \
        : "=r"(R0), "=r"(R1), "=r"(R2), "=r"(R3) : "r"(ADDR))

// ---------------- patchify ----------------
__global__ void patchify_k(const float* __restrict__ x, float* __restrict__ p) {
    long e = (long)blockIdx.x * 256 + threadIdx.x;
    if (e >= (long)ROWS * PDIM) return;
    int c   = (int)(e % PDIM);
    long row = e / PDIM;
    int b = (int)(row / NTOK), n = (int)(row % NTOK);
    int i = n / 14, j = n % 14;
    int ch = c / 256, r = c % 256, pi = r / 16, pj = r % 16;
    p[e] = x[(((long)b*3 + ch)*224 + (i*16 + pi))*224 + (j*16 + pj)];
}

// ---------------- bf16 split-2 mma GEMM (R9 core) ----------------
#define A_PITCH_B 80
#define BTB_PITCH_B 80
#define BNN_PITCH_B 272
#define AL_OFF 5120
#define BH_OFF 10240
#define BL_OFF 20480
#define STAGE_B 30720
#define SMEM2 (2*STAGE_B)

template<bool TB, bool DOGELU, bool LNA, bool STATS>
__global__ void __launch_bounds__(256, 2)
mmabf_k(const float* __restrict__ A, const float* __restrict__ Bm,
        const float* __restrict__ bias, const float* __restrict__ Res,
        float* __restrict__ C,
        int Mr, int Nc, int K,
        long sAb, int lda, long sBb, int ldb, long sCb, int ldc,
        float alpha, int nbatch, int kslices, long sPart,
        const float* __restrict__ muA, const float* __restrict__ rsA,
        const float* __restrict__ lngA, const float* __restrict__ lnbA,
        float* __restrict__ muO, float* __restrict__ rsO)
{
    extern __shared__ char smem_c[];
    unsigned sbase = (unsigned)__cvta_generic_to_shared(smem_c);

    int bz = blockIdx.z;
    int batch = bz % nbatch;
    int ksl   = bz / nbatch;
    int Kslice = K / kslices;
    int Klo = ksl * Kslice;
    int Khi = (ksl == kslices - 1) ? K : Klo + Kslice;

    const float* Ab = A + (long)batch * sAb;
    const float* Bb = Bm + (long)batch * sBb;
    float*       Cb;
    const float* Rb;
    if (kslices > 1) {
        Cb = C + (long)ksl * sPart + (long)batch * sCb;
        Rb = nullptr;
    } else {
        Cb = C + (long)batch * sCb;
        Rb = Res ? (Res + (long)batch * sCb) : nullptr;
    }

    int row0 = blockIdx.y * 64;
    int col0 = blockIdx.x * 128;
    int tid = threadIdx.x;
    int lane = tid & 31, warp = tid >> 5;
    int wm = warp >> 2, wn = warp & 3;
    int g = lane >> 2, tg = lane & 3;

    int ar = tid >> 3, ak = (tid & 7) * 4;
    int bkNN = tid >> 5, bnNN = (tid & 31) * 4;
    int bnTB = tid >> 3, bkTB = (tid & 7) * 4;

    float4 pa[2], pb[4];

    auto loadA = [&](int k0) {
        #pragma unroll
        for (int p = 0; p < 2; p++) {
            int gr = row0 + ar + p * 32, gk = k0 + ak;
            float4 v = make_float4(0.f, 0.f, 0.f, 0.f);
            if (gr < Mr) {
                if (gk + 3 < Khi) {
                    v = *(const float4*)&Ab[(long)gr * lda + gk];
                    if (LNA) {
                        float mu = __ldg(&muA[gr]);
                        float rs = __ldg(&rsA[gr]);
                        float4 gg = *(const float4*)&lngA[gk];
                        float4 bb = *(const float4*)&lnbA[gk];
                        v.x = (v.x - mu) * rs * gg.x + bb.x;
                        v.y = (v.y - mu) * rs * gg.y + bb.y;
                        v.z = (v.z - mu) * rs * gg.z + bb.z;
                        v.w = (v.w - mu) * rs * gg.w + bb.w;
                    }
                } else {
                    if (gk + 0 < Khi) v.x = Ab[(long)gr * lda + gk + 0];
                    if (gk + 1 < Khi) v.y = Ab[(long)gr * lda + gk + 1];
                    if (gk + 2 < Khi) v.z = Ab[(long)gr * lda + gk + 2];
                    if (gk + 3 < Khi) v.w = Ab[(long)gr * lda + gk + 3];
                }
            }
            pa[p] = v;
        }
    };
    auto loadB = [&](int k0) {
        if (TB) {
            #pragma unroll
            for (int p = 0; p < 4; p++) {
                int gn = col0 + bnTB + p * 32, gk = k0 + bkTB;
                float4 v = make_float4(0.f, 0.f, 0.f, 0.f);
                if (gn < Nc) {
                    if (gk + 3 < Khi) v = *(const float4*)&Bb[(long)gn * ldb + gk];
                    else {
                        if (gk + 0 < Khi) v.x = Bb[(long)gn * ldb + gk + 0];
                        if (gk + 1 < Khi) v.y = Bb[(long)gn * ldb + gk + 1];
                        if (gk + 2 < Khi) v.z = Bb[(long)gn * ldb + gk + 2];
                        if (gk + 3 < Khi) v.w = Bb[(long)gn * ldb + gk + 3];
                    }
                }
                pb[p] = v;
            }
        } else {
            #pragma unroll
            for (int p = 0; p < 4; p++) {
                int gk = k0 + bkNN + p * 8, gn = col0 + bnNN;
                float4 v = make_float4(0.f, 0.f, 0.f, 0.f);
                if (gk < Khi) {
                    if (gn + 3 < Nc) v = *(const float4*)&Bb[(long)gk * ldb + gn];
                    else {
                        if (gn + 0 < Nc) v.x = Bb[(long)gk * ldb + gn + 0];
                        if (gn + 1 < Nc) v.y = Bb[(long)gk * ldb + gn + 1];
                        if (gn + 2 < Nc) v.z = Bb[(long)gk * ldb + gn + 2];
                        if (gn + 3 < Nc) v.w = Bb[(long)gk * ldb + gn + 3];
                    }
                }
                pb[p] = v;
            }
        }
    };
    auto storeTiles = [&](int st) {
        char* sb = smem_c + st * STAGE_B;
        #pragma unroll
        for (int p = 0; p < 2; p++) {
            int r = ar + p * 32;
            float vv[4] = {pa[p].x, pa[p].y, pa[p].z, pa[p].w};
            unsigned short h[4], l[4];
            #pragma unroll
            for (int j = 0; j < 4; j++) split_bf16(vv[j], h[j], l[j]);
            *(uint2*)(sb + r * A_PITCH_B + ak * 2) =
                make_uint2(((unsigned)h[1] << 16) | h[0], ((unsigned)h[3] << 16) | h[2]);
            *(uint2*)(sb + AL_OFF + r * A_PITCH_B + ak * 2) =
                make_uint2(((unsigned)l[1] << 16) | l[0], ((unsigned)l[3] << 16) | l[2]);
        }
        if (TB) {
            #pragma unroll
            for (int p = 0; p < 4; p++) {
                int n = bnTB + p * 32;
                float vv[4] = {pb[p].x, pb[p].y, pb[p].z, pb[p].w};
                unsigned short h[4], l[4];
                #pragma unroll
                for (int j = 0; j < 4; j++) split_bf16(vv[j], h[j], l[j]);
                *(uint2*)(sb + BH_OFF + n * BTB_PITCH_B + bkTB * 2) =
                    make_uint2(((unsigned)h[1] << 16) | h[0], ((unsigned)h[3] << 16) | h[2]);
                *(uint2*)(sb + BL_OFF + n * BTB_PITCH_B + bkTB * 2) =
                    make_uint2(((unsigned)l[1] << 16) | l[0], ((unsigned)l[3] << 16) | l[2]);
            }
        } else {
            #pragma unroll
            for (int p = 0; p < 4; p++) {
                int k = bkNN + p * 8;
                float vv[4] = {pb[p].x, pb[p].y, pb[p].z, pb[p].w};
                unsigned short h[4], l[4];
                #pragma unroll
                for (int j = 0; j < 4; j++) split_bf16(vv[j], h[j], l[j]);
                *(uint2*)(sb + BH_OFF + k * BNN_PITCH_B + bnNN * 2) =
                    make_uint2(((unsigned)h[1] << 16) | h[0], ((unsigned)h[3] << 16) | h[2]);
                *(uint2*)(sb + BL_OFF + k * BNN_PITCH_B + bnNN * 2) =
                    make_uint2(((unsigned)l[1] << 16) | l[0], ((unsigned)l[3] << 16) | l[2]);
            }
        }
    };

    float acc[2][4][4];
    #pragma unroll
    for (int im = 0; im < 2; im++)
        #pragma unroll
        for (int jn = 0; jn < 4; jn++)
            #pragma unroll
            for (int c = 0; c < 4; c++) acc[im][jn][c] = 0.f;

    int nch = (Khi - Klo + 31) / 32;
    int stage = 0;

    loadA(Klo); loadB(Klo);
    storeTiles(0);
    __syncthreads();

    for (int c = 0; c < nch; c++) {
        if (c + 1 < nch) { loadA(Klo + (c + 1) * 32); loadB(Klo + (c + 1) * 32); }

        unsigned stb = sbase + stage * STAGE_B;
        #pragma unroll
        for (int ks2 = 0; ks2 < 2; ks2++) {
            int ksb = ks2 * 32;
            unsigned ah[2][4], al_[2][4];
            #pragma unroll
            for (int im = 0; im < 2; im++) {
                unsigned aaddr = stb
                    + (unsigned)((wm * 32 + im * 16 + (lane & 15)) * A_PITCH_B
                                 + ((lane >> 4) * 16) + ksb);
                LDSM4(ah[im][0], ah[im][1], ah[im][2], ah[im][3], aaddr);
                LDSM4(al_[im][0], al_[im][1], al_[im][2], al_[im][3], aaddr + AL_OFF);
            }
            unsigned bh[4][2], bl_[4][2];
            #pragma unroll
            for (int pr = 0; pr < 2; pr++) {
                int nb2 = wn * 32 + pr * 16;
                unsigned baddr;
                if (TB) {
                    baddr = stb + BH_OFF
                        + (unsigned)((nb2 + ((lane >> 4) << 3) + (lane & 7)) * BTB_PITCH_B
                                     + (((lane >> 3) & 1) * 16) + ksb);
                } else {
                    baddr = stb + BH_OFF
                        + (unsigned)((ks2 * 16 + ((lane >> 3) & 1) * 8 + (lane & 7)) * BNN_PITCH_B
                                     + (nb2 + (lane >> 4) * 8) * 2);
                }
                unsigned r0, r1, r2, r3;
                if (TB) { LDSM4(r0, r1, r2, r3, baddr); }
                else    { LDSM4T(r0, r1, r2, r3, baddr); }
                bh[2*pr][0] = r0; bh[2*pr][1] = r1; bh[2*pr+1][0] = r2; bh[2*pr+1][1] = r3;
                unsigned laddr = baddr + (BL_OFF - BH_OFF);
                if (TB) { LDSM4(r0, r1, r2, r3, laddr); }
                else    { LDSM4T(r0, r1, r2, r3, laddr); }
                bl_[2*pr][0] = r0; bl_[2*pr][1] = r1; bl_[2*pr+1][0] = r2; bl_[2*pr+1][1] = r3;
            }
            #pragma unroll
            for (int im = 0; im < 2; im++)
                #pragma unroll
                for (int jn = 0; jn < 4; jn++) {
                    MMA_BF16(acc[im][jn], ah[im], bl_[jn]);
                    MMA_BF16(acc[im][jn], al_[im], bh[jn]);
                    MMA_BF16(acc[im][jn], ah[im], bh[jn]);
                }
        }

        if (c + 1 < nch) {
            storeTiles(stage ^ 1);
            __syncthreads();
            stage ^= 1;
        }
    }

    // ---- epilogue
    float st1[2][2], st2[2][2];
    if (STATS) {
        #pragma unroll
        for (int im = 0; im < 2; im++)
            #pragma unroll
            for (int hh = 0; hh < 2; hh++) { st1[im][hh] = 0.f; st2[im][hh] = 0.f; }
    }
    #pragma unroll
    for (int im = 0; im < 2; im++) {
        #pragma unroll
        for (int jn = 0; jn < 4; jn++) {
            int r0 = row0 + wm * 32 + im * 16 + g;
            int c0 = col0 + wn * 32 + jn * 8 + 2 * tg;
            #pragma unroll
            for (int half = 0; half < 2; half++) {
                int gr = r0 + half * 8;
                if (gr >= Mr) continue;
                #pragma unroll
                for (int cc = 0; cc < 2; cc++) {
                    int gn = c0 + cc;
                    if (gn >= Nc) continue;
                    float v = acc[im][jn][half * 2 + cc] * alpha;
                    if (kslices == 1) {
                        if (bias) v += bias[gn];
                        if (Rb)   v += Rb[(long)gr * ldc + gn];
                        if (DOGELU) v = gelu_tanh(v);
                    }
                    if (STATS) { st1[im][half] += v; st2[im][half] += v * v; }
                    Cb[(long)gr * ldc + gn] = v;
                }
            }
        }
    }
    if (STATS) {
        __syncthreads();
        float* s1 = (float*)smem_c;
        float* s2 = s1 + 256;
        #pragma unroll
        for (int im = 0; im < 2; im++)
            #pragma unroll
            for (int hh = 0; hh < 2; hh++) {
                float x1 = st1[im][hh], x2 = st2[im][hh];
                x1 += __shfl_xor_sync(0xffffffffu, x1, 1);
                x1 += __shfl_xor_sync(0xffffffffu, x1, 2);
                x2 += __shfl_xor_sync(0xffffffffu, x2, 1);
                x2 += __shfl_xor_sync(0xffffffffu, x2, 2);
                if (tg == 0) {
                    int lr = wm * 32 + im * 16 + g + hh * 8;
                    s1[wn * 64 + lr] = x1;
                    s2[wn * 64 + lr] = x2;
                }
            }
        __syncthreads();
        if (tid < 64) {
            float t1 = s1[tid] + s1[64 + tid] + s1[128 + tid] + s1[192 + tid];
            float t2 = s2[tid] + s2[64 + tid] + s2[128 + tid] + s2[192 + tid];
            float mu = t1 * (1.f / 128.f);
            float var = t2 * (1.f / 128.f) - mu * mu;
            muO[row0 + tid] = mu;
            rsO[row0 + tid] = rsqrtf(var + LNEPS);
        }
    }
}

// ============================================================================
// msim: 1xTF32 2-stage pipelined GEMM (R7-verified layout). TB, alpha=SCALE.
// smem per stage: Ah[64*36] + Bh[32*136] words = 26624 B; x2 = 53248 B.
// ============================================================================
#define TAPAD 36
#define TBPAD 136
#define TWORDS (64*TAPAD + 32*TBPAD)
#define SMEMT (TWORDS * 8)

__global__ void __launch_bounds__(256, 2)
msimtf_k(const float* __restrict__ A, const float* __restrict__ Bm,
         float* __restrict__ C)
{
    extern __shared__ unsigned smem_u[];

    int batch = blockIdx.z;
    const float* Ab = A + (long)batch * NTOK * 384;           // q, stride 384
    const float* Bb = Bm + (long)batch * MKEYS * DMODEL;      // knn_k
    float*       Cb = C + (long)batch * NTOK * MKEYS;

    int row0 = blockIdx.y * 64;
    int col0 = blockIdx.x * 128;
    int tid = threadIdx.x;
    int lane = tid & 31, warp = tid >> 5;
    int wm = warp >> 2, wn = warp & 3;
    int g = lane >> 2, tg = lane & 3;

    int ar = tid >> 3, ak = (tid & 7) * 4;        // A: rows ar, ar+32
    int bnTB = tid >> 3, bkTB = (tid & 7) * 4;    // B: n rows bnTB+32p

    float4 pa[2], pb[4];

    auto loadA = [&](int k0) {
        #pragma unroll
        for (int p = 0; p < 2; p++) {
            int gr = row0 + ar + p * 32, gk = k0 + ak;
            float4 v = make_float4(0.f, 0.f, 0.f, 0.f);
            if (gr < NTOK) v = *(const float4*)&Ab[(long)gr * 384 + gk];
            pa[p] = v;
        }
    };
    auto loadB = [&](int k0) {
        #pragma unroll
        for (int p = 0; p < 4; p++) {
            int gn = col0 + bnTB + p * 32, gk = k0 + bkTB;
            pb[p] = *(const float4*)&Bb[(long)gn * DMODEL + gk];
        }
    };
    auto storeTiles = [&](int st) {
        unsigned* Ah = smem_u + st * TWORDS;
        unsigned* Bh = Ah + 64 * TAPAD;
        #pragma unroll
        for (int p = 0; p < 2; p++) {
            int r = ar + p * 32;
            Ah[r * TAPAD + ak + 0] = f2tf32(pa[p].x);
            Ah[r * TAPAD + ak + 1] = f2tf32(pa[p].y);
            Ah[r * TAPAD + ak + 2] = f2tf32(pa[p].z);
            Ah[r * TAPAD + ak + 3] = f2tf32(pa[p].w);
        }
        #pragma unroll
        for (int p = 0; p < 4; p++) {
            int n = bnTB + p * 32;
            Bh[(bkTB + 0) * TBPAD + n] = f2tf32(pb[p].x);
            Bh[(bkTB + 1) * TBPAD + n] = f2tf32(pb[p].y);
            Bh[(bkTB + 2) * TBPAD + n] = f2tf32(pb[p].z);
            Bh[(bkTB + 3) * TBPAD + n] = f2tf32(pb[p].w);
        }
    };

    float acc[2][4][4];
    #pragma unroll
    for (int im = 0; im < 2; im++)
        #pragma unroll
        for (int jn = 0; jn < 4; jn++)
            #pragma unroll
            for (int c = 0; c < 4; c++) acc[im][jn][c] = 0.f;

    int stage = 0;
    loadA(0); loadB(0);
    storeTiles(0);
    __syncthreads();

    for (int c = 0; c < 4; c++) {               // K=128 in 4 chunks of 32
        if (c + 1 < 4) { loadA((c + 1) * 32); loadB((c + 1) * 32); }

        unsigned* Ah = smem_u + stage * TWORDS;
        unsigned* Bh = Ah + 64 * TAPAD;
        #pragma unroll
        for (int ks = 0; ks < 32; ks += 8) {
            unsigned af[2][4], bf[4][2];
            #pragma unroll
            for (int im = 0; im < 2; im++) {
                int mb = wm * 32 + im * 16;
                af[im][0] = Ah[(mb + g    ) * TAPAD + ks +     tg];
                af[im][1] = Ah[(mb + g + 8) * TAPAD + ks +     tg];
                af[im][2] = Ah[(mb + g    ) * TAPAD + ks + 4 + tg];
                af[im][3] = Ah[(mb + g + 8) * TAPAD + ks + 4 + tg];
            }
            #pragma unroll
            for (int jn = 0; jn < 4; jn++) {
                int nb = wn * 32 + jn * 8;
                bf[jn][0] = Bh[(ks +     tg) * TBPAD + nb + g];
                bf[jn][1] = Bh[(ks + 4 + tg) * TBPAD + nb + g];
            }
            #pragma unroll
            for (int im = 0; im < 2; im++)
                #pragma unroll
                for (int jn = 0; jn < 4; jn++)
                    MMA_TF32(acc[im][jn], af[im], bf[jn]);
        }

        if (c + 1 < 4) {
            storeTiles(stage ^ 1);
            __syncthreads();
            stage ^= 1;
        }
    }

    #pragma unroll
    for (int im = 0; im < 2; im++) {
        #pragma unroll
        for (int jn = 0; jn < 4; jn++) {
            int r0 = row0 + wm * 32 + im * 16 + g;
            int c0 = col0 + wn * 32 + jn * 8 + 2 * tg;
            #pragma unroll
            for (int half = 0; half < 2; half++) {
                int gr = r0 + half * 8;
                if (gr >= NTOK) continue;
                Cb[(long)gr * MKEYS + c0    ] = acc[im][jn][half * 2 + 0] * SCALE;
                Cb[(long)gr * MKEYS + c0 + 1] = acc[im][jn][half * 2 + 1] * SCALE;
            }
        }
    }
}

// ============================================================================
// Fused softmax + av GEMM (R12-verified).
// ============================================================================
#define SATT_PITCH 204
#define SMEM_AV (SMEM2 + 64*SATT_PITCH*4)

__global__ void __launch_bounds__(256)
mmasav_k(const float* __restrict__ Att, const float* __restrict__ Bm,
         float* __restrict__ C, int nbatch)
{
    extern __shared__ char smem_c[];
    unsigned sbase = (unsigned)__cvta_generic_to_shared(smem_c);
    float* satt = (float*)(smem_c + SMEM2);

    int batch = blockIdx.z % nbatch;
    const float* Ab = Att + (long)batch * NTOK * NTOK;
    const float* Bb = Bm + (long)batch * NTOK * 384;
    float*       Cb = C + (long)batch * NTOK * DMODEL;

    int row0 = blockIdx.y * 64;
    int tid = threadIdx.x;
    int lane = tid & 31, warp = tid >> 5;
    int wm = warp >> 2, wn = warp & 3;
    int g = lane >> 2, tg = lane & 3;

    for (int idx = tid; idx < 64 * NTOK; idx += 256) {
        int r = idx / NTOK, c = idx % NTOK;
        int gr = row0 + r;
        satt[r * SATT_PITCH + c] = (gr < NTOK) ? Ab[(long)gr * NTOK + c] : 0.f;
    }
    __syncthreads();

    {
        int r = tid >> 2, part = tid & 3;
        float* rowp = satt + r * SATT_PITCH;
        float mx = -3.4e38f;
        for (int c = part; c < NTOK; c += 4) mx = fmaxf(mx, rowp[c]);
        mx = fmaxf(mx, __shfl_xor_sync(0xffffffffu, mx, 1));
        mx = fmaxf(mx, __shfl_xor_sync(0xffffffffu, mx, 2));
        float sum = 0.f;
        for (int c = part; c < NTOK; c += 4) {
            float e = expf(rowp[c] - mx);
            rowp[c] = e;
            sum += e;
        }
        sum += __shfl_xor_sync(0xffffffffu, sum, 1);
        sum += __shfl_xor_sync(0xffffffffu, sum, 2);
        float inv = 1.f / sum;
        for (int c = part; c < NTOK; c += 4) rowp[c] *= inv;
    }
    __syncthreads();

    int ar = tid >> 3, ak = (tid & 7) * 4;
    int bkNN = tid >> 5, bnNN = (tid & 31) * 4;
    const int K = NTOK, Nc = DMODEL;

    float4 pa[2], pb[4];

    auto loadA = [&](int k0) {
        #pragma unroll
        for (int p = 0; p < 2; p++) {
            int r = ar + p * 32, gk = k0 + ak;
            float4 v = make_float4(0.f, 0.f, 0.f, 0.f);
            if (gk + 3 < K) {
                v = *(const float4*)&satt[r * SATT_PITCH + gk];
            } else {
                if (gk + 0 < K) v.x = satt[r * SATT_PITCH + gk + 0];
                if (gk + 1 < K) v.y = satt[r * SATT_PITCH + gk + 1];
                if (gk + 2 < K) v.z = satt[r * SATT_PITCH + gk + 2];
                if (gk + 3 < K) v.w = satt[r * SATT_PITCH + gk + 3];
            }
            pa[p] = v;
        }
    };
    auto loadB = [&](int k0) {
        #pragma unroll
        for (int p = 0; p < 4; p++) {
            int gk = k0 + bkNN + p * 8, gn = bnNN;
            float4 v = make_float4(0.f, 0.f, 0.f, 0.f);
            if (gk < K && gn + 3 < Nc)
                v = *(const float4*)&Bb[(long)gk * 384 + gn];
            pb[p] = v;
        }
    };
    auto storeTiles = [&](int st) {
        char* sb = smem_c + st * STAGE_B;
        #pragma unroll
        for (int p = 0; p < 2; p++) {
            int r = ar + p * 32;
            float vv[4] = {pa[p].x, pa[p].y, pa[p].z, pa[p].w};
            unsigned short h[4], l[4];
            #pragma unroll
            for (int j = 0; j < 4; j++) split_bf16(vv[j], h[j], l[j]);
            *(uint2*)(sb + r * A_PITCH_B + ak * 2) =
                make_uint2(((unsigned)h[1] << 16) | h[0], ((unsigned)h[3] << 16) | h[2]);
            *(uint2*)(sb + AL_OFF + r * A_PITCH_B + ak * 2) =
                make_uint2(((unsigned)l[1] << 16) | l[0], ((unsigned)l[3] << 16) | l[2]);
        }
        #pragma unroll
        for (int p = 0; p < 4; p++) {
            int k = bkNN + p * 8;
            float vv[4] = {pb[p].x, pb[p].y, pb[p].z, pb[p].w};
            unsigned short h[4], l[4];
            #pragma unroll
            for (int j = 0; j < 4; j++) split_bf16(vv[j], h[j], l[j]);
            *(uint2*)(sb + BH_OFF + k * BNN_PITCH_B + bnNN * 2) =
                make_uint2(((unsigned)h[1] << 16) | h[0], ((unsigned)h[3] << 16) | h[2]);
            *(uint2*)(sb + BL_OFF + k * BNN_PITCH_B + bnNN * 2) =
                make_uint2(((unsigned)l[1] << 16) | l[0], ((unsigned)l[3] << 16) | l[2]);
        }
    };

    float acc[2][4][4];
    #pragma unroll
    for (int im = 0; im < 2; im++)
        #pragma unroll
        for (int jn = 0; jn < 4; jn++)
            #pragma unroll
            for (int c = 0; c < 4; c++) acc[im][jn][c] = 0.f;

    int nch = (K + 31) / 32;
    int stage = 0;

    loadA(0); loadB(0);
    storeTiles(0);
    __syncthreads();

    for (int c = 0; c < nch; c++) {
        if (c + 1 < nch) { loadA((c + 1) * 32); loadB((c + 1) * 32); }

        unsigned stb = sbase + stage * STAGE_B;
        #pragma unroll
        for (int ks2 = 0; ks2 < 2; ks2++) {
            int ksb = ks2 * 32;
            unsigned ah[2][4], al_[2][4];
            #pragma unroll
            for (int im = 0; im < 2; im++) {
                unsigned aaddr = stb
                    + (unsigned)((wm * 32 + im * 16 + (lane & 15)) * A_PITCH_B
                                 + ((lane >> 4) * 16) + ksb);
                LDSM4(ah[im][0], ah[im][1], ah[im][2], ah[im][3], aaddr);
                LDSM4(al_[im][0], al_[im][1], al_[im][2], al_[im][3], aaddr + AL_OFF);
            }
            unsigned bh[4][2], bl_[4][2];
            #pragma unroll
            for (int pr = 0; pr < 2; pr++) {
                int nb2 = wn * 32 + pr * 16;
                unsigned baddr = stb + BH_OFF
                    + (unsigned)((ks2 * 16 + ((lane >> 3) & 1) * 8 + (lane & 7)) * BNN_PITCH_B
                                 + (nb2 + (lane >> 4) * 8) * 2);
                unsigned r0, r1, r2, r3;
                LDSM4T(r0, r1, r2, r3, baddr);
                bh[2*pr][0] = r0; bh[2*pr][1] = r1; bh[2*pr+1][0] = r2; bh[2*pr+1][1] = r3;
                LDSM4T(r0, r1, r2, r3, baddr + (BL_OFF - BH_OFF));
                bl_[2*pr][0] = r0; bl_[2*pr][1] = r1; bl_[2*pr+1][0] = r2; bl_[2*pr+1][1] = r3;
            }
            #pragma unroll
            for (int im = 0; im < 2; im++)
                #pragma unroll
                for (int jn = 0; jn < 4; jn++) {
                    MMA_BF16(acc[im][jn], ah[im], bl_[jn]);
                    MMA_BF16(acc[im][jn], al_[im], bh[jn]);
                    MMA_BF16(acc[im][jn], ah[im], bh[jn]);
                }
        }

        if (c + 1 < nch) {
            storeTiles(stage ^ 1);
            __syncthreads();
            stage ^= 1;
        }
    }

    #pragma unroll
    for (int im = 0; im < 2; im++) {
        #pragma unroll
        for (int jn = 0; jn < 4; jn++) {
            int r0 = row0 + wm * 32 + im * 16 + g;
            int c0 = wn * 32 + jn * 8 + 2 * tg;
            #pragma unroll
            for (int half = 0; half < 2; half++) {
                int gr = r0 + half * 8;
                if (gr >= NTOK) continue;
                #pragma unroll
                for (int cc = 0; cc < 2; cc++) {
                    int gn = c0 + cc;
                    Cb[(long)gr * DMODEL + gn] = acc[im][jn][half * 2 + cc];
                }
            }
        }
    }
}

// ---------------- split-K reduce + LN stats ----------------
__global__ void reduce_stats_k(const float* __restrict__ part, long sstride, int ns,
                               const float* __restrict__ bias, const float* __restrict__ res,
                               float* __restrict__ out,
                               float* __restrict__ mu, float* __restrict__ rstd)
{
    long row = blockIdx.x;
    int d = threadIdx.x;
    long idx = row * DMODEL + d;
    float s = 0.f;
    for (int k = 0; k < ns; k++) s += part[(long)k * sstride + idx];
    s += bias[d];
    if (res) s += res[idx];
    out[idx] = s;
    __shared__ float r1[4], r2[4];
    float v1 = s, v2 = s * s;
    #pragma unroll
    for (int o = 16; o > 0; o >>= 1) {
        v1 += __shfl_xor_sync(0xffffffffu, v1, o);
        v2 += __shfl_xor_sync(0xffffffffu, v2, o);
    }
    if ((d & 31) == 0) { r1[d >> 5] = v1; r2[d >> 5] = v2; }
    __syncthreads();
    if (d == 0) {
        float t1 = r1[0] + r1[1] + r1[2] + r1[3];
        float t2 = r2[0] + r2[1] + r2[2] + r2[3];
        float m = t1 * (1.f / 128.f);
        float var = t2 * (1.f / 128.f) - m * m;
        mu[row] = m;
        rstd[row] = rsqrtf(var + LNEPS);
    }
}

// ---------------- final LN + mean pool fused ----------------
__global__ void feats_k(const float* __restrict__ h, const float* __restrict__ mu,
                        const float* __restrict__ rstd,
                        const float* __restrict__ g, const float* __restrict__ b,
                        float* __restrict__ feats)
{
    int bb = blockIdx.x, d = threadIdx.x;
    float gd = g[d], bd = b[d];
    float s = 0.f;
    for (int n = 0; n < NTOK; n++) {
        long row = (long)bb * NTOK + n;
        s += (h[row * DMODEL + d] - mu[row]) * rstd[row] * gd + bd;
    }
    feats[bb * DMODEL + d] = s * (1.f / 196.f);
}

// ---------------- top-32: register-resident incremental argmax ----------------
__global__ void __launch_bounds__(256) topk_k(const float* __restrict__ msim,
                       float* __restrict__ mvals, int* __restrict__ midx)
{
    long row = blockIdx.x;
    int tid = threadIdx.x;
    int lane = tid & 31, wid = tid >> 5;
    const float* src = msim + row * MKEYS;

    float v[32];
    const float4* s4 = (const float4*)(src + tid * 32);
    #pragma unroll
    for (int i = 0; i < 8; i++) {
        float4 t = s4[i];
        v[i*4+0] = t.x; v[i*4+1] = t.y; v[i*4+2] = t.z; v[i*4+3] = t.w;
    }

    unsigned long long p = 0ull;
    #pragma unroll
    for (int i = 0; i < 32; i++) {
        unsigned u = __float_as_uint(v[i]);
        u = (u & 0x80000000u) ? ~u : (u | 0x80000000u);
        unsigned long long key = ((unsigned long long)u << 32) | (unsigned)(MKEYS - 1 - (tid * 32 + i));
        if (key > p) p = key;
    }

    __shared__ unsigned long long wmax[2][8];

    for (int it = 0; it < TOPK; it++) {
        unsigned long long q = p;
        #pragma unroll
        for (int o = 16; o > 0; o >>= 1) {
            unsigned long long other = __shfl_xor_sync(0xffffffffu, q, o);
            if (other > q) q = other;
        }
        if (lane == 0) wmax[it & 1][wid] = q;
        __syncthreads();
        unsigned long long best = wmax[it & 1][0];
        #pragma unroll
        for (int w = 1; w < 8; w++) {
            unsigned long long o2 = wmax[it & 1][w];
            if (o2 > best) best = o2;
        }
        int gidx = MKEYS - 1 - (int)(best & 0xffffffffu);
        if (tid == (gidx >> 5)) {
            int sub = gidx & 31;
            float bv = 0.f;
            #pragma unroll
            for (int i = 0; i < 32; i++)
                if (i == sub) { bv = v[i]; v[i] = -3.4e38f; }
            mvals[row * TOPK + it] = bv;
            midx [row * TOPK + it] = gidx;
            unsigned long long np = 0ull;
            #pragma unroll
            for (int i = 0; i < 32; i++) {
                unsigned u = __float_as_uint(v[i]);
                u = (u & 0x80000000u) ? ~u : (u | 0x80000000u);
                unsigned long long key = ((unsigned long long)u << 32) | (unsigned)(MKEYS - 1 - (tid * 32 + i));
                if (key > np) np = key;
            }
            p = np;
        }
    }
}

// ---------------- kNN combine ----------------
__global__ void knn_combine_k(const float* __restrict__ att,
                              const float* __restrict__ mvals, const int* __restrict__ midx,
                              const float* __restrict__ qkv, const float* __restrict__ knn_v,
                              float* __restrict__ out)
{
    long row = blockIdx.x;
    int b = (int)(row / NTOK);
    int tid = threadIdx.x;
    __shared__ float w[TOPK + NTOK];
    __shared__ int   sidx[TOPK];
    __shared__ float red[4];

    if (tid < TOPK) {
        w[tid]    = mvals[row * TOPK + tid];
        sidx[tid] = midx [row * TOPK + tid];
    }
    for (int m = tid; m < NTOK; m += 128) w[TOPK + m] = att[row * NTOK + m];
    __syncthreads();

    float l0 = w[tid];
    float l1 = (tid < (TOPK + NTOK - 128)) ? w[tid + 128] : -3.4e38f;
    float m = fmaxf(l0, l1);
    #pragma unroll
    for (int o = 16; o > 0; o >>= 1) m = fmaxf(m, __shfl_xor_sync(0xffffffffu, m, o));
    if ((tid & 31) == 0) red[tid >> 5] = m;
    __syncthreads();
    m = fmaxf(fmaxf(red[0], red[1]), fmaxf(red[2], red[3]));
    float e0 = expf(l0 - m);
    float e1 = (tid < (TOPK + NTOK - 128)) ? expf(l1 - m) : 0.f;
    float s = e0 + e1;
    __syncthreads();
    #pragma unroll
    for (int o = 16; o > 0; o >>= 1) s += __shfl_xor_sync(0xffffffffu, s, o);
    if ((tid & 31) == 0) red[tid >> 5] = s;
    __syncthreads();
    s = red[0] + red[1] + red[2] + red[3];
    float inv = 1.f / s;
    w[tid] = e0 * inv;
    if (tid < (TOPK + NTOK - 128)) w[tid + 128] = e1 * inv;
    __syncthreads();

    float acc = 0.f;
    const float* kv = knn_v + (long)b * MKEYS * DMODEL;
    #pragma unroll 4
    for (int j = 0; j < TOPK; j++)
        acc += w[j] * kv[(long)sidx[j] * DMODEL + tid];
    const float* vbase = qkv + ((long)b * NTOK) * 384 + 256;
    for (int mm = 0; mm < NTOK; mm++)
        acc += w[TOPK + mm] * vbase[(long)mm * 384 + tid];
    out[row * DMODEL + tid] = acc;
}

// ---------------- launch ----------------
extern "C" void kernel_launch(void* const* d_in, const int* in_sizes, int n_in,
                              void* d_out, int out_size)
{
    const float* x       = (const float*)d_in[0];
    const float* patch_w = (const float*)d_in[1];
    const float* patch_b = (const float*)d_in[2];
    const float* ln1_g   = (const float*)d_in[3];
    const float* ln1_b   = (const float*)d_in[4];
    const float* qkv_w   = (const float*)d_in[5];
    const float* qkv_b   = (const float*)d_in[6];
    const float* out_w   = (const float*)d_in[7];
    const float* out_b   = (const float*)d_in[8];
    const float* ln2_g   = (const float*)d_in[9];
    const float* ln2_b   = (const float*)d_in[10];
    const float* ff1_w   = (const float*)d_in[11];
    const float* ff1_b   = (const float*)d_in[12];
    const float* ff2_w   = (const float*)d_in[13];
    const float* ff2_b   = (const float*)d_in[14];
    const float* lnf_g   = (const float*)d_in[15];
    const float* lnf_b   = (const float*)d_in[16];
    const float* knn_k   = (const float*)d_in[17];
    const float* knn_v   = (const float*)d_in[18];
    const float* head_w  = (const float*)d_in[19];
    const float* head_b  = (const float*)d_in[20];
    float* out = (float*)d_out;

    void* tp;
    cudaGetSymbolAddress(&tp, g_p);    float* pP    = (float*)tp;
    cudaGetSymbolAddress(&tp, g_h);    float* pH    = (float*)tp;
    cudaGetSymbolAddress(&tp, g_qkv);  float* pQKV  = (float*)tp;
    cudaGetSymbolAddress(&tp, g_att);  float* pATT  = (float*)tp;
    cudaGetSymbolAddress(&tp, g_msim); float* pMSIM = (float*)tp;
    cudaGetSymbolAddress(&tp, g_o);    float* pO    = (float*)tp;
    cudaGetSymbolAddress(&tp, g_ff);   float* pFF   = (float*)tp;
    cudaGetSymbolAddress(&tp, g_part); float* pPart = (float*)tp;
    cudaGetSymbolAddress(&tp, g_mv);   float* pMV   = (float*)tp;
    cudaGetSymbolAddress(&tp, g_mi);   int*   pMI   = (int*)tp;
    cudaGetSymbolAddress(&tp, g_feats);float* pFeat = (float*)tp;
    cudaGetSymbolAddress(&tp, g_mu);   float* pMu   = (float*)tp;
    cudaGetSymbolAddress(&tp, g_rs);   float* pRs   = (float*)tp;

    cudaFuncSetAttribute(mmabf_k<false,false,false,false>, cudaFuncAttributeMaxDynamicSharedMemorySize, SMEM2);
    cudaFuncSetAttribute(mmabf_k<true, false,false,false>, cudaFuncAttributeMaxDynamicSharedMemorySize, SMEM2);
    cudaFuncSetAttribute(mmabf_k<false,false,true ,false>, cudaFuncAttributeMaxDynamicSharedMemorySize, SMEM2);
    cudaFuncSetAttribute(mmabf_k<false,true ,true ,false>, cudaFuncAttributeMaxDynamicSharedMemorySize, SMEM2);
    cudaFuncSetAttribute(mmabf_k<false,false,false,true >, cudaFuncAttributeMaxDynamicSharedMemorySize, SMEM2);
    cudaFuncSetAttribute(mmasav_k, cudaFuncAttributeMaxDynamicSharedMemorySize, SMEM_AV);
    cudaFuncSetAttribute(msimtf_k, cudaFuncAttributeMaxDynamicSharedMemorySize, SMEMT);

    const long sPart = (long)ROWS * DMODEL;

    // patch embed: split-K 6 -> reduce + ln1 stats
    patchify_k<<<(int)(((long)ROWS * PDIM + 255) / 256), 256>>>(x, pP);
    mmabf_k<false,false,false,false><<<dim3(1, 98, 6), 256, SMEM2>>>(pP, patch_w, nullptr, nullptr, pPart,
        ROWS, DMODEL, PDIM, 0, PDIM, 0, DMODEL, 0, DMODEL, 1.f, 1, 6, sPart,
        nullptr, nullptr, nullptr, nullptr, nullptr, nullptr);
    reduce_stats_k<<<ROWS, 128>>>(pPart, sPart, 6, patch_b, nullptr, pH, pMu, pRs);

    for (int i = 0; i < DEPTH; i++) {
        // qkv with inline ln1
        mmabf_k<false,false,true,false><<<dim3(3, 98, 1), 256, SMEM2>>>(pH, qkv_w + (long)i * DMODEL * 3 * DMODEL,
            qkv_b + i * 3 * DMODEL, nullptr, pQKV,
            ROWS, 3 * DMODEL, DMODEL, 0, DMODEL, 0, 3 * DMODEL, 0, 3 * DMODEL, 1.f, 1, 1, 0,
            pMu, pRs, ln1_g + i * DMODEL, ln1_b + i * DMODEL, nullptr, nullptr);
        // sim = q @ k^T * scale
        mmabf_k<true,false,false,false><<<dim3(2, 4, BATCH), 256, SMEM2>>>(pQKV, pQKV + 128, nullptr, nullptr, pATT,
            NTOK, NTOK, DMODEL,
            (long)NTOK * 384, 384, (long)NTOK * 384, 384, (long)NTOK * NTOK, NTOK, SCALE, BATCH, 1, 0,
            nullptr, nullptr, nullptr, nullptr, nullptr, nullptr);

        if (i == KNN_LAYER) {
            // msim = q @ knn_k^T * scale — 1xTF32 (logits only; tolerance verified R4-R7)
            msimtf_k<<<dim3(MKEYS / 128, 4, BATCH), 256, SMEMT>>>(pQKV, knn_k, pMSIM);
            topk_k<<<ROWS, 256>>>(pMSIM, pMV, pMI);
            knn_combine_k<<<ROWS, 128>>>(pATT, pMV, pMI, pQKV, knn_v, pO);
        } else {
            // fused softmax + av
            mmasav_k<<<dim3(1, 4, BATCH), 256, SMEM_AV>>>(pATT, pQKV + 256, pO, BATCH);
        }

        // h = h + o @ out_w + out_b ; epilogue emits ln2 stats
        mmabf_k<false,false,false,true><<<dim3(1, 98, 1), 256, SMEM2>>>(pO, out_w + (long)i * DMODEL * DMODEL,
            out_b + i * DMODEL, pH, pH,
            ROWS, DMODEL, DMODEL, 0, DMODEL, 0, DMODEL, 0, DMODEL, 1.f, 1, 1, 0,
            nullptr, nullptr, nullptr, nullptr, pMu, pRs);

        // ff1 + gelu with inline ln2
        mmabf_k<false,true,true,false><<<dim3(4, 98, 1), 256, SMEM2>>>(pH, ff1_w + (long)i * DMODEL * FFH,
            ff1_b + i * FFH, nullptr, pFF,
            ROWS, FFH, DMODEL, 0, DMODEL, 0, FFH, 0, FFH, 1.f, 1, 1, 0,
            pMu, pRs, ln2_g + i * DMODEL, ln2_b + i * DMODEL, nullptr, nullptr);
        // ff2: split-K 4, reduce adds bias + residual h, emits next ln1 stats
        mmabf_k<false,false,false,false><<<dim3(1, 98, 4), 256, SMEM2>>>(pFF, ff2_w + (long)i * FFH * DMODEL,
            nullptr, nullptr, pPart,
            ROWS, DMODEL, FFH, 0, FFH, 0, DMODEL, 0, DMODEL, 1.f, 1, 4, sPart,
            nullptr, nullptr, nullptr, nullptr, nullptr, nullptr);
        reduce_stats_k<<<ROWS, 128>>>(pPart, sPart, 4, ff2_b + i * DMODEL, pH, pH, pMu, pRs);
    }

    // final LN + mean pool, then head
    feats_k<<<BATCH, 128>>>(pH, pMu, pRs, lnf_g, lnf_b, pFeat);
    mmabf_k<false,false,false,false><<<dim3(8, 1, 1), 256, SMEM2>>>(pFeat, head_w, head_b, nullptr, out,
        BATCH, NCLS, DMODEL, 0, DMODEL, 0, NCLS, 0, NCLS, 1.f, 1, 1, 0,
        nullptr, nullptr, nullptr, nullptr, nullptr, nullptr);
}

// round 14
// speedup vs baseline: 1.0352x; 1.0352x over previous
#include <cuda_runtime.h>
#include <cuda_bf16.h>
#include <math.h>

// ---------------- problem constants ----------------
#define BATCH   32
#define NTOK    196
#define DMODEL  128
#define ROWS    (BATCH*NTOK) // 6272
#define PDIM    768
#define DEPTH   7
#define KNN_LAYER 6
#define MKEYS   8192
#define TOPK    32
#define FFH     512
#define NCLS    1000
#define SCALE   0.08838834764831845f
#define LNEPS   1e-5f

// ---------------- device scratch ----------------
__device__ float g_h   [ (long)ROWS*DMODEL ];
__device__ float g_qkv [ (long)ROWS*3*DMODEL ];
__device__ float g_att [ (long)BATCH*NTOK*NTOK ];
__device__ float g_msim[ (long)BATCH*NTOK*MKEYS ];
__device__ float g_o   [ (long)ROWS*DMODEL ];
__device__ float g_ff  [ (long)ROWS*FFH ];
__device__ float g_part[ (long)6*ROWS*DMODEL ];
__device__ float g_mv  [ (long)ROWS*TOPK ];
__device__ int   g_mi  [ (long)ROWS*TOPK ];
__device__ float g_feats[ BATCH*DMODEL ];
__device__ float g_mu  [ ROWS ];
__device__ float g_rs  [ ROWS ];

// ---------------- helpers ----------------
__device__ __forceinline__ float gelu_tanh(float v) {
    const float c = 0.7978845608028654f;
    float t = tanhf(c * (v + 0.044715f * v * v * v));
    return 0.5f * v * (1.f + t);
}
__device__ __forceinline__ void split_bf16(float v, unsigned short& h, unsigned short& l) {
    __nv_bfloat16 hb = __float2bfloat16_rn(v);
    h = __bfloat16_as_ushort(hb);
    l = __bfloat16_as_ushort(__float2bfloat16_rn(v - __bfloat162float(hb)));
}
#define MMA_BF16(ACC, A, B)                                                 \
    asm volatile(                                                           \
        "mma.sync.aligned.m16n8k16.row.col.f32.bf16.bf16.f32 "              \
        "{%0,%1,%2,%3}, {%4,%5,%6,%7}, {%8,%9}, {%0,%1,%2,%3};"             \
        : "+f"((ACC)[0]), "+f"((ACC)[1]), "+f"((ACC)[2]), "+f"((ACC)[3])    \
        : "r"((A)[0]), "r"((A)[1]), "r"((A)[2]), "r"((A)[3]),               \
          "r"((B)[0]), "r"((B)[1]))
#define LDSM4(R0,R1,R2,R3, ADDR)                                            \
    asm volatile("ldmatrix.sync.aligned.m8n8.x4.shared.b16 {%0,%1,%2,%3}, [%4];" \
        : "=r"(R0), "=r"(R1), "=r"(R2), "=r"(R3) : "r"(ADDR))
#define LDSM4T(R0,R1,R2,R3, ADDR)                                           \
    asm volatile("ldmatrix.sync.aligned.m8n8.x4.trans.shared.b16 {%0,%1,%2,%3}, [%4];" \
        : "=r"(R0), "=r"(R1), "=r"(R2), "=r"(R3) : "r"(ADDR))

// ---------------- bf16 split-2 mma GEMM (R9/R12 core) ----------------
// Block 64(M) x 128(N), K-chunk 32, 2-stage pipeline, ldmatrix fragments.
// LNA: apply layernorm (muA/rsA/lngA/lnbA) to A rows during load.
// STATS: (gridDim.x==1, Nc==128) epilogue emits row mean/rstd.
// PATCHA: A is the raw image x; loadA gathers patches inline (patch embed).
#define A_PITCH_B 80
#define BTB_PITCH_B 80
#define BNN_PITCH_B 272
#define AL_OFF 5120
#define BH_OFF 10240
#define BL_OFF 20480
#define STAGE_B 30720
#define SMEM2 (2*STAGE_B)

template<bool TB, bool DOGELU, bool LNA, bool STATS, bool PATCHA = false>
__global__ void __launch_bounds__(256, 2)
mmabf_k(const float* __restrict__ A, const float* __restrict__ Bm,
        const float* __restrict__ bias, const float* __restrict__ Res,
        float* __restrict__ C,
        int Mr, int Nc, int K,
        long sAb, int lda, long sBb, int ldb, long sCb, int ldc,
        float alpha, int nbatch, int kslices, long sPart,
        const float* __restrict__ muA, const float* __restrict__ rsA,
        const float* __restrict__ lngA, const float* __restrict__ lnbA,
        float* __restrict__ muO, float* __restrict__ rsO)
{
    extern __shared__ char smem_c[];
    unsigned sbase = (unsigned)__cvta_generic_to_shared(smem_c);

    int bz = blockIdx.z;
    int batch = bz % nbatch;
    int ksl   = bz / nbatch;
    int Kslice = K / kslices;
    int Klo = ksl * Kslice;
    int Khi = (ksl == kslices - 1) ? K : Klo + Kslice;

    const float* Ab = A + (PATCHA ? 0 : (long)batch * sAb);
    const float* Bb = Bm + (long)batch * sBb;
    float*       Cb;
    const float* Rb;
    if (kslices > 1) {
        Cb = C + (long)ksl * sPart + (long)batch * sCb;
        Rb = nullptr;
    } else {
        Cb = C + (long)batch * sCb;
        Rb = Res ? (Res + (long)batch * sCb) : nullptr;
    }

    int row0 = blockIdx.y * 64;
    int col0 = blockIdx.x * 128;
    int tid = threadIdx.x;
    int lane = tid & 31, warp = tid >> 5;
    int wm = warp >> 2, wn = warp & 3;
    int g = lane >> 2, tg = lane & 3;

    int ar = tid >> 3, ak = (tid & 7) * 4;
    int bkNN = tid >> 5, bnNN = (tid & 31) * 4;
    int bnTB = tid >> 3, bkTB = (tid & 7) * 4;

    float4 pa[2], pb[4];

    auto loadA = [&](int k0) {
        #pragma unroll
        for (int p = 0; p < 2; p++) {
            int gr = row0 + ar + p * 32, gk = k0 + ak;
            float4 v = make_float4(0.f, 0.f, 0.f, 0.f);
            if (PATCHA) {
                // patch-embed gather: row gr -> (b, token), col gk -> (ch, pi, pj)
                if (gr < Mr) {
                    int b  = gr / NTOK, n = gr % NTOK;
                    int i  = n / 14,    j = n % 14;
                    int ch = gk >> 8;
                    int r  = gk & 255;
                    int pi = r >> 4, pj = r & 15;      // gk%4==0 -> pj%4==0
                    const float* xs = Ab + (((long)b * 3 + ch) * 224 + (i * 16 + pi)) * 224
                                         + (j * 16 + pj);
                    v = *(const float4*)xs;
                }
            } else if (gr < Mr) {
                if (gk + 3 < Khi) {
                    v = *(const float4*)&Ab[(long)gr * lda + gk];
                    if (LNA) {
                        float mu = __ldg(&muA[gr]);
                        float rs = __ldg(&rsA[gr]);
                        float4 gg = *(const float4*)&lngA[gk];
                        float4 bb = *(const float4*)&lnbA[gk];
                        v.x = (v.x - mu) * rs * gg.x + bb.x;
                        v.y = (v.y - mu) * rs * gg.y + bb.y;
                        v.z = (v.z - mu) * rs * gg.z + bb.z;
                        v.w = (v.w - mu) * rs * gg.w + bb.w;
                    }
                } else {
                    if (gk + 0 < Khi) v.x = Ab[(long)gr * lda + gk + 0];
                    if (gk + 1 < Khi) v.y = Ab[(long)gr * lda + gk + 1];
                    if (gk + 2 < Khi) v.z = Ab[(long)gr * lda + gk + 2];
                    if (gk + 3 < Khi) v.w = Ab[(long)gr * lda + gk + 3];
                }
            }
            pa[p] = v;
        }
    };
    auto loadB = [&](int k0) {
        if (TB) {
            #pragma unroll
            for (int p = 0; p < 4; p++) {
                int gn = col0 + bnTB + p * 32, gk = k0 + bkTB;
                float4 v = make_float4(0.f, 0.f, 0.f, 0.f);
                if (gn < Nc) {
                    if (gk + 3 < Khi) v = *(const float4*)&Bb[(long)gn * ldb + gk];
                    else {
                        if (gk + 0 < Khi) v.x = Bb[(long)gn * ldb + gk + 0];
                        if (gk + 1 < Khi) v.y = Bb[(long)gn * ldb + gk + 1];
                        if (gk + 2 < Khi) v.z = Bb[(long)gn * ldb + gk + 2];
                        if (gk + 3 < Khi) v.w = Bb[(long)gn * ldb + gk + 3];
                    }
                }
                pb[p] = v;
            }
        } else {
            #pragma unroll
            for (int p = 0; p < 4; p++) {
                int gk = k0 + bkNN + p * 8, gn = col0 + bnNN;
                float4 v = make_float4(0.f, 0.f, 0.f, 0.f);
                if (gk < Khi) {
                    if (gn + 3 < Nc) v = *(const float4*)&Bb[(long)gk * ldb + gn];
                    else {
                        if (gn + 0 < Nc) v.x = Bb[(long)gk * ldb + gn + 0];
                        if (gn + 1 < Nc) v.y = Bb[(long)gk * ldb + gn + 1];
                        if (gn + 2 < Nc) v.z = Bb[(long)gk * ldb + gn + 2];
                        if (gn + 3 < Nc) v.w = Bb[(long)gk * ldb + gn + 3];
                    }
                }
                pb[p] = v;
            }
        }
    };
    auto storeTiles = [&](int st) {
        char* sb = smem_c + st * STAGE_B;
        #pragma unroll
        for (int p = 0; p < 2; p++) {
            int r = ar + p * 32;
            float vv[4] = {pa[p].x, pa[p].y, pa[p].z, pa[p].w};
            unsigned short h[4], l[4];
            #pragma unroll
            for (int j = 0; j < 4; j++) split_bf16(vv[j], h[j], l[j]);
            *(uint2*)(sb + r * A_PITCH_B + ak * 2) =
                make_uint2(((unsigned)h[1] << 16) | h[0], ((unsigned)h[3] << 16) | h[2]);
            *(uint2*)(sb + AL_OFF + r * A_PITCH_B + ak * 2) =
                make_uint2(((unsigned)l[1] << 16) | l[0], ((unsigned)l[3] << 16) | l[2]);
        }
        if (TB) {
            #pragma unroll
            for (int p = 0; p < 4; p++) {
                int n = bnTB + p * 32;
                float vv[4] = {pb[p].x, pb[p].y, pb[p].z, pb[p].w};
                unsigned short h[4], l[4];
                #pragma unroll
                for (int j = 0; j < 4; j++) split_bf16(vv[j], h[j], l[j]);
                *(uint2*)(sb + BH_OFF + n * BTB_PITCH_B + bkTB * 2) =
                    make_uint2(((unsigned)h[1] << 16) | h[0], ((unsigned)h[3] << 16) | h[2]);
                *(uint2*)(sb + BL_OFF + n * BTB_PITCH_B + bkTB * 2) =
                    make_uint2(((unsigned)l[1] << 16) | l[0], ((unsigned)l[3] << 16) | l[2]);
            }
        } else {
            #pragma unroll
            for (int p = 0; p < 4; p++) {
                int k = bkNN + p * 8;
                float vv[4] = {pb[p].x, pb[p].y, pb[p].z, pb[p].w};
                unsigned short h[4], l[4];
                #pragma unroll
                for (int j = 0; j < 4; j++) split_bf16(vv[j], h[j], l[j]);
                *(uint2*)(sb + BH_OFF + k * BNN_PITCH_B + bnNN * 2) =
                    make_uint2(((unsigned)h[1] << 16) | h[0], ((unsigned)h[3] << 16) | h[2]);
                *(uint2*)(sb + BL_OFF + k * BNN_PITCH_B + bnNN * 2) =
                    make_uint2(((unsigned)l[1] << 16) | l[0], ((unsigned)l[3] << 16) | l[2]);
            }
        }
    };

    float acc[2][4][4];
    #pragma unroll
    for (int im = 0; im < 2; im++)
        #pragma unroll
        for (int jn = 0; jn < 4; jn++)
            #pragma unroll
            for (int c = 0; c < 4; c++) acc[im][jn][c] = 0.f;

    int nch = (Khi - Klo + 31) / 32;
    int stage = 0;

    loadA(Klo); loadB(Klo);
    storeTiles(0);
    __syncthreads();

    for (int c = 0; c < nch; c++) {
        if (c + 1 < nch) { loadA(Klo + (c + 1) * 32); loadB(Klo + (c + 1) * 32); }

        unsigned stb = sbase + stage * STAGE_B;
        #pragma unroll
        for (int ks2 = 0; ks2 < 2; ks2++) {
            int ksb = ks2 * 32;
            unsigned ah[2][4], al_[2][4];
            #pragma unroll
            for (int im = 0; im < 2; im++) {
                unsigned aaddr = stb
                    + (unsigned)((wm * 32 + im * 16 + (lane & 15)) * A_PITCH_B
                                 + ((lane >> 4) * 16) + ksb);
                LDSM4(ah[im][0], ah[im][1], ah[im][2], ah[im][3], aaddr);
                LDSM4(al_[im][0], al_[im][1], al_[im][2], al_[im][3], aaddr + AL_OFF);
            }
            unsigned bh[4][2], bl_[4][2];
            #pragma unroll
            for (int pr = 0; pr < 2; pr++) {
                int nb2 = wn * 32 + pr * 16;
                unsigned baddr;
                if (TB) {
                    baddr = stb + BH_OFF
                        + (unsigned)((nb2 + ((lane >> 4) << 3) + (lane & 7)) * BTB_PITCH_B
                                     + (((lane >> 3) & 1) * 16) + ksb);
                } else {
                    baddr = stb + BH_OFF
                        + (unsigned)((ks2 * 16 + ((lane >> 3) & 1) * 8 + (lane & 7)) * BNN_PITCH_B
                                     + (nb2 + (lane >> 4) * 8) * 2);
                }
                unsigned r0, r1, r2, r3;
                if (TB) { LDSM4(r0, r1, r2, r3, baddr); }
                else    { LDSM4T(r0, r1, r2, r3, baddr); }
                bh[2*pr][0] = r0; bh[2*pr][1] = r1; bh[2*pr+1][0] = r2; bh[2*pr+1][1] = r3;
                unsigned laddr = baddr + (BL_OFF - BH_OFF);
                if (TB) { LDSM4(r0, r1, r2, r3, laddr); }
                else    { LDSM4T(r0, r1, r2, r3, laddr); }
                bl_[2*pr][0] = r0; bl_[2*pr][1] = r1; bl_[2*pr+1][0] = r2; bl_[2*pr+1][1] = r3;
            }
            #pragma unroll
            for (int im = 0; im < 2; im++)
                #pragma unroll
                for (int jn = 0; jn < 4; jn++) {
                    MMA_BF16(acc[im][jn], ah[im], bl_[jn]);
                    MMA_BF16(acc[im][jn], al_[im], bh[jn]);
                    MMA_BF16(acc[im][jn], ah[im], bh[jn]);
                }
        }

        if (c + 1 < nch) {
            storeTiles(stage ^ 1);
            __syncthreads();
            stage ^= 1;
        }
    }

    // ---- epilogue
    float st1[2][2], st2[2][2];
    if (STATS) {
        #pragma unroll
        for (int im = 0; im < 2; im++)
            #pragma unroll
            for (int hh = 0; hh < 2; hh++) { st1[im][hh] = 0.f; st2[im][hh] = 0.f; }
    }
    #pragma unroll
    for (int im = 0; im < 2; im++) {
        #pragma unroll
        for (int jn = 0; jn < 4; jn++) {
            int r0 = row0 + wm * 32 + im * 16 + g;
            int c0 = col0 + wn * 32 + jn * 8 + 2 * tg;
            #pragma unroll
            for (int half = 0; half < 2; half++) {
                int gr = r0 + half * 8;
                if (gr >= Mr) continue;
                #pragma unroll
                for (int cc = 0; cc < 2; cc++) {
                    int gn = c0 + cc;
                    if (gn >= Nc) continue;
                    float v = acc[im][jn][half * 2 + cc] * alpha;
                    if (kslices == 1) {
                        if (bias) v += bias[gn];
                        if (Rb)   v += Rb[(long)gr * ldc + gn];
                        if (DOGELU) v = gelu_tanh(v);
                    }
                    if (STATS) { st1[im][half] += v; st2[im][half] += v * v; }
                    Cb[(long)gr * ldc + gn] = v;
                }
            }
        }
    }
    if (STATS) {
        __syncthreads();
        float* s1 = (float*)smem_c;
        float* s2 = s1 + 256;
        #pragma unroll
        for (int im = 0; im < 2; im++)
            #pragma unroll
            for (int hh = 0; hh < 2; hh++) {
                float x1 = st1[im][hh], x2 = st2[im][hh];
                x1 += __shfl_xor_sync(0xffffffffu, x1, 1);
                x1 += __shfl_xor_sync(0xffffffffu, x1, 2);
                x2 += __shfl_xor_sync(0xffffffffu, x2, 1);
                x2 += __shfl_xor_sync(0xffffffffu, x2, 2);
                if (tg == 0) {
                    int lr = wm * 32 + im * 16 + g + hh * 8;
                    s1[wn * 64 + lr] = x1;
                    s2[wn * 64 + lr] = x2;
                }
            }
        __syncthreads();
        if (tid < 64) {
            float t1 = s1[tid] + s1[64 + tid] + s1[128 + tid] + s1[192 + tid];
            float t2 = s2[tid] + s2[64 + tid] + s2[128 + tid] + s2[192 + tid];
            float mu = t1 * (1.f / 128.f);
            float var = t2 * (1.f / 128.f) - mu * mu;
            muO[row0 + tid] = mu;
            rsO[row0 + tid] = rsqrtf(var + LNEPS);
        }
    }
}

// ============================================================================
// Fused softmax + av GEMM (R12-verified).
// ============================================================================
#define SATT_PITCH 204
#define SMEM_AV (SMEM2 + 64*SATT_PITCH*4)

__global__ void __launch_bounds__(256)
mmasav_k(const float* __restrict__ Att, const float* __restrict__ Bm,
         float* __restrict__ C, int nbatch)
{
    extern __shared__ char smem_c[];
    unsigned sbase = (unsigned)__cvta_generic_to_shared(smem_c);
    float* satt = (float*)(smem_c + SMEM2);

    int batch = blockIdx.z % nbatch;
    const float* Ab = Att + (long)batch * NTOK * NTOK;
    const float* Bb = Bm + (long)batch * NTOK * 384;
    float*       Cb = C + (long)batch * NTOK * DMODEL;

    int row0 = blockIdx.y * 64;
    int tid = threadIdx.x;
    int lane = tid & 31, warp = tid >> 5;
    int wm = warp >> 2, wn = warp & 3;
    int g = lane >> 2, tg = lane & 3;

    for (int idx = tid; idx < 64 * NTOK; idx += 256) {
        int r = idx / NTOK, c = idx % NTOK;
        int gr = row0 + r;
        satt[r * SATT_PITCH + c] = (gr < NTOK) ? Ab[(long)gr * NTOK + c] : 0.f;
    }
    __syncthreads();

    {
        int r = tid >> 2, part = tid & 3;
        float* rowp = satt + r * SATT_PITCH;
        float mx = -3.4e38f;
        for (int c = part; c < NTOK; c += 4) mx = fmaxf(mx, rowp[c]);
        mx = fmaxf(mx, __shfl_xor_sync(0xffffffffu, mx, 1));
        mx = fmaxf(mx, __shfl_xor_sync(0xffffffffu, mx, 2));
        float sum = 0.f;
        for (int c = part; c < NTOK; c += 4) {
            float e = expf(rowp[c] - mx);
            rowp[c] = e;
            sum += e;
        }
        sum += __shfl_xor_sync(0xffffffffu, sum, 1);
        sum += __shfl_xor_sync(0xffffffffu, sum, 2);
        float inv = 1.f / sum;
        for (int c = part; c < NTOK; c += 4) rowp[c] *= inv;
    }
    __syncthreads();

    int ar = tid >> 3, ak = (tid & 7) * 4;
    int bkNN = tid >> 5, bnNN = (tid & 31) * 4;
    const int K = NTOK, Nc = DMODEL;

    float4 pa[2], pb[4];

    auto loadA = [&](int k0) {
        #pragma unroll
        for (int p = 0; p < 2; p++) {
            int r = ar + p * 32, gk = k0 + ak;
            float4 v = make_float4(0.f, 0.f, 0.f, 0.f);
            if (gk + 3 < K) {
                v = *(const float4*)&satt[r * SATT_PITCH + gk];
            } else {
                if (gk + 0 < K) v.x = satt[r * SATT_PITCH + gk + 0];
                if (gk + 1 < K) v.y = satt[r * SATT_PITCH + gk + 1];
                if (gk + 2 < K) v.z = satt[r * SATT_PITCH + gk + 2];
                if (gk + 3 < K) v.w = satt[r * SATT_PITCH + gk + 3];
            }
            pa[p] = v;
        }
    };
    auto loadB = [&](int k0) {
        #pragma unroll
        for (int p = 0; p < 4; p++) {
            int gk = k0 + bkNN + p * 8, gn = bnNN;
            float4 v = make_float4(0.f, 0.f, 0.f, 0.f);
            if (gk < K && gn + 3 < Nc)
                v = *(const float4*)&Bb[(long)gk * 384 + gn];
            pb[p] = v;
        }
    };
    auto storeTiles = [&](int st) {
        char* sb = smem_c + st * STAGE_B;
        #pragma unroll
        for (int p = 0; p < 2; p++) {
            int r = ar + p * 32;
            float vv[4] = {pa[p].x, pa[p].y, pa[p].z, pa[p].w};
            unsigned short h[4], l[4];
            #pragma unroll
            for (int j = 0; j < 4; j++) split_bf16(vv[j], h[j], l[j]);
            *(uint2*)(sb + r * A_PITCH_B + ak * 2) =
                make_uint2(((unsigned)h[1] << 16) | h[0], ((unsigned)h[3] << 16) | h[2]);
            *(uint2*)(sb + AL_OFF + r * A_PITCH_B + ak * 2) =
                make_uint2(((unsigned)l[1] << 16) | l[0], ((unsigned)l[3] << 16) | l[2]);
        }
        #pragma unroll
        for (int p = 0; p < 4; p++) {
            int k = bkNN + p * 8;
            float vv[4] = {pb[p].x, pb[p].y, pb[p].z, pb[p].w};
            unsigned short h[4], l[4];
            #pragma unroll
            for (int j = 0; j < 4; j++) split_bf16(vv[j], h[j], l[j]);
            *(uint2*)(sb + BH_OFF + k * BNN_PITCH_B + bnNN * 2) =
                make_uint2(((unsigned)h[1] << 16) | h[0], ((unsigned)h[3] << 16) | h[2]);
            *(uint2*)(sb + BL_OFF + k * BNN_PITCH_B + bnNN * 2) =
                make_uint2(((unsigned)l[1] << 16) | l[0], ((unsigned)l[3] << 16) | l[2]);
        }
    };

    float acc[2][4][4];
    #pragma unroll
    for (int im = 0; im < 2; im++)
        #pragma unroll
        for (int jn = 0; jn < 4; jn++)
            #pragma unroll
            for (int c = 0; c < 4; c++) acc[im][jn][c] = 0.f;

    int nch = (K + 31) / 32;
    int stage = 0;

    loadA(0); loadB(0);
    storeTiles(0);
    __syncthreads();

    for (int c = 0; c < nch; c++) {
        if (c + 1 < nch) { loadA((c + 1) * 32); loadB((c + 1) * 32); }

        unsigned stb = sbase + stage * STAGE_B;
        #pragma unroll
        for (int ks2 = 0; ks2 < 2; ks2++) {
            int ksb = ks2 * 32;
            unsigned ah[2][4], al_[2][4];
            #pragma unroll
            for (int im = 0; im < 2; im++) {
                unsigned aaddr = stb
                    + (unsigned)((wm * 32 + im * 16 + (lane & 15)) * A_PITCH_B
                                 + ((lane >> 4) * 16) + ksb);
                LDSM4(ah[im][0], ah[im][1], ah[im][2], ah[im][3], aaddr);
                LDSM4(al_[im][0], al_[im][1], al_[im][2], al_[im][3], aaddr + AL_OFF);
            }
            unsigned bh[4][2], bl_[4][2];
            #pragma unroll
            for (int pr = 0; pr < 2; pr++) {
                int nb2 = wn * 32 + pr * 16;
                unsigned baddr = stb + BH_OFF
                    + (unsigned)((ks2 * 16 + ((lane >> 3) & 1) * 8 + (lane & 7)) * BNN_PITCH_B
                                 + (nb2 + (lane >> 4) * 8) * 2);
                unsigned r0, r1, r2, r3;
                LDSM4T(r0, r1, r2, r3, baddr);
                bh[2*pr][0] = r0; bh[2*pr][1] = r1; bh[2*pr+1][0] = r2; bh[2*pr+1][1] = r3;
                LDSM4T(r0, r1, r2, r3, baddr + (BL_OFF - BH_OFF));
                bl_[2*pr][0] = r0; bl_[2*pr][1] = r1; bl_[2*pr+1][0] = r2; bl_[2*pr+1][1] = r3;
            }
            #pragma unroll
            for (int im = 0; im < 2; im++)
                #pragma unroll
                for (int jn = 0; jn < 4; jn++) {
                    MMA_BF16(acc[im][jn], ah[im], bl_[jn]);
                    MMA_BF16(acc[im][jn], al_[im], bh[jn]);
                    MMA_BF16(acc[im][jn], ah[im], bh[jn]);
                }
        }

        if (c + 1 < nch) {
            storeTiles(stage ^ 1);
            __syncthreads();
            stage ^= 1;
        }
    }

    #pragma unroll
    for (int im = 0; im < 2; im++) {
        #pragma unroll
        for (int jn = 0; jn < 4; jn++) {
            int r0 = row0 + wm * 32 + im * 16 + g;
            int c0 = wn * 32 + jn * 8 + 2 * tg;
            #pragma unroll
            for (int half = 0; half < 2; half++) {
                int gr = r0 + half * 8;
                if (gr >= NTOK) continue;
                #pragma unroll
                for (int cc = 0; cc < 2; cc++) {
                    int gn = c0 + cc;
                    Cb[(long)gr * DMODEL + gn] = acc[im][jn][half * 2 + cc];
                }
            }
        }
    }
}

// ---------------- split-K reduce + LN stats ----------------
__global__ void reduce_stats_k(const float* __restrict__ part, long sstride, int ns,
                               const float* __restrict__ bias, const float* __restrict__ res,
                               float* __restrict__ out,
                               float* __restrict__ mu, float* __restrict__ rstd)
{
    long row = blockIdx.x;
    int d = threadIdx.x;
    long idx = row * DMODEL + d;
    float s = 0.f;
    for (int k = 0; k < ns; k++) s += part[(long)k * sstride + idx];
    s += bias[d];
    if (res) s += res[idx];
    out[idx] = s;
    __shared__ float r1[4], r2[4];
    float v1 = s, v2 = s * s;
    #pragma unroll
    for (int o = 16; o > 0; o >>= 1) {
        v1 += __shfl_xor_sync(0xffffffffu, v1, o);
        v2 += __shfl_xor_sync(0xffffffffu, v2, o);
    }
    if ((d & 31) == 0) { r1[d >> 5] = v1; r2[d >> 5] = v2; }
    __syncthreads();
    if (d == 0) {
        float t1 = r1[0] + r1[1] + r1[2] + r1[3];
        float t2 = r2[0] + r2[1] + r2[2] + r2[3];
        float m = t1 * (1.f / 128.f);
        float var = t2 * (1.f / 128.f) - m * m;
        mu[row] = m;
        rstd[row] = rsqrtf(var + LNEPS);
    }
}

// ---------------- final LN + mean pool fused ----------------
__global__ void feats_k(const float* __restrict__ h, const float* __restrict__ mu,
                        const float* __restrict__ rstd,
                        const float* __restrict__ g, const float* __restrict__ b,
                        float* __restrict__ feats)
{
    int bb = blockIdx.x, d = threadIdx.x;
    float gd = g[d], bd = b[d];
    float s = 0.f;
    for (int n = 0; n < NTOK; n++) {
        long row = (long)bb * NTOK + n;
        s += (h[row * DMODEL + d] - mu[row]) * rstd[row] * gd + bd;
    }
    feats[bb * DMODEL + d] = s * (1.f / 196.f);
}

// ---------------- top-32: register-resident incremental argmax ----------------
__global__ void __launch_bounds__(256) topk_k(const float* __restrict__ msim,
                       float* __restrict__ mvals, int* __restrict__ midx)
{
    long row = blockIdx.x;
    int tid = threadIdx.x;
    int lane = tid & 31, wid = tid >> 5;
    const float* src = msim + row * MKEYS;

    float v[32];
    const float4* s4 = (const float4*)(src + tid * 32);
    #pragma unroll
    for (int i = 0; i < 8; i++) {
        float4 t = s4[i];
        v[i*4+0] = t.x; v[i*4+1] = t.y; v[i*4+2] = t.z; v[i*4+3] = t.w;
    }

    unsigned long long p = 0ull;
    #pragma unroll
    for (int i = 0; i < 32; i++) {
        unsigned u = __float_as_uint(v[i]);
        u = (u & 0x80000000u) ? ~u : (u | 0x80000000u);
        unsigned long long key = ((unsigned long long)u << 32) | (unsigned)(MKEYS - 1 - (tid * 32 + i));
        if (key > p) p = key;
    }

    __shared__ unsigned long long wmax[2][8];

    for (int it = 0; it < TOPK; it++) {
        unsigned long long q = p;
        #pragma unroll
        for (int o = 16; o > 0; o >>= 1) {
            unsigned long long other = __shfl_xor_sync(0xffffffffu, q, o);
            if (other > q) q = other;
        }
        if (lane == 0) wmax[it & 1][wid] = q;
        __syncthreads();
        unsigned long long best = wmax[it & 1][0];
        #pragma unroll
        for (int w = 1; w < 8; w++) {
            unsigned long long o2 = wmax[it & 1][w];
            if (o2 > best) best = o2;
        }
        int gidx = MKEYS - 1 - (int)(best & 0xffffffffu);
        if (tid == (gidx >> 5)) {
            int sub = gidx & 31;
            float bv = 0.f;
            #pragma unroll
            for (int i = 0; i < 32; i++)
                if (i == sub) { bv = v[i]; v[i] = -3.4e38f; }
            mvals[row * TOPK + it] = bv;
            midx [row * TOPK + it] = gidx;
            unsigned long long np = 0ull;
            #pragma unroll
            for (int i = 0; i < 32; i++) {
                unsigned u = __float_as_uint(v[i]);
                u = (u & 0x80000000u) ? ~u : (u | 0x80000000u);
                unsigned long long key = ((unsigned long long)u << 32) | (unsigned)(MKEYS - 1 - (tid * 32 + i));
                if (key > np) np = key;
            }
            p = np;
        }
    }
}

// ---------------- kNN combine ----------------
__global__ void knn_combine_k(const float* __restrict__ att,
                              const float* __restrict__ mvals, const int* __restrict__ midx,
                              const float* __restrict__ qkv, const float* __restrict__ knn_v,
                              float* __restrict__ out)
{
    long row = blockIdx.x;
    int b = (int)(row / NTOK);
    int tid = threadIdx.x;
    __shared__ float w[TOPK + NTOK];
    __shared__ int   sidx[TOPK];
    __shared__ float red[4];

    if (tid < TOPK) {
        w[tid]    = mvals[row * TOPK + tid];
        sidx[tid] = midx [row * TOPK + tid];
    }
    for (int m = tid; m < NTOK; m += 128) w[TOPK + m] = att[row * NTOK + m];
    __syncthreads();

    float l0 = w[tid];
    float l1 = (tid < (TOPK + NTOK - 128)) ? w[tid + 128] : -3.4e38f;
    float m = fmaxf(l0, l1);
    #pragma unroll
    for (int o = 16; o > 0; o >>= 1) m = fmaxf(m, __shfl_xor_sync(0xffffffffu, m, o));
    if ((tid & 31) == 0) red[tid >> 5] = m;
    __syncthreads();
    m = fmaxf(fmaxf(red[0], red[1]), fmaxf(red[2], red[3]));
    float e0 = expf(l0 - m);
    float e1 = (tid < (TOPK + NTOK - 128)) ? expf(l1 - m) : 0.f;
    float s = e0 + e1;
    __syncthreads();
    #pragma unroll
    for (int o = 16; o > 0; o >>= 1) s += __shfl_xor_sync(0xffffffffu, s, o);
    if ((tid & 31) == 0) red[tid >> 5] = s;
    __syncthreads();
    s = red[0] + red[1] + red[2] + red[3];
    float inv = 1.f / s;
    w[tid] = e0 * inv;
    if (tid < (TOPK + NTOK - 128)) w[tid + 128] = e1 * inv;
    __syncthreads();

    float acc = 0.f;
    const float* kv = knn_v + (long)b * MKEYS * DMODEL;
    #pragma unroll 4
    for (int j = 0; j < TOPK; j++)
        acc += w[j] * kv[(long)sidx[j] * DMODEL + tid];
    const float* vbase = qkv + ((long)b * NTOK) * 384 + 256;
    for (int mm = 0; mm < NTOK; mm++)
        acc += w[TOPK + mm] * vbase[(long)mm * 384 + tid];
    out[row * DMODEL + tid] = acc;
}

// ---------------- launch ----------------
extern "C" void kernel_launch(void* const* d_in, const int* in_sizes, int n_in,
                              void* d_out, int out_size)
{
    const float* x       = (const float*)d_in[0];
    const float* patch_w = (const float*)d_in[1];
    const float* patch_b = (const float*)d_in[2];
    const float* ln1_g   = (const float*)d_in[3];
    const float* ln1_b   = (const float*)d_in[4];
    const float* qkv_w   = (const float*)d_in[5];
    const float* qkv_b   = (const float*)d_in[6];
    const float* out_w   = (const float*)d_in[7];
    const float* out_b   = (const float*)d_in[8];
    const float* ln2_g   = (const float*)d_in[9];
    const float* ln2_b   = (const float*)d_in[10];
    const float* ff1_w   = (const float*)d_in[11];
    const float* ff1_b   = (const float*)d_in[12];
    const float* ff2_w   = (const float*)d_in[13];
    const float* ff2_b   = (const float*)d_in[14];
    const float* lnf_g   = (const float*)d_in[15];
    const float* lnf_b   = (const float*)d_in[16];
    const float* knn_k   = (const float*)d_in[17];
    const float* knn_v   = (const float*)d_in[18];
    const float* head_w  = (const float*)d_in[19];
    const float* head_b  = (const float*)d_in[20];
    float* out = (float*)d_out;

    void* tp;
    cudaGetSymbolAddress(&tp, g_h);    float* pH    = (float*)tp;
    cudaGetSymbolAddress(&tp, g_qkv);  float* pQKV  = (float*)tp;
    cudaGetSymbolAddress(&tp, g_att);  float* pATT  = (float*)tp;
    cudaGetSymbolAddress(&tp, g_msim); float* pMSIM = (float*)tp;
    cudaGetSymbolAddress(&tp, g_o);    float* pO    = (float*)tp;
    cudaGetSymbolAddress(&tp, g_ff);   float* pFF   = (float*)tp;
    cudaGetSymbolAddress(&tp, g_part); float* pPart = (float*)tp;
    cudaGetSymbolAddress(&tp, g_mv);   float* pMV   = (float*)tp;
    cudaGetSymbolAddress(&tp, g_mi);   int*   pMI   = (int*)tp;
    cudaGetSymbolAddress(&tp, g_feats);float* pFeat = (float*)tp;
    cudaGetSymbolAddress(&tp, g_mu);   float* pMu   = (float*)tp;
    cudaGetSymbolAddress(&tp, g_rs);   float* pRs   = (float*)tp;

    cudaFuncSetAttribute(mmabf_k<false,false,false,false>, cudaFuncAttributeMaxDynamicSharedMemorySize, SMEM2);
    cudaFuncSetAttribute(mmabf_k<true, false,false,false>, cudaFuncAttributeMaxDynamicSharedMemorySize, SMEM2);
    cudaFuncSetAttribute(mmabf_k<false,false,true ,false>, cudaFuncAttributeMaxDynamicSharedMemorySize, SMEM2);
    cudaFuncSetAttribute(mmabf_k<false,true ,true ,false>, cudaFuncAttributeMaxDynamicSharedMemorySize, SMEM2);
    cudaFuncSetAttribute(mmabf_k<false,false,false,true >, cudaFuncAttributeMaxDynamicSharedMemorySize, SMEM2);
    cudaFuncSetAttribute(mmabf_k<false,false,false,false,true>, cudaFuncAttributeMaxDynamicSharedMemorySize, SMEM2);
    cudaFuncSetAttribute(mmasav_k, cudaFuncAttributeMaxDynamicSharedMemorySize, SMEM_AV);

    const long sPart = (long)ROWS * DMODEL;

    // patch embed: fused gather (PATCHA) + split-K 6 -> reduce + ln1 stats
    mmabf_k<false,false,false,false,true><<<dim3(1, 98, 6), 256, SMEM2>>>(x, patch_w, nullptr, nullptr, pPart,
        ROWS, DMODEL, PDIM, 0, PDIM, 0, DMODEL, 0, DMODEL, 1.f, 1, 6, sPart,
        nullptr, nullptr, nullptr, nullptr, nullptr, nullptr);
    reduce_stats_k<<<ROWS, 128>>>(pPart, sPart, 6, patch_b, nullptr, pH, pMu, pRs);

    for (int i = 0; i < DEPTH; i++) {
        // qkv with inline ln1
        mmabf_k<false,false,true,false><<<dim3(3, 98, 1), 256, SMEM2>>>(pH, qkv_w + (long)i * DMODEL * 3 * DMODEL,
            qkv_b + i * 3 * DMODEL, nullptr, pQKV,
            ROWS, 3 * DMODEL, DMODEL, 0, DMODEL, 0, 3 * DMODEL, 0, 3 * DMODEL, 1.f, 1, 1, 0,
            pMu, pRs, ln1_g + i * DMODEL, ln1_b + i * DMODEL, nullptr, nullptr);
        // sim = q @ k^T * scale
        mmabf_k<true,false,false,false><<<dim3(2, 4, BATCH), 256, SMEM2>>>(pQKV, pQKV + 128, nullptr, nullptr, pATT,
            NTOK, NTOK, DMODEL,
            (long)NTOK * 384, 384, (long)NTOK * 384, 384, (long)NTOK * NTOK, NTOK, SCALE, BATCH, 1, 0,
            nullptr, nullptr, nullptr, nullptr, nullptr, nullptr);

        if (i == KNN_LAYER) {
            // msim = q @ knn_k^T * scale (bf16 split-2, R12-verified)
            mmabf_k<true,false,false,false><<<dim3(64, 4, BATCH), 256, SMEM2>>>(pQKV, knn_k, nullptr, nullptr, pMSIM,
                NTOK, MKEYS, DMODEL,
                (long)NTOK * 384, 384, (long)MKEYS * DMODEL, DMODEL, (long)NTOK * MKEYS, MKEYS, SCALE, BATCH, 1, 0,
                nullptr, nullptr, nullptr, nullptr, nullptr, nullptr);
            topk_k<<<ROWS, 256>>>(pMSIM, pMV, pMI);
            knn_combine_k<<<ROWS, 128>>>(pATT, pMV, pMI, pQKV, knn_v, pO);
        } else {
            // fused softmax + av
            mmasav_k<<<dim3(1, 4, BATCH), 256, SMEM_AV>>>(pATT, pQKV + 256, pO, BATCH);
        }

        // h = h + o @ out_w + out_b ; epilogue emits ln2 stats
        mmabf_k<false,false,false,true><<<dim3(1, 98, 1), 256, SMEM2>>>(pO, out_w + (long)i * DMODEL * DMODEL,
            out_b + i * DMODEL, pH, pH,
            ROWS, DMODEL, DMODEL, 0, DMODEL, 0, DMODEL, 0, DMODEL, 1.f, 1, 1, 0,
            nullptr, nullptr, nullptr, nullptr, pMu, pRs);

        // ff1 + gelu with inline ln2
        mmabf_k<false,true,true,false><<<dim3(4, 98, 1), 256, SMEM2>>>(pH, ff1_w + (long)i * DMODEL * FFH,
            ff1_b + i * FFH, nullptr, pFF,
            ROWS, FFH, DMODEL, 0, DMODEL, 0, FFH, 0, FFH, 1.f, 1, 1, 0,
            pMu, pRs, ln2_g + i * DMODEL, ln2_b + i * DMODEL, nullptr, nullptr);
        // ff2: split-K 4, reduce adds bias + residual h, emits next ln1 stats
        mmabf_k<false,false,false,false><<<dim3(1, 98, 4), 256, SMEM2>>>(pFF, ff2_w + (long)i * FFH * DMODEL,
            nullptr, nullptr, pPart,
            ROWS, DMODEL, FFH, 0, FFH, 0, DMODEL, 0, DMODEL, 1.f, 1, 4, sPart,
            nullptr, nullptr, nullptr, nullptr, nullptr, nullptr);
        reduce_stats_k<<<ROWS, 128>>>(pPart, sPart, 4, ff2_b + i * DMODEL, pH, pH, pMu, pRs);
    }

    // final LN + mean pool, then head
    feats_k<<<BATCH, 128>>>(pH, pMu, pRs, lnf_g, lnf_b, pFeat);
    mmabf_k<false,false,false,false><<<dim3(8, 1, 1), 256, SMEM2>>>(pFeat, head_w, head_b, nullptr, out,
        BATCH, NCLS, DMODEL, 0, DMODEL, 0, NCLS, 0, NCLS, 1.f, 1, 1, 0,
        nullptr, nullptr, nullptr, nullptr, nullptr, nullptr);
}

// round 15
// speedup vs baseline: 1.0769x; 1.0403x over previous
#include <cuda_runtime.h>
#include <cuda_bf16.h>
#include <math.h>

// ---------------- problem constants ----------------
#define BATCH   32
#define NTOK    196
#define DMODEL  128
#define ROWS    (BATCH*NTOK) // 6272
#define PDIM    768
#define DEPTH   7
#define KNN_LAYER 6
#define MKEYS   8192
#define TOPK    32
#define FFH     512
#define NCLS    1000
#define SCALE   0.08838834764831845f
#define LNEPS   1e-5f

// ---------------- device scratch ----------------
__device__ float g_h   [ (long)ROWS*DMODEL ];
__device__ float g_qkv [ (long)ROWS*3*DMODEL ];
__device__ float g_att [ (long)BATCH*NTOK*NTOK ];
__device__ float g_msim[ (long)BATCH*NTOK*MKEYS ];
__device__ float g_o   [ (long)ROWS*DMODEL ];
__device__ float g_ff  [ (long)ROWS*FFH ];
__device__ float g_part[ (long)6*ROWS*DMODEL ];
__device__ float g_mv  [ (long)ROWS*TOPK ];
__device__ int   g_mi  [ (long)ROWS*TOPK ];
__device__ float g_feats[ BATCH*DMODEL ];
__device__ float g_mu  [ ROWS ];
__device__ float g_rs  [ ROWS ];

// ---------------- helpers ----------------
__device__ __forceinline__ float gelu_tanh(float v) {
    const float c = 0.7978845608028654f;
    float t = tanhf(c * (v + 0.044715f * v * v * v));
    return 0.5f * v * (1.f + t);
}
__device__ __forceinline__ void split_bf16(float v, unsigned short& h, unsigned short& l) {
    __nv_bfloat16 hb = __float2bfloat16_rn(v);
    h = __bfloat16_as_ushort(hb);
    l = __bfloat16_as_ushort(__float2bfloat16_rn(v - __bfloat162float(hb)));
}
#define MMA_BF16(ACC, A, B)                                                 \
    asm volatile(                                                           \
        "mma.sync.aligned.m16n8k16.row.col.f32.bf16.bf16.f32 "              \
        "{%0,%1,%2,%3}, {%4,%5,%6,%7}, {%8,%9}, {%0,%1,%2,%3};"             \
        : "+f"((ACC)[0]), "+f"((ACC)[1]), "+f"((ACC)[2]), "+f"((ACC)[3])    \
        : "r"((A)[0]), "r"((A)[1]), "r"((A)[2]), "r"((A)[3]),               \
          "r"((B)[0]), "r"((B)[1]))
#define LDSM4(R0,R1,R2,R3, ADDR)                                            \
    asm volatile("ldmatrix.sync.aligned.m8n8.x4.shared.b16 {%0,%1,%2,%3}, [%4];" \
        : "=r"(R0), "=r"(R1), "=r"(R2), "=r"(R3) : "r"(ADDR))
#define LDSM4T(R0,R1,R2,R3, ADDR)                                           \
    asm volatile("ldmatrix.sync.aligned.m8n8.x4.trans.shared.b16 {%0,%1,%2,%3}, [%4];" \
        : "=r"(R0), "=r"(R1), "=r"(R2), "=r"(R3) : "r"(ADDR))

// ---------------- bf16 split-2 mma GEMM (R9/R12 core) ----------------
#define A_PITCH_B 80
#define BTB_PITCH_B 80
#define BNN_PITCH_B 272
#define AL_OFF 5120
#define BH_OFF 10240
#define BL_OFF 20480
#define STAGE_B 30720
#define SMEM2 (2*STAGE_B)

template<bool TB, bool DOGELU, bool LNA, bool STATS, bool PATCHA = false>
__global__ void __launch_bounds__(256, 2)
mmabf_k(const float* __restrict__ A, const float* __restrict__ Bm,
        const float* __restrict__ bias, const float* __restrict__ Res,
        float* __restrict__ C,
        int Mr, int Nc, int K,
        long sAb, int lda, long sBb, int ldb, long sCb, int ldc,
        float alpha, int nbatch, int kslices, long sPart,
        const float* __restrict__ muA, const float* __restrict__ rsA,
        const float* __restrict__ lngA, const float* __restrict__ lnbA,
        float* __restrict__ muO, float* __restrict__ rsO)
{
    extern __shared__ char smem_c[];
    unsigned sbase = (unsigned)__cvta_generic_to_shared(smem_c);

    int bz = blockIdx.z;
    int batch = bz % nbatch;
    int ksl   = bz / nbatch;
    int Kslice = K / kslices;
    int Klo = ksl * Kslice;
    int Khi = (ksl == kslices - 1) ? K : Klo + Kslice;

    const float* Ab = A + (PATCHA ? 0 : (long)batch * sAb);
    const float* Bb = Bm + (long)batch * sBb;
    float*       Cb;
    const float* Rb;
    if (kslices > 1) {
        Cb = C + (long)ksl * sPart + (long)batch * sCb;
        Rb = nullptr;
    } else {
        Cb = C + (long)batch * sCb;
        Rb = Res ? (Res + (long)batch * sCb) : nullptr;
    }

    int row0 = blockIdx.y * 64;
    int col0 = blockIdx.x * 128;
    int tid = threadIdx.x;
    int lane = tid & 31, warp = tid >> 5;
    int wm = warp >> 2, wn = warp & 3;
    int g = lane >> 2, tg = lane & 3;

    int ar = tid >> 3, ak = (tid & 7) * 4;
    int bkNN = tid >> 5, bnNN = (tid & 31) * 4;
    int bnTB = tid >> 3, bkTB = (tid & 7) * 4;

    float4 pa[2], pb[4];

    auto loadA = [&](int k0) {
        #pragma unroll
        for (int p = 0; p < 2; p++) {
            int gr = row0 + ar + p * 32, gk = k0 + ak;
            float4 v = make_float4(0.f, 0.f, 0.f, 0.f);
            if (PATCHA) {
                if (gr < Mr) {
                    int b  = gr / NTOK, n = gr % NTOK;
                    int i  = n / 14,    j = n % 14;
                    int ch = gk >> 8;
                    int r  = gk & 255;
                    int pi = r >> 4, pj = r & 15;
                    const float* xs = Ab + (((long)b * 3 + ch) * 224 + (i * 16 + pi)) * 224
                                         + (j * 16 + pj);
                    v = *(const float4*)xs;
                }
            } else if (gr < Mr) {
                if (gk + 3 < Khi) {
                    v = *(const float4*)&Ab[(long)gr * lda + gk];
                    if (LNA) {
                        float mu = __ldg(&muA[gr]);
                        float rs = __ldg(&rsA[gr]);
                        float4 gg = *(const float4*)&lngA[gk];
                        float4 bb = *(const float4*)&lnbA[gk];
                        v.x = (v.x - mu) * rs * gg.x + bb.x;
                        v.y = (v.y - mu) * rs * gg.y + bb.y;
                        v.z = (v.z - mu) * rs * gg.z + bb.z;
                        v.w = (v.w - mu) * rs * gg.w + bb.w;
                    }
                } else {
                    if (gk + 0 < Khi) v.x = Ab[(long)gr * lda + gk + 0];
                    if (gk + 1 < Khi) v.y = Ab[(long)gr * lda + gk + 1];
                    if (gk + 2 < Khi) v.z = Ab[(long)gr * lda + gk + 2];
                    if (gk + 3 < Khi) v.w = Ab[(long)gr * lda + gk + 3];
                }
            }
            pa[p] = v;
        }
    };
    auto loadB = [&](int k0) {
        if (TB) {
            #pragma unroll
            for (int p = 0; p < 4; p++) {
                int gn = col0 + bnTB + p * 32, gk = k0 + bkTB;
                float4 v = make_float4(0.f, 0.f, 0.f, 0.f);
                if (gn < Nc) {
                    if (gk + 3 < Khi) v = *(const float4*)&Bb[(long)gn * ldb + gk];
                    else {
                        if (gk + 0 < Khi) v.x = Bb[(long)gn * ldb + gk + 0];
                        if (gk + 1 < Khi) v.y = Bb[(long)gn * ldb + gk + 1];
                        if (gk + 2 < Khi) v.z = Bb[(long)gn * ldb + gk + 2];
                        if (gk + 3 < Khi) v.w = Bb[(long)gn * ldb + gk + 3];
                    }
                }
                pb[p] = v;
            }
        } else {
            #pragma unroll
            for (int p = 0; p < 4; p++) {
                int gk = k0 + bkNN + p * 8, gn = col0 + bnNN;
                float4 v = make_float4(0.f, 0.f, 0.f, 0.f);
                if (gk < Khi) {
                    if (gn + 3 < Nc) v = *(const float4*)&Bb[(long)gk * ldb + gn];
                    else {
                        if (gn + 0 < Nc) v.x = Bb[(long)gk * ldb + gn + 0];
                        if (gn + 1 < Nc) v.y = Bb[(long)gk * ldb + gn + 1];
                        if (gn + 2 < Nc) v.z = Bb[(long)gk * ldb + gn + 2];
                        if (gn + 3 < Nc) v.w = Bb[(long)gk * ldb + gn + 3];
                    }
                }
                pb[p] = v;
            }
        }
    };
    auto storeTiles = [&](int st) {
        char* sb = smem_c + st * STAGE_B;
        #pragma unroll
        for (int p = 0; p < 2; p++) {
            int r = ar + p * 32;
            float vv[4] = {pa[p].x, pa[p].y, pa[p].z, pa[p].w};
            unsigned short h[4], l[4];
            #pragma unroll
            for (int j = 0; j < 4; j++) split_bf16(vv[j], h[j], l[j]);
            *(uint2*)(sb + r * A_PITCH_B + ak * 2) =
                make_uint2(((unsigned)h[1] << 16) | h[0], ((unsigned)h[3] << 16) | h[2]);
            *(uint2*)(sb + AL_OFF + r * A_PITCH_B + ak * 2) =
                make_uint2(((unsigned)l[1] << 16) | l[0], ((unsigned)l[3] << 16) | l[2]);
        }
        if (TB) {
            #pragma unroll
            for (int p = 0; p < 4; p++) {
                int n = bnTB + p * 32;
                float vv[4] = {pb[p].x, pb[p].y, pb[p].z, pb[p].w};
                unsigned short h[4], l[4];
                #pragma unroll
                for (int j = 0; j < 4; j++) split_bf16(vv[j], h[j], l[j]);
                *(uint2*)(sb + BH_OFF + n * BTB_PITCH_B + bkTB * 2) =
                    make_uint2(((unsigned)h[1] << 16) | h[0], ((unsigned)h[3] << 16) | h[2]);
                *(uint2*)(sb + BL_OFF + n * BTB_PITCH_B + bkTB * 2) =
                    make_uint2(((unsigned)l[1] << 16) | l[0], ((unsigned)l[3] << 16) | l[2]);
            }
        } else {
            #pragma unroll
            for (int p = 0; p < 4; p++) {
                int k = bkNN + p * 8;
                float vv[4] = {pb[p].x, pb[p].y, pb[p].z, pb[p].w};
                unsigned short h[4], l[4];
                #pragma unroll
                for (int j = 0; j < 4; j++) split_bf16(vv[j], h[j], l[j]);
                *(uint2*)(sb + BH_OFF + k * BNN_PITCH_B + bnNN * 2) =
                    make_uint2(((unsigned)h[1] << 16) | h[0], ((unsigned)h[3] << 16) | h[2]);
                *(uint2*)(sb + BL_OFF + k * BNN_PITCH_B + bnNN * 2) =
                    make_uint2(((unsigned)l[1] << 16) | l[0], ((unsigned)l[3] << 16) | l[2]);
            }
        }
    };

    float acc[2][4][4];
    #pragma unroll
    for (int im = 0; im < 2; im++)
        #pragma unroll
        for (int jn = 0; jn < 4; jn++)
            #pragma unroll
            for (int c = 0; c < 4; c++) acc[im][jn][c] = 0.f;

    int nch = (Khi - Klo + 31) / 32;
    int stage = 0;

    loadA(Klo); loadB(Klo);
    storeTiles(0);
    __syncthreads();

    for (int c = 0; c < nch; c++) {
        if (c + 1 < nch) { loadA(Klo + (c + 1) * 32); loadB(Klo + (c + 1) * 32); }

        unsigned stb = sbase + stage * STAGE_B;
        #pragma unroll
        for (int ks2 = 0; ks2 < 2; ks2++) {
            int ksb = ks2 * 32;
            unsigned ah[2][4], al_[2][4];
            #pragma unroll
            for (int im = 0; im < 2; im++) {
                unsigned aaddr = stb
                    + (unsigned)((wm * 32 + im * 16 + (lane & 15)) * A_PITCH_B
                                 + ((lane >> 4) * 16) + ksb);
                LDSM4(ah[im][0], ah[im][1], ah[im][2], ah[im][3], aaddr);
                LDSM4(al_[im][0], al_[im][1], al_[im][2], al_[im][3], aaddr + AL_OFF);
            }
            unsigned bh[4][2], bl_[4][2];
            #pragma unroll
            for (int pr = 0; pr < 2; pr++) {
                int nb2 = wn * 32 + pr * 16;
                unsigned baddr;
                if (TB) {
                    baddr = stb + BH_OFF
                        + (unsigned)((nb2 + ((lane >> 4) << 3) + (lane & 7)) * BTB_PITCH_B
                                     + (((lane >> 3) & 1) * 16) + ksb);
                } else {
                    baddr = stb + BH_OFF
                        + (unsigned)((ks2 * 16 + ((lane >> 3) & 1) * 8 + (lane & 7)) * BNN_PITCH_B
                                     + (nb2 + (lane >> 4) * 8) * 2);
                }
                unsigned r0, r1, r2, r3;
                if (TB) { LDSM4(r0, r1, r2, r3, baddr); }
                else    { LDSM4T(r0, r1, r2, r3, baddr); }
                bh[2*pr][0] = r0; bh[2*pr][1] = r1; bh[2*pr+1][0] = r2; bh[2*pr+1][1] = r3;
                unsigned laddr = baddr + (BL_OFF - BH_OFF);
                if (TB) { LDSM4(r0, r1, r2, r3, laddr); }
                else    { LDSM4T(r0, r1, r2, r3, laddr); }
                bl_[2*pr][0] = r0; bl_[2*pr][1] = r1; bl_[2*pr+1][0] = r2; bl_[2*pr+1][1] = r3;
            }
            #pragma unroll
            for (int im = 0; im < 2; im++)
                #pragma unroll
                for (int jn = 0; jn < 4; jn++) {
                    MMA_BF16(acc[im][jn], ah[im], bl_[jn]);
                    MMA_BF16(acc[im][jn], al_[im], bh[jn]);
                    MMA_BF16(acc[im][jn], ah[im], bh[jn]);
                }
        }

        if (c + 1 < nch) {
            storeTiles(stage ^ 1);
            __syncthreads();
            stage ^= 1;
        }
    }

    // ---- epilogue
    float st1[2][2], st2[2][2];
    if (STATS) {
        #pragma unroll
        for (int im = 0; im < 2; im++)
            #pragma unroll
            for (int hh = 0; hh < 2; hh++) { st1[im][hh] = 0.f; st2[im][hh] = 0.f; }
    }
    #pragma unroll
    for (int im = 0; im < 2; im++) {
        #pragma unroll
        for (int jn = 0; jn < 4; jn++) {
            int r0 = row0 + wm * 32 + im * 16 + g;
            int c0 = col0 + wn * 32 + jn * 8 + 2 * tg;
            #pragma unroll
            for (int half = 0; half < 2; half++) {
                int gr = r0 + half * 8;
                if (gr >= Mr) continue;
                #pragma unroll
                for (int cc = 0; cc < 2; cc++) {
                    int gn = c0 + cc;
                    if (gn >= Nc) continue;
                    float v = acc[im][jn][half * 2 + cc] * alpha;
                    if (kslices == 1) {
                        if (bias) v += bias[gn];
                        if (Rb)   v += Rb[(long)gr * ldc + gn];
                        if (DOGELU) v = gelu_tanh(v);
                    }
                    if (STATS) { st1[im][half] += v; st2[im][half] += v * v; }
                    Cb[(long)gr * ldc + gn] = v;
                }
            }
        }
    }
    if (STATS) {
        __syncthreads();
        float* s1 = (float*)smem_c;
        float* s2 = s1 + 256;
        #pragma unroll
        for (int im = 0; im < 2; im++)
            #pragma unroll
            for (int hh = 0; hh < 2; hh++) {
                float x1 = st1[im][hh], x2 = st2[im][hh];
                x1 += __shfl_xor_sync(0xffffffffu, x1, 1);
                x1 += __shfl_xor_sync(0xffffffffu, x1, 2);
                x2 += __shfl_xor_sync(0xffffffffu, x2, 1);
                x2 += __shfl_xor_sync(0xffffffffu, x2, 2);
                if (tg == 0) {
                    int lr = wm * 32 + im * 16 + g + hh * 8;
                    s1[wn * 64 + lr] = x1;
                    s2[wn * 64 + lr] = x2;
                }
            }
        __syncthreads();
        if (tid < 64) {
            float t1 = s1[tid] + s1[64 + tid] + s1[128 + tid] + s1[192 + tid];
            float t2 = s2[tid] + s2[64 + tid] + s2[128 + tid] + s2[192 + tid];
            float mu = t1 * (1.f / 128.f);
            float var = t2 * (1.f / 128.f) - mu * mu;
            muO[row0 + tid] = mu;
            rsO[row0 + tid] = rsqrtf(var + LNEPS);
        }
    }
}

// ============================================================================
// msim2: B (knn_k 128x128 tile) staged ONCE in smem; loop over 4 q-row-tiles,
// streaming A (q) via 2-stage pipeline. grid (64, 1, BATCH).
// smem: A stages [2 x 10240) at 0; Bh @ 20480 (34816 B, pitch 272); Bl @ 55296.
// ============================================================================
#define M2_ASTG 10240
#define M2_BH   20480
#define M2_BLD  34816     // Bl = Bh + this
#define M2_BPITCH 272
#define M2_SMEM 90112

__global__ void __launch_bounds__(256, 2)
msim2_k(const float* __restrict__ qkv, const float* __restrict__ knnk,
        float* __restrict__ msim)
{
    extern __shared__ char smem_c[];
    unsigned sbase = (unsigned)__cvta_generic_to_shared(smem_c);

    int batch = blockIdx.z;
    int col0 = blockIdx.x * 128;
    const float* Aq = qkv + (long)batch * NTOK * 384;          // q, stride 384
    const float* Bk = knnk + (long)batch * MKEYS * DMODEL;
    float*       Cb = msim + (long)batch * NTOK * MKEYS;

    int tid = threadIdx.x;
    int lane = tid & 31, warp = tid >> 5;
    int wm = warp >> 2, wn = warp & 3;
    int g = lane >> 2, tg = lane & 3;

    int ar = tid >> 3, ak = (tid & 7) * 4;
    int bnTB = tid >> 3, bkTB = (tid & 7) * 4;

    // ---- stage full B tile (128 n x 128 k), hi/lo bf16, pitch 272
    #pragma unroll
    for (int kh = 0; kh < 4; kh++) {
        #pragma unroll
        for (int p = 0; p < 4; p++) {
            int n = bnTB + p * 32;
            int kg = kh * 32 + bkTB;
            float4 v = *(const float4*)&Bk[(long)(col0 + n) * DMODEL + kg];
            float vv[4] = {v.x, v.y, v.z, v.w};
            unsigned short h[4], l[4];
            #pragma unroll
            for (int j = 0; j < 4; j++) split_bf16(vv[j], h[j], l[j]);
            *(uint2*)(smem_c + M2_BH + n * M2_BPITCH + kg * 2) =
                make_uint2(((unsigned)h[1] << 16) | h[0], ((unsigned)h[3] << 16) | h[2]);
            *(uint2*)(smem_c + M2_BH + M2_BLD + n * M2_BPITCH + kg * 2) =
                make_uint2(((unsigned)l[1] << 16) | l[0], ((unsigned)l[3] << 16) | l[2]);
        }
    }

    float4 pa[2];
    auto loadA = [&](int row0, int k0) {
        #pragma unroll
        for (int p = 0; p < 2; p++) {
            int gr = row0 + ar + p * 32, gk = k0 + ak;
            float4 v = make_float4(0.f, 0.f, 0.f, 0.f);
            if (gr < NTOK) v = *(const float4*)&Aq[(long)gr * 384 + gk];
            pa[p] = v;
        }
    };
    auto storeA = [&](int st) {
        char* sb = smem_c + st * M2_ASTG;
        #pragma unroll
        for (int p = 0; p < 2; p++) {
            int r = ar + p * 32;
            float vv[4] = {pa[p].x, pa[p].y, pa[p].z, pa[p].w};
            unsigned short h[4], l[4];
            #pragma unroll
            for (int j = 0; j < 4; j++) split_bf16(vv[j], h[j], l[j]);
            *(uint2*)(sb + r * A_PITCH_B + ak * 2) =
                make_uint2(((unsigned)h[1] << 16) | h[0], ((unsigned)h[3] << 16) | h[2]);
            *(uint2*)(sb + AL_OFF + r * A_PITCH_B + ak * 2) =
                make_uint2(((unsigned)l[1] << 16) | l[0], ((unsigned)l[3] << 16) | l[2]);
        }
    };

    for (int y = 0; y < 4; y++) {
        int row0 = y * 64;

        float acc[2][4][4];
        #pragma unroll
        for (int im = 0; im < 2; im++)
            #pragma unroll
            for (int jn = 0; jn < 4; jn++)
                #pragma unroll
                for (int c = 0; c < 4; c++) acc[im][jn][c] = 0.f;

        // protect stage reuse from previous y-iteration (and B fill on y=0)
        loadA(row0, 0);
        __syncthreads();
        storeA(0);
        __syncthreads();

        int stage = 0;
        #pragma unroll
        for (int c = 0; c < 4; c++) {
            if (c + 1 < 4) loadA(row0, (c + 1) * 32);

            unsigned stb = sbase + stage * M2_ASTG;
            #pragma unroll
            for (int ks2 = 0; ks2 < 2; ks2++) {
                int ksb = ks2 * 32;                   // byte offset within A stage
                int kbyte = c * 64 + ks2 * 32;        // byte offset within B tile (k*2)
                unsigned ah[2][4], al_[2][4];
                #pragma unroll
                for (int im = 0; im < 2; im++) {
                    unsigned aaddr = stb
                        + (unsigned)((wm * 32 + im * 16 + (lane & 15)) * A_PITCH_B
                                     + ((lane >> 4) * 16) + ksb);
                    LDSM4(ah[im][0], ah[im][1], ah[im][2], ah[im][3], aaddr);
                    LDSM4(al_[im][0], al_[im][1], al_[im][2], al_[im][3], aaddr + AL_OFF);
                }
                unsigned bh[4][2], bl_[4][2];
                #pragma unroll
                for (int pr = 0; pr < 2; pr++) {
                    int nb2 = wn * 32 + pr * 16;
                    unsigned baddr = sbase + M2_BH
                        + (unsigned)((nb2 + ((lane >> 4) << 3) + (lane & 7)) * M2_BPITCH
                                     + (((lane >> 3) & 1) * 16) + kbyte);
                    unsigned r0, r1, r2, r3;
                    LDSM4(r0, r1, r2, r3, baddr);
                    bh[2*pr][0] = r0; bh[2*pr][1] = r1; bh[2*pr+1][0] = r2; bh[2*pr+1][1] = r3;
                    LDSM4(r0, r1, r2, r3, baddr + M2_BLD);
                    bl_[2*pr][0] = r0; bl_[2*pr][1] = r1; bl_[2*pr+1][0] = r2; bl_[2*pr+1][1] = r3;
                }
                #pragma unroll
                for (int im = 0; im < 2; im++)
                    #pragma unroll
                    for (int jn = 0; jn < 4; jn++) {
                        MMA_BF16(acc[im][jn], ah[im], bl_[jn]);
                        MMA_BF16(acc[im][jn], al_[im], bh[jn]);
                        MMA_BF16(acc[im][jn], ah[im], bh[jn]);
                    }
            }

            if (c + 1 < 4) {
                storeA(stage ^ 1);
                __syncthreads();
                stage ^= 1;
            }
        }

        // epilogue
        #pragma unroll
        for (int im = 0; im < 2; im++) {
            #pragma unroll
            for (int jn = 0; jn < 4; jn++) {
                int r0 = row0 + wm * 32 + im * 16 + g;
                int c0 = col0 + wn * 32 + jn * 8 + 2 * tg;
                #pragma unroll
                for (int half = 0; half < 2; half++) {
                    int gr = r0 + half * 8;
                    if (gr >= NTOK) continue;
                    Cb[(long)gr * MKEYS + c0    ] = acc[im][jn][half * 2 + 0] * SCALE;
                    Cb[(long)gr * MKEYS + c0 + 1] = acc[im][jn][half * 2 + 1] * SCALE;
                }
            }
        }
    }
}

// ============================================================================
// Fused softmax + av GEMM (R12-verified).
// ============================================================================
#define SATT_PITCH 204
#define SMEM_AV (SMEM2 + 64*SATT_PITCH*4)

__global__ void __launch_bounds__(256)
mmasav_k(const float* __restrict__ Att, const float* __restrict__ Bm,
         float* __restrict__ C, int nbatch)
{
    extern __shared__ char smem_c[];
    unsigned sbase = (unsigned)__cvta_generic_to_shared(smem_c);
    float* satt = (float*)(smem_c + SMEM2);

    int batch = blockIdx.z % nbatch;
    const float* Ab = Att + (long)batch * NTOK * NTOK;
    const float* Bb = Bm + (long)batch * NTOK * 384;
    float*       Cb = C + (long)batch * NTOK * DMODEL;

    int row0 = blockIdx.y * 64;
    int tid = threadIdx.x;
    int lane = tid & 31, warp = tid >> 5;
    int wm = warp >> 2, wn = warp & 3;
    int g = lane >> 2, tg = lane & 3;

    for (int idx = tid; idx < 64 * NTOK; idx += 256) {
        int r = idx / NTOK, c = idx % NTOK;
        int gr = row0 + r;
        satt[r * SATT_PITCH + c] = (gr < NTOK) ? Ab[(long)gr * NTOK + c] : 0.f;
    }
    __syncthreads();

    {
        int r = tid >> 2, part = tid & 3;
        float* rowp = satt + r * SATT_PITCH;
        float mx = -3.4e38f;
        for (int c = part; c < NTOK; c += 4) mx = fmaxf(mx, rowp[c]);
        mx = fmaxf(mx, __shfl_xor_sync(0xffffffffu, mx, 1));
        mx = fmaxf(mx, __shfl_xor_sync(0xffffffffu, mx, 2));
        float sum = 0.f;
        for (int c = part; c < NTOK; c += 4) {
            float e = expf(rowp[c] - mx);
            rowp[c] = e;
            sum += e;
        }
        sum += __shfl_xor_sync(0xffffffffu, sum, 1);
        sum += __shfl_xor_sync(0xffffffffu, sum, 2);
        float inv = 1.f / sum;
        for (int c = part; c < NTOK; c += 4) rowp[c] *= inv;
    }
    __syncthreads();

    int ar = tid >> 3, ak = (tid & 7) * 4;
    int bkNN = tid >> 5, bnNN = (tid & 31) * 4;
    const int K = NTOK, Nc = DMODEL;

    float4 pa[2], pb[4];

    auto loadA = [&](int k0) {
        #pragma unroll
        for (int p = 0; p < 2; p++) {
            int r = ar + p * 32, gk = k0 + ak;
            float4 v = make_float4(0.f, 0.f, 0.f, 0.f);
            if (gk + 3 < K) {
                v = *(const float4*)&satt[r * SATT_PITCH + gk];
            } else {
                if (gk + 0 < K) v.x = satt[r * SATT_PITCH + gk + 0];
                if (gk + 1 < K) v.y = satt[r * SATT_PITCH + gk + 1];
                if (gk + 2 < K) v.z = satt[r * SATT_PITCH + gk + 2];
                if (gk + 3 < K) v.w = satt[r * SATT_PITCH + gk + 3];
            }
            pa[p] = v;
        }
    };
    auto loadB = [&](int k0) {
        #pragma unroll
        for (int p = 0; p < 4; p++) {
            int gk = k0 + bkNN + p * 8, gn = bnNN;
            float4 v = make_float4(0.f, 0.f, 0.f, 0.f);
            if (gk < K && gn + 3 < Nc)
                v = *(const float4*)&Bb[(long)gk * 384 + gn];
            pb[p] = v;
        }
    };
    auto storeTiles = [&](int st) {
        char* sb = smem_c + st * STAGE_B;
        #pragma unroll
        for (int p = 0; p < 2; p++) {
            int r = ar + p * 32;
            float vv[4] = {pa[p].x, pa[p].y, pa[p].z, pa[p].w};
            unsigned short h[4], l[4];
            #pragma unroll
            for (int j = 0; j < 4; j++) split_bf16(vv[j], h[j], l[j]);
            *(uint2*)(sb + r * A_PITCH_B + ak * 2) =
                make_uint2(((unsigned)h[1] << 16) | h[0], ((unsigned)h[3] << 16) | h[2]);
            *(uint2*)(sb + AL_OFF + r * A_PITCH_B + ak * 2) =
                make_uint2(((unsigned)l[1] << 16) | l[0], ((unsigned)l[3] << 16) | l[2]);
        }
        #pragma unroll
        for (int p = 0; p < 4; p++) {
            int k = bkNN + p * 8;
            float vv[4] = {pb[p].x, pb[p].y, pb[p].z, pb[p].w};
            unsigned short h[4], l[4];
            #pragma unroll
            for (int j = 0; j < 4; j++) split_bf16(vv[j], h[j], l[j]);
            *(uint2*)(sb + BH_OFF + k * BNN_PITCH_B + bnNN * 2) =
                make_uint2(((unsigned)h[1] << 16) | h[0], ((unsigned)h[3] << 16) | h[2]);
            *(uint2*)(sb + BL_OFF + k * BNN_PITCH_B + bnNN * 2) =
                make_uint2(((unsigned)l[1] << 16) | l[0], ((unsigned)l[3] << 16) | l[2]);
        }
    };

    float acc[2][4][4];
    #pragma unroll
    for (int im = 0; im < 2; im++)
        #pragma unroll
        for (int jn = 0; jn < 4; jn++)
            #pragma unroll
            for (int c = 0; c < 4; c++) acc[im][jn][c] = 0.f;

    int nch = (K + 31) / 32;
    int stage = 0;

    loadA(0); loadB(0);
    storeTiles(0);
    __syncthreads();

    for (int c = 0; c < nch; c++) {
        if (c + 1 < nch) { loadA((c + 1) * 32); loadB((c + 1) * 32); }

        unsigned stb = sbase + stage * STAGE_B;
        #pragma unroll
        for (int ks2 = 0; ks2 < 2; ks2++) {
            int ksb = ks2 * 32;
            unsigned ah[2][4], al_[2][4];
            #pragma unroll
            for (int im = 0; im < 2; im++) {
                unsigned aaddr = stb
                    + (unsigned)((wm * 32 + im * 16 + (lane & 15)) * A_PITCH_B
                                 + ((lane >> 4) * 16) + ksb);
                LDSM4(ah[im][0], ah[im][1], ah[im][2], ah[im][3], aaddr);
                LDSM4(al_[im][0], al_[im][1], al_[im][2], al_[im][3], aaddr + AL_OFF);
            }
            unsigned bh[4][2], bl_[4][2];
            #pragma unroll
            for (int pr = 0; pr < 2; pr++) {
                int nb2 = wn * 32 + pr * 16;
                unsigned baddr = stb + BH_OFF
                    + (unsigned)((ks2 * 16 + ((lane >> 3) & 1) * 8 + (lane & 7)) * BNN_PITCH_B
                                 + (nb2 + (lane >> 4) * 8) * 2);
                unsigned r0, r1, r2, r3;
                LDSM4T(r0, r1, r2, r3, baddr);
                bh[2*pr][0] = r0; bh[2*pr][1] = r1; bh[2*pr+1][0] = r2; bh[2*pr+1][1] = r3;
                LDSM4T(r0, r1, r2, r3, baddr + (BL_OFF - BH_OFF));
                bl_[2*pr][0] = r0; bl_[2*pr][1] = r1; bl_[2*pr+1][0] = r2; bl_[2*pr+1][1] = r3;
            }
            #pragma unroll
            for (int im = 0; im < 2; im++)
                #pragma unroll
                for (int jn = 0; jn < 4; jn++) {
                    MMA_BF16(acc[im][jn], ah[im], bl_[jn]);
                    MMA_BF16(acc[im][jn], al_[im], bh[jn]);
                    MMA_BF16(acc[im][jn], ah[im], bh[jn]);
                }
        }

        if (c + 1 < nch) {
            storeTiles(stage ^ 1);
            __syncthreads();
            stage ^= 1;
        }
    }

    #pragma unroll
    for (int im = 0; im < 2; im++) {
        #pragma unroll
        for (int jn = 0; jn < 4; jn++) {
            int r0 = row0 + wm * 32 + im * 16 + g;
            int c0 = wn * 32 + jn * 8 + 2 * tg;
            #pragma unroll
            for (int half = 0; half < 2; half++) {
                int gr = r0 + half * 8;
                if (gr >= NTOK) continue;
                #pragma unroll
                for (int cc = 0; cc < 2; cc++) {
                    int gn = c0 + cc;
                    Cb[(long)gr * DMODEL + gn] = acc[im][jn][half * 2 + cc];
                }
            }
        }
    }
}

// ---------------- split-K reduce + LN stats ----------------
__global__ void reduce_stats_k(const float* __restrict__ part, long sstride, int ns,
                               const float* __restrict__ bias, const float* __restrict__ res,
                               float* __restrict__ out,
                               float* __restrict__ mu, float* __restrict__ rstd)
{
    long row = blockIdx.x;
    int d = threadIdx.x;
    long idx = row * DMODEL + d;
    float s = 0.f;
    for (int k = 0; k < ns; k++) s += part[(long)k * sstride + idx];
    s += bias[d];
    if (res) s += res[idx];
    out[idx] = s;
    __shared__ float r1[4], r2[4];
    float v1 = s, v2 = s * s;
    #pragma unroll
    for (int o = 16; o > 0; o >>= 1) {
        v1 += __shfl_xor_sync(0xffffffffu, v1, o);
        v2 += __shfl_xor_sync(0xffffffffu, v2, o);
    }
    if ((d & 31) == 0) { r1[d >> 5] = v1; r2[d >> 5] = v2; }
    __syncthreads();
    if (d == 0) {
        float t1 = r1[0] + r1[1] + r1[2] + r1[3];
        float t2 = r2[0] + r2[1] + r2[2] + r2[3];
        float m = t1 * (1.f / 128.f);
        float var = t2 * (1.f / 128.f) - m * m;
        mu[row] = m;
        rstd[row] = rsqrtf(var + LNEPS);
    }
}

// ---------------- final LN + mean pool fused ----------------
__global__ void feats_k(const float* __restrict__ h, const float* __restrict__ mu,
                        const float* __restrict__ rstd,
                        const float* __restrict__ g, const float* __restrict__ b,
                        float* __restrict__ feats)
{
    int bb = blockIdx.x, d = threadIdx.x;
    float gd = g[d], bd = b[d];
    float s = 0.f;
    for (int n = 0; n < NTOK; n++) {
        long row = (long)bb * NTOK + n;
        s += (h[row * DMODEL + d] - mu[row]) * rstd[row] * gd + bd;
    }
    feats[bb * DMODEL + d] = s * (1.f / 196.f);
}

// ---------------- top-32: register-resident incremental argmax ----------------
__global__ void __launch_bounds__(256) topk_k(const float* __restrict__ msim,
                       float* __restrict__ mvals, int* __restrict__ midx)
{
    long row = blockIdx.x;
    int tid = threadIdx.x;
    int lane = tid & 31, wid = tid >> 5;
    const float* src = msim + row * MKEYS;

    float v[32];
    const float4* s4 = (const float4*)(src + tid * 32);
    #pragma unroll
    for (int i = 0; i < 8; i++) {
        float4 t = s4[i];
        v[i*4+0] = t.x; v[i*4+1] = t.y; v[i*4+2] = t.z; v[i*4+3] = t.w;
    }

    unsigned long long p = 0ull;
    #pragma unroll
    for (int i = 0; i < 32; i++) {
        unsigned u = __float_as_uint(v[i]);
        u = (u & 0x80000000u) ? ~u : (u | 0x80000000u);
        unsigned long long key = ((unsigned long long)u << 32) | (unsigned)(MKEYS - 1 - (tid * 32 + i));
        if (key > p) p = key;
    }

    __shared__ unsigned long long wmax[2][8];

    for (int it = 0; it < TOPK; it++) {
        unsigned long long q = p;
        #pragma unroll
        for (int o = 16; o > 0; o >>= 1) {
            unsigned long long other = __shfl_xor_sync(0xffffffffu, q, o);
            if (other > q) q = other;
        }
        if (lane == 0) wmax[it & 1][wid] = q;
        __syncthreads();
        unsigned long long best = wmax[it & 1][0];
        #pragma unroll
        for (int w = 1; w < 8; w++) {
            unsigned long long o2 = wmax[it & 1][w];
            if (o2 > best) best = o2;
        }
        int gidx = MKEYS - 1 - (int)(best & 0xffffffffu);
        if (tid == (gidx >> 5)) {
            int sub = gidx & 31;
            float bv = 0.f;
            #pragma unroll
            for (int i = 0; i < 32; i++)
                if (i == sub) { bv = v[i]; v[i] = -3.4e38f; }
            mvals[row * TOPK + it] = bv;
            midx [row * TOPK + it] = gidx;
            unsigned long long np = 0ull;
            #pragma unroll
            for (int i = 0; i < 32; i++) {
                unsigned u = __float_as_uint(v[i]);
                u = (u & 0x80000000u) ? ~u : (u | 0x80000000u);
                unsigned long long key = ((unsigned long long)u << 32) | (unsigned)(MKEYS - 1 - (tid * 32 + i));
                if (key > np) np = key;
            }
            p = np;
        }
    }
}

// ---------------- kNN combine ----------------
__global__ void knn_combine_k(const float* __restrict__ att,
                              const float* __restrict__ mvals, const int* __restrict__ midx,
                              const float* __restrict__ qkv, const float* __restrict__ knn_v,
                              float* __restrict__ out)
{
    long row = blockIdx.x;
    int b = (int)(row / NTOK);
    int tid = threadIdx.x;
    __shared__ float w[TOPK + NTOK];
    __shared__ int   sidx[TOPK];
    __shared__ float red[4];

    if (tid < TOPK) {
        w[tid]    = mvals[row * TOPK + tid];
        sidx[tid] = midx [row * TOPK + tid];
    }
    for (int m = tid; m < NTOK; m += 128) w[TOPK + m] = att[row * NTOK + m];
    __syncthreads();

    float l0 = w[tid];
    float l1 = (tid < (TOPK + NTOK - 128)) ? w[tid + 128] : -3.4e38f;
    float m = fmaxf(l0, l1);
    #pragma unroll
    for (int o = 16; o > 0; o >>= 1) m = fmaxf(m, __shfl_xor_sync(0xffffffffu, m, o));
    if ((tid & 31) == 0) red[tid >> 5] = m;
    __syncthreads();
    m = fmaxf(fmaxf(red[0], red[1]), fmaxf(red[2], red[3]));
    float e0 = expf(l0 - m);
    float e1 = (tid < (TOPK + NTOK - 128)) ? expf(l1 - m) : 0.f;
    float s = e0 + e1;
    __syncthreads();
    #pragma unroll
    for (int o = 16; o > 0; o >>= 1) s += __shfl_xor_sync(0xffffffffu, s, o);
    if ((tid & 31) == 0) red[tid >> 5] = s;
    __syncthreads();
    s = red[0] + red[1] + red[2] + red[3];
    float inv = 1.f / s;
    w[tid] = e0 * inv;
    if (tid < (TOPK + NTOK - 128)) w[tid + 128] = e1 * inv;
    __syncthreads();

    float acc = 0.f;
    const float* kv = knn_v + (long)b * MKEYS * DMODEL;
    #pragma unroll 4
    for (int j = 0; j < TOPK; j++)
        acc += w[j] * kv[(long)sidx[j] * DMODEL + tid];
    const float* vbase = qkv + ((long)b * NTOK) * 384 + 256;
    for (int mm = 0; mm < NTOK; mm++)
        acc += w[TOPK + mm] * vbase[(long)mm * 384 + tid];
    out[row * DMODEL + tid] = acc;
}

// ---------------- launch ----------------
extern "C" void kernel_launch(void* const* d_in, const int* in_sizes, int n_in,
                              void* d_out, int out_size)
{
    const float* x       = (const float*)d_in[0];
    const float* patch_w = (const float*)d_in[1];
    const float* patch_b = (const float*)d_in[2];
    const float* ln1_g   = (const float*)d_in[3];
    const float* ln1_b   = (const float*)d_in[4];
    const float* qkv_w   = (const float*)d_in[5];
    const float* qkv_b   = (const float*)d_in[6];
    const float* out_w   = (const float*)d_in[7];
    const float* out_b   = (const float*)d_in[8];
    const float* ln2_g   = (const float*)d_in[9];
    const float* ln2_b   = (const float*)d_in[10];
    const float* ff1_w   = (const float*)d_in[11];
    const float* ff1_b   = (const float*)d_in[12];
    const float* ff2_w   = (const float*)d_in[13];
    const float* ff2_b   = (const float*)d_in[14];
    const float* lnf_g   = (const float*)d_in[15];
    const float* lnf_b   = (const float*)d_in[16];
    const float* knn_k   = (const float*)d_in[17];
    const float* knn_v   = (const float*)d_in[18];
    const float* head_w  = (const float*)d_in[19];
    const float* head_b  = (const float*)d_in[20];
    float* out = (float*)d_out;

    void* tp;
    cudaGetSymbolAddress(&tp, g_h);    float* pH    = (float*)tp;
    cudaGetSymbolAddress(&tp, g_qkv);  float* pQKV  = (float*)tp;
    cudaGetSymbolAddress(&tp, g_att);  float* pATT  = (float*)tp;
    cudaGetSymbolAddress(&tp, g_msim); float* pMSIM = (float*)tp;
    cudaGetSymbolAddress(&tp, g_o);    float* pO    = (float*)tp;
    cudaGetSymbolAddress(&tp, g_ff);   float* pFF   = (float*)tp;
    cudaGetSymbolAddress(&tp, g_part); float* pPart = (float*)tp;
    cudaGetSymbolAddress(&tp, g_mv);   float* pMV   = (float*)tp;
    cudaGetSymbolAddress(&tp, g_mi);   int*   pMI   = (int*)tp;
    cudaGetSymbolAddress(&tp, g_feats);float* pFeat = (float*)tp;
    cudaGetSymbolAddress(&tp, g_mu);   float* pMu   = (float*)tp;
    cudaGetSymbolAddress(&tp, g_rs);   float* pRs   = (float*)tp;

    cudaFuncSetAttribute(mmabf_k<false,false,false,false>, cudaFuncAttributeMaxDynamicSharedMemorySize, SMEM2);
    cudaFuncSetAttribute(mmabf_k<true, false,false,false>, cudaFuncAttributeMaxDynamicSharedMemorySize, SMEM2);
    cudaFuncSetAttribute(mmabf_k<false,false,true ,false>, cudaFuncAttributeMaxDynamicSharedMemorySize, SMEM2);
    cudaFuncSetAttribute(mmabf_k<false,true ,true ,false>, cudaFuncAttributeMaxDynamicSharedMemorySize, SMEM2);
    cudaFuncSetAttribute(mmabf_k<false,false,false,true >, cudaFuncAttributeMaxDynamicSharedMemorySize, SMEM2);
    cudaFuncSetAttribute(mmabf_k<false,false,false,false,true>, cudaFuncAttributeMaxDynamicSharedMemorySize, SMEM2);
    cudaFuncSetAttribute(mmasav_k, cudaFuncAttributeMaxDynamicSharedMemorySize, SMEM_AV);
    cudaFuncSetAttribute(msim2_k, cudaFuncAttributeMaxDynamicSharedMemorySize, M2_SMEM);

    const long sPart = (long)ROWS * DMODEL;

    // patch embed: fused gather (PATCHA) + split-K 6 -> reduce + ln1 stats
    mmabf_k<false,false,false,false,true><<<dim3(1, 98, 6), 256, SMEM2>>>(x, patch_w, nullptr, nullptr, pPart,
        ROWS, DMODEL, PDIM, 0, PDIM, 0, DMODEL, 0, DMODEL, 1.f, 1, 6, sPart,
        nullptr, nullptr, nullptr, nullptr, nullptr, nullptr);
    reduce_stats_k<<<ROWS, 128>>>(pPart, sPart, 6, patch_b, nullptr, pH, pMu, pRs);

    for (int i = 0; i < DEPTH; i++) {
        // qkv with inline ln1
        mmabf_k<false,false,true,false><<<dim3(3, 98, 1), 256, SMEM2>>>(pH, qkv_w + (long)i * DMODEL * 3 * DMODEL,
            qkv_b + i * 3 * DMODEL, nullptr, pQKV,
            ROWS, 3 * DMODEL, DMODEL, 0, DMODEL, 0, 3 * DMODEL, 0, 3 * DMODEL, 1.f, 1, 1, 0,
            pMu, pRs, ln1_g + i * DMODEL, ln1_b + i * DMODEL, nullptr, nullptr);
        // sim = q @ k^T * scale
        mmabf_k<true,false,false,false><<<dim3(2, 4, BATCH), 256, SMEM2>>>(pQKV, pQKV + 128, nullptr, nullptr, pATT,
            NTOK, NTOK, DMODEL,
            (long)NTOK * 384, 384, (long)NTOK * 384, 384, (long)NTOK * NTOK, NTOK, SCALE, BATCH, 1, 0,
            nullptr, nullptr, nullptr, nullptr, nullptr, nullptr);

        if (i == KNN_LAYER) {
            // msim with persistent B tile + q-row loop
            msim2_k<<<dim3(MKEYS / 128, 1, BATCH), 256, M2_SMEM>>>(pQKV, knn_k, pMSIM);
            topk_k<<<ROWS, 256>>>(pMSIM, pMV, pMI);
            knn_combine_k<<<ROWS, 128>>>(pATT, pMV, pMI, pQKV, knn_v, pO);
        } else {
            // fused softmax + av
            mmasav_k<<<dim3(1, 4, BATCH), 256, SMEM_AV>>>(pATT, pQKV + 256, pO, BATCH);
        }

        // h = h + o @ out_w + out_b ; epilogue emits ln2 stats
        mmabf_k<false,false,false,true><<<dim3(1, 98, 1), 256, SMEM2>>>(pO, out_w + (long)i * DMODEL * DMODEL,
            out_b + i * DMODEL, pH, pH,
            ROWS, DMODEL, DMODEL, 0, DMODEL, 0, DMODEL, 0, DMODEL, 1.f, 1, 1, 0,
            nullptr, nullptr, nullptr, nullptr, pMu, pRs);

        // ff1 + gelu with inline ln2
        mmabf_k<false,true,true,false><<<dim3(4, 98, 1), 256, SMEM2>>>(pH, ff1_w + (long)i * DMODEL * FFH,
            ff1_b + i * FFH, nullptr, pFF,
            ROWS, FFH, DMODEL, 0, DMODEL, 0, FFH, 0, FFH, 1.f, 1, 1, 0,
            pMu, pRs, ln2_g + i * DMODEL, ln2_b + i * DMODEL, nullptr, nullptr);
        // ff2: split-K 4, reduce adds bias + residual h, emits next ln1 stats
        mmabf_k<false,false,false,false><<<dim3(1, 98, 4), 256, SMEM2>>>(pFF, ff2_w + (long)i * FFH * DMODEL,
            nullptr, nullptr, pPart,
            ROWS, DMODEL, FFH, 0, FFH, 0, DMODEL, 0, DMODEL, 1.f, 1, 4, sPart,
            nullptr, nullptr, nullptr, nullptr, nullptr, nullptr);
        reduce_stats_k<<<ROWS, 128>>>(pPart, sPart, 4, ff2_b + i * DMODEL, pH, pH, pMu, pRs);
    }

    // final LN + mean pool, then head
    feats_k<<<BATCH, 128>>>(pH, pMu, pRs, lnf_g, lnf_b, pFeat);
    mmabf_k<false,false,false,false><<<dim3(8, 1, 1), 256, SMEM2>>>(pFeat, head_w, head_b, nullptr, out,
        BATCH, NCLS, DMODEL, 0, DMODEL, 0, NCLS, 0, NCLS, 1.f, 1, 1, 0,
        nullptr, nullptr, nullptr, nullptr, nullptr, nullptr);
}

// round 16
// speedup vs baseline: 1.1024x; 1.0236x over previous
#include <cuda_runtime.h>
#include <cuda_bf16.h>
#include <cuda_fp16.h>
#include <math.h>

// ---------------- problem constants ----------------
#define BATCH   32
#define NTOK    196
#define DMODEL  128
#define ROWS    (BATCH*NTOK) // 6272
#define PDIM    768
#define DEPTH   7
#define KNN_LAYER 6
#define MKEYS   8192
#define TOPK    32
#define FFH     512
#define NCLS    1000
#define SCALE   0.08838834764831845f
#define LNEPS   1e-5f

// ---------------- device scratch ----------------
__device__ float g_h   [ (long)ROWS*DMODEL ];
__device__ float g_qkv [ (long)ROWS*3*DMODEL ];
__device__ float g_att [ (long)BATCH*NTOK*NTOK ];
__device__ __half g_msim[ (long)BATCH*NTOK*MKEYS ];   // fp16 logits (102 MB)
__device__ float g_o   [ (long)ROWS*DMODEL ];
__device__ float g_ff  [ (long)ROWS*FFH ];
__device__ float g_part[ (long)6*ROWS*DMODEL ];
__device__ float g_mv  [ (long)ROWS*TOPK ];
__device__ int   g_mi  [ (long)ROWS*TOPK ];
__device__ float g_feats[ BATCH*DMODEL ];
__device__ float g_mu  [ ROWS ];
__device__ float g_rs  [ ROWS ];

// ---------------- helpers ----------------
__device__ __forceinline__ float gelu_tanh(float v) {
    const float c = 0.7978845608028654f;
    float t = tanhf(c * (v + 0.044715f * v * v * v));
    return 0.5f * v * (1.f + t);
}
__device__ __forceinline__ void split_bf16(float v, unsigned short& h, unsigned short& l) {
    __nv_bfloat16 hb = __float2bfloat16_rn(v);
    h = __bfloat16_as_ushort(hb);
    l = __bfloat16_as_ushort(__float2bfloat16_rn(v - __bfloat162float(hb)));
}
#define MMA_BF16(ACC, A, B)                                                 \
    asm volatile(                                                           \
        "mma.sync.aligned.m16n8k16.row.col.f32.bf16.bf16.f32 "              \
        "{%0,%1,%2,%3}, {%4,%5,%6,%7}, {%8,%9}, {%0,%1,%2,%3};"             \
        : "+f"((ACC)[0]), "+f"((ACC)[1]), "+f"((ACC)[2]), "+f"((ACC)[3])    \
        : "r"((A)[0]), "r"((A)[1]), "r"((A)[2]), "r"((A)[3]),               \
          "r"((B)[0]), "r"((B)[1]))
#define LDSM4(R0,R1,R2,R3, ADDR)                                            \
    asm volatile("ldmatrix.sync.aligned.m8n8.x4.shared.b16 {%0,%1,%2,%3}, [%4];" \
        : "=r"(R0), "=r"(R1), "=r"(R2), "=r"(R3) : "r"(ADDR))
#define LDSM4T(R0,R1,R2,R3, ADDR)                                           \
    asm volatile("ldmatrix.sync.aligned.m8n8.x4.trans.shared.b16 {%0,%1,%2,%3}, [%4];" \
        : "=r"(R0), "=r"(R1), "=r"(R2), "=r"(R3) : "r"(ADDR))

// ---------------- bf16 split-2 mma GEMM (R9/R12 core) ----------------
#define A_PITCH_B 80
#define BTB_PITCH_B 80
#define BNN_PITCH_B 272
#define AL_OFF 5120
#define BH_OFF 10240
#define BL_OFF 20480
#define STAGE_B 30720
#define SMEM2 (2*STAGE_B)

template<bool TB, bool DOGELU, bool LNA, bool STATS, bool PATCHA = false>
__global__ void __launch_bounds__(256, 2)
mmabf_k(const float* __restrict__ A, const float* __restrict__ Bm,
        const float* __restrict__ bias, const float* __restrict__ Res,
        float* __restrict__ C,
        int Mr, int Nc, int K,
        long sAb, int lda, long sBb, int ldb, long sCb, int ldc,
        float alpha, int nbatch, int kslices, long sPart,
        const float* __restrict__ muA, const float* __restrict__ rsA,
        const float* __restrict__ lngA, const float* __restrict__ lnbA,
        float* __restrict__ muO, float* __restrict__ rsO)
{
    extern __shared__ char smem_c[];
    unsigned sbase = (unsigned)__cvta_generic_to_shared(smem_c);

    int bz = blockIdx.z;
    int batch = bz % nbatch;
    int ksl   = bz / nbatch;
    int Kslice = K / kslices;
    int Klo = ksl * Kslice;
    int Khi = (ksl == kslices - 1) ? K : Klo + Kslice;

    const float* Ab = A + (PATCHA ? 0 : (long)batch * sAb);
    const float* Bb = Bm + (long)batch * sBb;
    float*       Cb;
    const float* Rb;
    if (kslices > 1) {
        Cb = C + (long)ksl * sPart + (long)batch * sCb;
        Rb = nullptr;
    } else {
        Cb = C + (long)batch * sCb;
        Rb = Res ? (Res + (long)batch * sCb) : nullptr;
    }

    int row0 = blockIdx.y * 64;
    int col0 = blockIdx.x * 128;
    int tid = threadIdx.x;
    int lane = tid & 31, warp = tid >> 5;
    int wm = warp >> 2, wn = warp & 3;
    int g = lane >> 2, tg = lane & 3;

    int ar = tid >> 3, ak = (tid & 7) * 4;
    int bkNN = tid >> 5, bnNN = (tid & 31) * 4;
    int bnTB = tid >> 3, bkTB = (tid & 7) * 4;

    float4 pa[2], pb[4];

    auto loadA = [&](int k0) {
        #pragma unroll
        for (int p = 0; p < 2; p++) {
            int gr = row0 + ar + p * 32, gk = k0 + ak;
            float4 v = make_float4(0.f, 0.f, 0.f, 0.f);
            if (PATCHA) {
                if (gr < Mr) {
                    int b  = gr / NTOK, n = gr % NTOK;
                    int i  = n / 14,    j = n % 14;
                    int ch = gk >> 8;
                    int r  = gk & 255;
                    int pi = r >> 4, pj = r & 15;
                    const float* xs = Ab + (((long)b * 3 + ch) * 224 + (i * 16 + pi)) * 224
                                         + (j * 16 + pj);
                    v = *(const float4*)xs;
                }
            } else if (gr < Mr) {
                if (gk + 3 < Khi) {
                    v = *(const float4*)&Ab[(long)gr * lda + gk];
                    if (LNA) {
                        float mu = __ldg(&muA[gr]);
                        float rs = __ldg(&rsA[gr]);
                        float4 gg = *(const float4*)&lngA[gk];
                        float4 bb = *(const float4*)&lnbA[gk];
                        v.x = (v.x - mu) * rs * gg.x + bb.x;
                        v.y = (v.y - mu) * rs * gg.y + bb.y;
                        v.z = (v.z - mu) * rs * gg.z + bb.z;
                        v.w = (v.w - mu) * rs * gg.w + bb.w;
                    }
                } else {
                    if (gk + 0 < Khi) v.x = Ab[(long)gr * lda + gk + 0];
                    if (gk + 1 < Khi) v.y = Ab[(long)gr * lda + gk + 1];
                    if (gk + 2 < Khi) v.z = Ab[(long)gr * lda + gk + 2];
                    if (gk + 3 < Khi) v.w = Ab[(long)gr * lda + gk + 3];
                }
            }
            pa[p] = v;
        }
    };
    auto loadB = [&](int k0) {
        if (TB) {
            #pragma unroll
            for (int p = 0; p < 4; p++) {
                int gn = col0 + bnTB + p * 32, gk = k0 + bkTB;
                float4 v = make_float4(0.f, 0.f, 0.f, 0.f);
                if (gn < Nc) {
                    if (gk + 3 < Khi) v = *(const float4*)&Bb[(long)gn * ldb + gk];
                    else {
                        if (gk + 0 < Khi) v.x = Bb[(long)gn * ldb + gk + 0];
                        if (gk + 1 < Khi) v.y = Bb[(long)gn * ldb + gk + 1];
                        if (gk + 2 < Khi) v.z = Bb[(long)gn * ldb + gk + 2];
                        if (gk + 3 < Khi) v.w = Bb[(long)gn * ldb + gk + 3];
                    }
                }
                pb[p] = v;
            }
        } else {
            #pragma unroll
            for (int p = 0; p < 4; p++) {
                int gk = k0 + bkNN + p * 8, gn = col0 + bnNN;
                float4 v = make_float4(0.f, 0.f, 0.f, 0.f);
                if (gk < Khi) {
                    if (gn + 3 < Nc) v = *(const float4*)&Bb[(long)gk * ldb + gn];
                    else {
                        if (gn + 0 < Nc) v.x = Bb[(long)gk * ldb + gn + 0];
                        if (gn + 1 < Nc) v.y = Bb[(long)gk * ldb + gn + 1];
                        if (gn + 2 < Nc) v.z = Bb[(long)gk * ldb + gn + 2];
                        if (gn + 3 < Nc) v.w = Bb[(long)gk * ldb + gn + 3];
                    }
                }
                pb[p] = v;
            }
        }
    };
    auto storeTiles = [&](int st) {
        char* sb = smem_c + st * STAGE_B;
        #pragma unroll
        for (int p = 0; p < 2; p++) {
            int r = ar + p * 32;
            float vv[4] = {pa[p].x, pa[p].y, pa[p].z, pa[p].w};
            unsigned short h[4], l[4];
            #pragma unroll
            for (int j = 0; j < 4; j++) split_bf16(vv[j], h[j], l[j]);
            *(uint2*)(sb + r * A_PITCH_B + ak * 2) =
                make_uint2(((unsigned)h[1] << 16) | h[0], ((unsigned)h[3] << 16) | h[2]);
            *(uint2*)(sb + AL_OFF + r * A_PITCH_B + ak * 2) =
                make_uint2(((unsigned)l[1] << 16) | l[0], ((unsigned)l[3] << 16) | l[2]);
        }
        if (TB) {
            #pragma unroll
            for (int p = 0; p < 4; p++) {
                int n = bnTB + p * 32;
                float vv[4] = {pb[p].x, pb[p].y, pb[p].z, pb[p].w};
                unsigned short h[4], l[4];
                #pragma unroll
                for (int j = 0; j < 4; j++) split_bf16(vv[j], h[j], l[j]);
                *(uint2*)(sb + BH_OFF + n * BTB_PITCH_B + bkTB * 2) =
                    make_uint2(((unsigned)h[1] << 16) | h[0], ((unsigned)h[3] << 16) | h[2]);
                *(uint2*)(sb + BL_OFF + n * BTB_PITCH_B + bkTB * 2) =
                    make_uint2(((unsigned)l[1] << 16) | l[0], ((unsigned)l[3] << 16) | l[2]);
            }
        } else {
            #pragma unroll
            for (int p = 0; p < 4; p++) {
                int k = bkNN + p * 8;
                float vv[4] = {pb[p].x, pb[p].y, pb[p].z, pb[p].w};
                unsigned short h[4], l[4];
                #pragma unroll
                for (int j = 0; j < 4; j++) split_bf16(vv[j], h[j], l[j]);
                *(uint2*)(sb + BH_OFF + k * BNN_PITCH_B + bnNN * 2) =
                    make_uint2(((unsigned)h[1] << 16) | h[0], ((unsigned)h[3] << 16) | h[2]);
                *(uint2*)(sb + BL_OFF + k * BNN_PITCH_B + bnNN * 2) =
                    make_uint2(((unsigned)l[1] << 16) | l[0], ((unsigned)l[3] << 16) | l[2]);
            }
        }
    };

    float acc[2][4][4];
    #pragma unroll
    for (int im = 0; im < 2; im++)
        #pragma unroll
        for (int jn = 0; jn < 4; jn++)
            #pragma unroll
            for (int c = 0; c < 4; c++) acc[im][jn][c] = 0.f;

    int nch = (Khi - Klo + 31) / 32;
    int stage = 0;

    loadA(Klo); loadB(Klo);
    storeTiles(0);
    __syncthreads();

    for (int c = 0; c < nch; c++) {
        if (c + 1 < nch) { loadA(Klo + (c + 1) * 32); loadB(Klo + (c + 1) * 32); }

        unsigned stb = sbase + stage * STAGE_B;
        #pragma unroll
        for (int ks2 = 0; ks2 < 2; ks2++) {
            int ksb = ks2 * 32;
            unsigned ah[2][4], al_[2][4];
            #pragma unroll
            for (int im = 0; im < 2; im++) {
                unsigned aaddr = stb
                    + (unsigned)((wm * 32 + im * 16 + (lane & 15)) * A_PITCH_B
                                 + ((lane >> 4) * 16) + ksb);
                LDSM4(ah[im][0], ah[im][1], ah[im][2], ah[im][3], aaddr);
                LDSM4(al_[im][0], al_[im][1], al_[im][2], al_[im][3], aaddr + AL_OFF);
            }
            unsigned bh[4][2], bl_[4][2];
            #pragma unroll
            for (int pr = 0; pr < 2; pr++) {
                int nb2 = wn * 32 + pr * 16;
                unsigned baddr;
                if (TB) {
                    baddr = stb + BH_OFF
                        + (unsigned)((nb2 + ((lane >> 4) << 3) + (lane & 7)) * BTB_PITCH_B
                                     + (((lane >> 3) & 1) * 16) + ksb);
                } else {
                    baddr = stb + BH_OFF
                        + (unsigned)((ks2 * 16 + ((lane >> 3) & 1) * 8 + (lane & 7)) * BNN_PITCH_B
                                     + (nb2 + (lane >> 4) * 8) * 2);
                }
                unsigned r0, r1, r2, r3;
                if (TB) { LDSM4(r0, r1, r2, r3, baddr); }
                else    { LDSM4T(r0, r1, r2, r3, baddr); }
                bh[2*pr][0] = r0; bh[2*pr][1] = r1; bh[2*pr+1][0] = r2; bh[2*pr+1][1] = r3;
                unsigned laddr = baddr + (BL_OFF - BH_OFF);
                if (TB) { LDSM4(r0, r1, r2, r3, laddr); }
                else    { LDSM4T(r0, r1, r2, r3, laddr); }
                bl_[2*pr][0] = r0; bl_[2*pr][1] = r1; bl_[2*pr+1][0] = r2; bl_[2*pr+1][1] = r3;
            }
            #pragma unroll
            for (int im = 0; im < 2; im++)
                #pragma unroll
                for (int jn = 0; jn < 4; jn++) {
                    MMA_BF16(acc[im][jn], ah[im], bl_[jn]);
                    MMA_BF16(acc[im][jn], al_[im], bh[jn]);
                    MMA_BF16(acc[im][jn], ah[im], bh[jn]);
                }
        }

        if (c + 1 < nch) {
            storeTiles(stage ^ 1);
            __syncthreads();
            stage ^= 1;
        }
    }

    // ---- epilogue
    float st1[2][2], st2[2][2];
    if (STATS) {
        #pragma unroll
        for (int im = 0; im < 2; im++)
            #pragma unroll
            for (int hh = 0; hh < 2; hh++) { st1[im][hh] = 0.f; st2[im][hh] = 0.f; }
    }
    #pragma unroll
    for (int im = 0; im < 2; im++) {
        #pragma unroll
        for (int jn = 0; jn < 4; jn++) {
            int r0 = row0 + wm * 32 + im * 16 + g;
            int c0 = col0 + wn * 32 + jn * 8 + 2 * tg;
            #pragma unroll
            for (int half = 0; half < 2; half++) {
                int gr = r0 + half * 8;
                if (gr >= Mr) continue;
                #pragma unroll
                for (int cc = 0; cc < 2; cc++) {
                    int gn = c0 + cc;
                    if (gn >= Nc) continue;
                    float v = acc[im][jn][half * 2 + cc] * alpha;
                    if (kslices == 1) {
                        if (bias) v += bias[gn];
                        if (Rb)   v += Rb[(long)gr * ldc + gn];
                        if (DOGELU) v = gelu_tanh(v);
                    }
                    if (STATS) { st1[im][half] += v; st2[im][half] += v * v; }
                    Cb[(long)gr * ldc + gn] = v;
                }
            }
        }
    }
    if (STATS) {
        __syncthreads();
        float* s1 = (float*)smem_c;
        float* s2 = s1 + 256;
        #pragma unroll
        for (int im = 0; im < 2; im++)
            #pragma unroll
            for (int hh = 0; hh < 2; hh++) {
                float x1 = st1[im][hh], x2 = st2[im][hh];
                x1 += __shfl_xor_sync(0xffffffffu, x1, 1);
                x1 += __shfl_xor_sync(0xffffffffu, x1, 2);
                x2 += __shfl_xor_sync(0xffffffffu, x2, 1);
                x2 += __shfl_xor_sync(0xffffffffu, x2, 2);
                if (tg == 0) {
                    int lr = wm * 32 + im * 16 + g + hh * 8;
                    s1[wn * 64 + lr] = x1;
                    s2[wn * 64 + lr] = x2;
                }
            }
        __syncthreads();
        if (tid < 64) {
            float t1 = s1[tid] + s1[64 + tid] + s1[128 + tid] + s1[192 + tid];
            float t2 = s2[tid] + s2[64 + tid] + s2[128 + tid] + s2[192 + tid];
            float mu = t1 * (1.f / 128.f);
            float var = t2 * (1.f / 128.f) - mu * mu;
            muO[row0 + tid] = mu;
            rsO[row0 + tid] = rsqrtf(var + LNEPS);
        }
    }
}

// ============================================================================
// msim2: B (knn_k 128x128 tile) staged ONCE; loop over 4 q-row-tiles.
// fp16 output. grid (64, 1, BATCH).
// ============================================================================
#define M2_ASTG 10240
#define M2_BH   20480
#define M2_BLD  34816
#define M2_BPITCH 272
#define M2_SMEM 90112

__global__ void __launch_bounds__(256, 2)
msim2_k(const float* __restrict__ qkv, const float* __restrict__ knnk,
        __half* __restrict__ msim)
{
    extern __shared__ char smem_c[];
    unsigned sbase = (unsigned)__cvta_generic_to_shared(smem_c);

    int batch = blockIdx.z;
    int col0 = blockIdx.x * 128;
    const float* Aq = qkv + (long)batch * NTOK * 384;
    const float* Bk = knnk + (long)batch * MKEYS * DMODEL;
    __half*      Cb = msim + (long)batch * NTOK * MKEYS;

    int tid = threadIdx.x;
    int lane = tid & 31, warp = tid >> 5;
    int wm = warp >> 2, wn = warp & 3;
    int g = lane >> 2, tg = lane & 3;

    int ar = tid >> 3, ak = (tid & 7) * 4;
    int bnTB = tid >> 3, bkTB = (tid & 7) * 4;

    #pragma unroll
    for (int kh = 0; kh < 4; kh++) {
        #pragma unroll
        for (int p = 0; p < 4; p++) {
            int n = bnTB + p * 32;
            int kg = kh * 32 + bkTB;
            float4 v = *(const float4*)&Bk[(long)(col0 + n) * DMODEL + kg];
            float vv[4] = {v.x, v.y, v.z, v.w};
            unsigned short h[4], l[4];
            #pragma unroll
            for (int j = 0; j < 4; j++) split_bf16(vv[j], h[j], l[j]);
            *(uint2*)(smem_c + M2_BH + n * M2_BPITCH + kg * 2) =
                make_uint2(((unsigned)h[1] << 16) | h[0], ((unsigned)h[3] << 16) | h[2]);
            *(uint2*)(smem_c + M2_BH + M2_BLD + n * M2_BPITCH + kg * 2) =
                make_uint2(((unsigned)l[1] << 16) | l[0], ((unsigned)l[3] << 16) | l[2]);
        }
    }

    float4 pa[2];
    auto loadA = [&](int row0, int k0) {
        #pragma unroll
        for (int p = 0; p < 2; p++) {
            int gr = row0 + ar + p * 32, gk = k0 + ak;
            float4 v = make_float4(0.f, 0.f, 0.f, 0.f);
            if (gr < NTOK) v = *(const float4*)&Aq[(long)gr * 384 + gk];
            pa[p] = v;
        }
    };
    auto storeA = [&](int st) {
        char* sb = smem_c + st * M2_ASTG;
        #pragma unroll
        for (int p = 0; p < 2; p++) {
            int r = ar + p * 32;
            float vv[4] = {pa[p].x, pa[p].y, pa[p].z, pa[p].w};
            unsigned short h[4], l[4];
            #pragma unroll
            for (int j = 0; j < 4; j++) split_bf16(vv[j], h[j], l[j]);
            *(uint2*)(sb + r * A_PITCH_B + ak * 2) =
                make_uint2(((unsigned)h[1] << 16) | h[0], ((unsigned)h[3] << 16) | h[2]);
            *(uint2*)(sb + AL_OFF + r * A_PITCH_B + ak * 2) =
                make_uint2(((unsigned)l[1] << 16) | l[0], ((unsigned)l[3] << 16) | l[2]);
        }
    };

    for (int y = 0; y < 4; y++) {
        int row0 = y * 64;

        float acc[2][4][4];
        #pragma unroll
        for (int im = 0; im < 2; im++)
            #pragma unroll
            for (int jn = 0; jn < 4; jn++)
                #pragma unroll
                for (int c = 0; c < 4; c++) acc[im][jn][c] = 0.f;

        loadA(row0, 0);
        __syncthreads();
        storeA(0);
        __syncthreads();

        int stage = 0;
        #pragma unroll
        for (int c = 0; c < 4; c++) {
            if (c + 1 < 4) loadA(row0, (c + 1) * 32);

            unsigned stb = sbase + stage * M2_ASTG;
            #pragma unroll
            for (int ks2 = 0; ks2 < 2; ks2++) {
                int ksb = ks2 * 32;
                int kbyte = c * 64 + ks2 * 32;
                unsigned ah[2][4], al_[2][4];
                #pragma unroll
                for (int im = 0; im < 2; im++) {
                    unsigned aaddr = stb
                        + (unsigned)((wm * 32 + im * 16 + (lane & 15)) * A_PITCH_B
                                     + ((lane >> 4) * 16) + ksb);
                    LDSM4(ah[im][0], ah[im][1], ah[im][2], ah[im][3], aaddr);
                    LDSM4(al_[im][0], al_[im][1], al_[im][2], al_[im][3], aaddr + AL_OFF);
                }
                unsigned bh[4][2], bl_[4][2];
                #pragma unroll
                for (int pr = 0; pr < 2; pr++) {
                    int nb2 = wn * 32 + pr * 16;
                    unsigned baddr = sbase + M2_BH
                        + (unsigned)((nb2 + ((lane >> 4) << 3) + (lane & 7)) * M2_BPITCH
                                     + (((lane >> 3) & 1) * 16) + kbyte);
                    unsigned r0, r1, r2, r3;
                    LDSM4(r0, r1, r2, r3, baddr);
                    bh[2*pr][0] = r0; bh[2*pr][1] = r1; bh[2*pr+1][0] = r2; bh[2*pr+1][1] = r3;
                    LDSM4(r0, r1, r2, r3, baddr + M2_BLD);
                    bl_[2*pr][0] = r0; bl_[2*pr][1] = r1; bl_[2*pr+1][0] = r2; bl_[2*pr+1][1] = r3;
                }
                #pragma unroll
                for (int im = 0; im < 2; im++)
                    #pragma unroll
                    for (int jn = 0; jn < 4; jn++) {
                        MMA_BF16(acc[im][jn], ah[im], bl_[jn]);
                        MMA_BF16(acc[im][jn], al_[im], bh[jn]);
                        MMA_BF16(acc[im][jn], ah[im], bh[jn]);
                    }
            }

            if (c + 1 < 4) {
                storeA(stage ^ 1);
                __syncthreads();
                stage ^= 1;
            }
        }

        // epilogue: fp16 paired stores (c0 is even)
        #pragma unroll
        for (int im = 0; im < 2; im++) {
            #pragma unroll
            for (int jn = 0; jn < 4; jn++) {
                int r0 = row0 + wm * 32 + im * 16 + g;
                int c0 = col0 + wn * 32 + jn * 8 + 2 * tg;
                #pragma unroll
                for (int half = 0; half < 2; half++) {
                    int gr = r0 + half * 8;
                    if (gr >= NTOK) continue;
                    __half2 hv = __floats2half2_rn(acc[im][jn][half * 2 + 0] * SCALE,
                                                   acc[im][jn][half * 2 + 1] * SCALE);
                    *(__half2*)&Cb[(long)gr * MKEYS + c0] = hv;
                }
            }
        }
    }
}

// ============================================================================
// Fused softmax + av GEMM (R12-verified).
// ============================================================================
#define SATT_PITCH 204
#define SMEM_AV (SMEM2 + 64*SATT_PITCH*4)

__global__ void __launch_bounds__(256)
mmasav_k(const float* __restrict__ Att, const float* __restrict__ Bm,
         float* __restrict__ C, int nbatch)
{
    extern __shared__ char smem_c[];
    unsigned sbase = (unsigned)__cvta_generic_to_shared(smem_c);
    float* satt = (float*)(smem_c + SMEM2);

    int batch = blockIdx.z % nbatch;
    const float* Ab = Att + (long)batch * NTOK * NTOK;
    const float* Bb = Bm + (long)batch * NTOK * 384;
    float*       Cb = C + (long)batch * NTOK * DMODEL;

    int row0 = blockIdx.y * 64;
    int tid = threadIdx.x;
    int lane = tid & 31, warp = tid >> 5;
    int wm = warp >> 2, wn = warp & 3;
    int g = lane >> 2, tg = lane & 3;

    for (int idx = tid; idx < 64 * NTOK; idx += 256) {
        int r = idx / NTOK, c = idx % NTOK;
        int gr = row0 + r;
        satt[r * SATT_PITCH + c] = (gr < NTOK) ? Ab[(long)gr * NTOK + c] : 0.f;
    }
    __syncthreads();

    {
        int r = tid >> 2, part = tid & 3;
        float* rowp = satt + r * SATT_PITCH;
        float mx = -3.4e38f;
        for (int c = part; c < NTOK; c += 4) mx = fmaxf(mx, rowp[c]);
        mx = fmaxf(mx, __shfl_xor_sync(0xffffffffu, mx, 1));
        mx = fmaxf(mx, __shfl_xor_sync(0xffffffffu, mx, 2));
        float sum = 0.f;
        for (int c = part; c < NTOK; c += 4) {
            float e = expf(rowp[c] - mx);
            rowp[c] = e;
            sum += e;
        }
        sum += __shfl_xor_sync(0xffffffffu, sum, 1);
        sum += __shfl_xor_sync(0xffffffffu, sum, 2);
        float inv = 1.f / sum;
        for (int c = part; c < NTOK; c += 4) rowp[c] *= inv;
    }
    __syncthreads();

    int ar = tid >> 3, ak = (tid & 7) * 4;
    int bkNN = tid >> 5, bnNN = (tid & 31) * 4;
    const int K = NTOK, Nc = DMODEL;

    float4 pa[2], pb[4];

    auto loadA = [&](int k0) {
        #pragma unroll
        for (int p = 0; p < 2; p++) {
            int r = ar + p * 32, gk = k0 + ak;
            float4 v = make_float4(0.f, 0.f, 0.f, 0.f);
            if (gk + 3 < K) {
                v = *(const float4*)&satt[r * SATT_PITCH + gk];
            } else {
                if (gk + 0 < K) v.x = satt[r * SATT_PITCH + gk + 0];
                if (gk + 1 < K) v.y = satt[r * SATT_PITCH + gk + 1];
                if (gk + 2 < K) v.z = satt[r * SATT_PITCH + gk + 2];
                if (gk + 3 < K) v.w = satt[r * SATT_PITCH + gk + 3];
            }
            pa[p] = v;
        }
    };
    auto loadB = [&](int k0) {
        #pragma unroll
        for (int p = 0; p < 4; p++) {
            int gk = k0 + bkNN + p * 8, gn = bnNN;
            float4 v = make_float4(0.f, 0.f, 0.f, 0.f);
            if (gk < K && gn + 3 < Nc)
                v = *(const float4*)&Bb[(long)gk * 384 + gn];
            pb[p] = v;
        }
    };
    auto storeTiles = [&](int st) {
        char* sb = smem_c + st * STAGE_B;
        #pragma unroll
        for (int p = 0; p < 2; p++) {
            int r = ar + p * 32;
            float vv[4] = {pa[p].x, pa[p].y, pa[p].z, pa[p].w};
            unsigned short h[4], l[4];
            #pragma unroll
            for (int j = 0; j < 4; j++) split_bf16(vv[j], h[j], l[j]);
            *(uint2*)(sb + r * A_PITCH_B + ak * 2) =
                make_uint2(((unsigned)h[1] << 16) | h[0], ((unsigned)h[3] << 16) | h[2]);
            *(uint2*)(sb + AL_OFF + r * A_PITCH_B + ak * 2) =
                make_uint2(((unsigned)l[1] << 16) | l[0], ((unsigned)l[3] << 16) | l[2]);
        }
        #pragma unroll
        for (int p = 0; p < 4; p++) {
            int k = bkNN + p * 8;
            float vv[4] = {pb[p].x, pb[p].y, pb[p].z, pb[p].w};
            unsigned short h[4], l[4];
            #pragma unroll
            for (int j = 0; j < 4; j++) split_bf16(vv[j], h[j], l[j]);
            *(uint2*)(sb + BH_OFF + k * BNN_PITCH_B + bnNN * 2) =
                make_uint2(((unsigned)h[1] << 16) | h[0], ((unsigned)h[3] << 16) | h[2]);
            *(uint2*)(sb + BL_OFF + k * BNN_PITCH_B + bnNN * 2) =
                make_uint2(((unsigned)l[1] << 16) | l[0], ((unsigned)l[3] << 16) | l[2]);
        }
    };

    float acc[2][4][4];
    #pragma unroll
    for (int im = 0; im < 2; im++)
        #pragma unroll
        for (int jn = 0; jn < 4; jn++)
            #pragma unroll
            for (int c = 0; c < 4; c++) acc[im][jn][c] = 0.f;

    int nch = (K + 31) / 32;
    int stage = 0;

    loadA(0); loadB(0);
    storeTiles(0);
    __syncthreads();

    for (int c = 0; c < nch; c++) {
        if (c + 1 < nch) { loadA((c + 1) * 32); loadB((c + 1) * 32); }

        unsigned stb = sbase + stage * STAGE_B;
        #pragma unroll
        for (int ks2 = 0; ks2 < 2; ks2++) {
            int ksb = ks2 * 32;
            unsigned ah[2][4], al_[2][4];
            #pragma unroll
            for (int im = 0; im < 2; im++) {
                unsigned aaddr = stb
                    + (unsigned)((wm * 32 + im * 16 + (lane & 15)) * A_PITCH_B
                                 + ((lane >> 4) * 16) + ksb);
                LDSM4(ah[im][0], ah[im][1], ah[im][2], ah[im][3], aaddr);
                LDSM4(al_[im][0], al_[im][1], al_[im][2], al_[im][3], aaddr + AL_OFF);
            }
            unsigned bh[4][2], bl_[4][2];
            #pragma unroll
            for (int pr = 0; pr < 2; pr++) {
                int nb2 = wn * 32 + pr * 16;
                unsigned baddr = stb + BH_OFF
                    + (unsigned)((ks2 * 16 + ((lane >> 3) & 1) * 8 + (lane & 7)) * BNN_PITCH_B
                                 + (nb2 + (lane >> 4) * 8) * 2);
                unsigned r0, r1, r2, r3;
                LDSM4T(r0, r1, r2, r3, baddr);
                bh[2*pr][0] = r0; bh[2*pr][1] = r1; bh[2*pr+1][0] = r2; bh[2*pr+1][1] = r3;
                LDSM4T(r0, r1, r2, r3, baddr + (BL_OFF - BH_OFF));
                bl_[2*pr][0] = r0; bl_[2*pr][1] = r1; bl_[2*pr+1][0] = r2; bl_[2*pr+1][1] = r3;
            }
            #pragma unroll
            for (int im = 0; im < 2; im++)
                #pragma unroll
                for (int jn = 0; jn < 4; jn++) {
                    MMA_BF16(acc[im][jn], ah[im], bl_[jn]);
                    MMA_BF16(acc[im][jn], al_[im], bh[jn]);
                    MMA_BF16(acc[im][jn], ah[im], bh[jn]);
                }
        }

        if (c + 1 < nch) {
            storeTiles(stage ^ 1);
            __syncthreads();
            stage ^= 1;
        }
    }

    #pragma unroll
    for (int im = 0; im < 2; im++) {
        #pragma unroll
        for (int jn = 0; jn < 4; jn++) {
            int r0 = row0 + wm * 32 + im * 16 + g;
            int c0 = wn * 32 + jn * 8 + 2 * tg;
            #pragma unroll
            for (int half = 0; half < 2; half++) {
                int gr = r0 + half * 8;
                if (gr >= NTOK) continue;
                #pragma unroll
                for (int cc = 0; cc < 2; cc++) {
                    int gn = c0 + cc;
                    Cb[(long)gr * DMODEL + gn] = acc[im][jn][half * 2 + cc];
                }
            }
        }
    }
}

// ---------------- split-K reduce + LN stats ----------------
__global__ void reduce_stats_k(const float* __restrict__ part, long sstride, int ns,
                               const float* __restrict__ bias, const float* __restrict__ res,
                               float* __restrict__ out,
                               float* __restrict__ mu, float* __restrict__ rstd)
{
    long row = blockIdx.x;
    int d = threadIdx.x;
    long idx = row * DMODEL + d;
    float s = 0.f;
    for (int k = 0; k < ns; k++) s += part[(long)k * sstride + idx];
    s += bias[d];
    if (res) s += res[idx];
    out[idx] = s;
    __shared__ float r1[4], r2[4];
    float v1 = s, v2 = s * s;
    #pragma unroll
    for (int o = 16; o > 0; o >>= 1) {
        v1 += __shfl_xor_sync(0xffffffffu, v1, o);
        v2 += __shfl_xor_sync(0xffffffffu, v2, o);
    }
    if ((d & 31) == 0) { r1[d >> 5] = v1; r2[d >> 5] = v2; }
    __syncthreads();
    if (d == 0) {
        float t1 = r1[0] + r1[1] + r1[2] + r1[3];
        float t2 = r2[0] + r2[1] + r2[2] + r2[3];
        float m = t1 * (1.f / 128.f);
        float var = t2 * (1.f / 128.f) - m * m;
        mu[row] = m;
        rstd[row] = rsqrtf(var + LNEPS);
    }
}

// ---------------- final LN + mean pool fused ----------------
__global__ void feats_k(const float* __restrict__ h, const float* __restrict__ mu,
                        const float* __restrict__ rstd,
                        const float* __restrict__ g, const float* __restrict__ b,
                        float* __restrict__ feats)
{
    int bb = blockIdx.x, d = threadIdx.x;
    float gd = g[d], bd = b[d];
    float s = 0.f;
    for (int n = 0; n < NTOK; n++) {
        long row = (long)bb * NTOK + n;
        s += (h[row * DMODEL + d] - mu[row]) * rstd[row] * gd + bd;
    }
    feats[bb * DMODEL + d] = s * (1.f / 196.f);
}

// ---------------- top-32: register-resident incremental argmax (fp16 src) ----
__global__ void __launch_bounds__(256) topk_k(const __half* __restrict__ msim,
                       float* __restrict__ mvals, int* __restrict__ midx)
{
    long row = blockIdx.x;
    int tid = threadIdx.x;
    int lane = tid & 31, wid = tid >> 5;
    const __half* src = msim + row * MKEYS;

    float v[32];
    const uint4* s4 = (const uint4*)(src + tid * 32);   // 8 halfs per uint4
    #pragma unroll
    for (int i = 0; i < 4; i++) {
        uint4 t = s4[i];
        unsigned w[4] = {t.x, t.y, t.z, t.w};
        #pragma unroll
        for (int j = 0; j < 4; j++) {
            __half2 h2 = *(__half2*)&w[j];
            float2 f2 = __half22float2(h2);
            v[i*8 + j*2 + 0] = f2.x;
            v[i*8 + j*2 + 1] = f2.y;
        }
    }

    unsigned long long p = 0ull;
    #pragma unroll
    for (int i = 0; i < 32; i++) {
        unsigned u = __float_as_uint(v[i]);
        u = (u & 0x80000000u) ? ~u : (u | 0x80000000u);
        unsigned long long key = ((unsigned long long)u << 32) | (unsigned)(MKEYS - 1 - (tid * 32 + i));
        if (key > p) p = key;
    }

    __shared__ unsigned long long wmax[2][8];

    for (int it = 0; it < TOPK; it++) {
        unsigned long long q = p;
        #pragma unroll
        for (int o = 16; o > 0; o >>= 1) {
            unsigned long long other = __shfl_xor_sync(0xffffffffu, q, o);
            if (other > q) q = other;
        }
        if (lane == 0) wmax[it & 1][wid] = q;
        __syncthreads();
        unsigned long long best = wmax[it & 1][0];
        #pragma unroll
        for (int w = 1; w < 8; w++) {
            unsigned long long o2 = wmax[it & 1][w];
            if (o2 > best) best = o2;
        }
        int gidx = MKEYS - 1 - (int)(best & 0xffffffffu);
        if (tid == (gidx >> 5)) {
            int sub = gidx & 31;
            float bv = 0.f;
            #pragma unroll
            for (int i = 0; i < 32; i++)
                if (i == sub) { bv = v[i]; v[i] = -3.4e38f; }
            mvals[row * TOPK + it] = bv;
            midx [row * TOPK + it] = gidx;
            unsigned long long np = 0ull;
            #pragma unroll
            for (int i = 0; i < 32; i++) {
                unsigned u = __float_as_uint(v[i]);
                u = (u & 0x80000000u) ? ~u : (u | 0x80000000u);
                unsigned long long key = ((unsigned long long)u << 32) | (unsigned)(MKEYS - 1 - (tid * 32 + i));
                if (key > np) np = key;
            }
            p = np;
        }
    }
}

// ---------------- kNN combine ----------------
__global__ void knn_combine_k(const float* __restrict__ att,
                              const float* __restrict__ mvals, const int* __restrict__ midx,
                              const float* __restrict__ qkv, const float* __restrict__ knn_v,
                              float* __restrict__ out)
{
    long row = blockIdx.x;
    int b = (int)(row / NTOK);
    int tid = threadIdx.x;
    __shared__ float w[TOPK + NTOK];
    __shared__ int   sidx[TOPK];
    __shared__ float red[4];

    if (tid < TOPK) {
        w[tid]    = mvals[row * TOPK + tid];
        sidx[tid] = midx [row * TOPK + tid];
    }
    for (int m = tid; m < NTOK; m += 128) w[TOPK + m] = att[row * NTOK + m];
    __syncthreads();

    float l0 = w[tid];
    float l1 = (tid < (TOPK + NTOK - 128)) ? w[tid + 128] : -3.4e38f;
    float m = fmaxf(l0, l1);
    #pragma unroll
    for (int o = 16; o > 0; o >>= 1) m = fmaxf(m, __shfl_xor_sync(0xffffffffu, m, o));
    if ((tid & 31) == 0) red[tid >> 5] = m;
    __syncthreads();
    m = fmaxf(fmaxf(red[0], red[1]), fmaxf(red[2], red[3]));
    float e0 = expf(l0 - m);
    float e1 = (tid < (TOPK + NTOK - 128)) ? expf(l1 - m) : 0.f;
    float s = e0 + e1;
    __syncthreads();
    #pragma unroll
    for (int o = 16; o > 0; o >>= 1) s += __shfl_xor_sync(0xffffffffu, s, o);
    if ((tid & 31) == 0) red[tid >> 5] = s;
    __syncthreads();
    s = red[0] + red[1] + red[2] + red[3];
    float inv = 1.f / s;
    w[tid] = e0 * inv;
    if (tid < (TOPK + NTOK - 128)) w[tid + 128] = e1 * inv;
    __syncthreads();

    float acc = 0.f;
    const float* kv = knn_v + (long)b * MKEYS * DMODEL;
    #pragma unroll 4
    for (int j = 0; j < TOPK; j++)
        acc += w[j] * kv[(long)sidx[j] * DMODEL + tid];
    const float* vbase = qkv + ((long)b * NTOK) * 384 + 256;
    for (int mm = 0; mm < NTOK; mm++)
        acc += w[TOPK + mm] * vbase[(long)mm * 384 + tid];
    out[row * DMODEL + tid] = acc;
}

// ---------------- launch ----------------
extern "C" void kernel_launch(void* const* d_in, const int* in_sizes, int n_in,
                              void* d_out, int out_size)
{
    const float* x       = (const float*)d_in[0];
    const float* patch_w = (const float*)d_in[1];
    const float* patch_b = (const float*)d_in[2];
    const float* ln1_g   = (const float*)d_in[3];
    const float* ln1_b   = (const float*)d_in[4];
    const float* qkv_w   = (const float*)d_in[5];
    const float* qkv_b   = (const float*)d_in[6];
    const float* out_w   = (const float*)d_in[7];
    const float* out_b   = (const float*)d_in[8];
    const float* ln2_g   = (const float*)d_in[9];
    const float* ln2_b   = (const float*)d_in[10];
    const float* ff1_w   = (const float*)d_in[11];
    const float* ff1_b   = (const float*)d_in[12];
    const float* ff2_w   = (const float*)d_in[13];
    const float* ff2_b   = (const float*)d_in[14];
    const float* lnf_g   = (const float*)d_in[15];
    const float* lnf_b   = (const float*)d_in[16];
    const float* knn_k   = (const float*)d_in[17];
    const float* knn_v   = (const float*)d_in[18];
    const float* head_w  = (const float*)d_in[19];
    const float* head_b  = (const float*)d_in[20];
    float* out = (float*)d_out;

    void* tp;
    cudaGetSymbolAddress(&tp, g_h);    float*  pH    = (float*)tp;
    cudaGetSymbolAddress(&tp, g_qkv);  float*  pQKV  = (float*)tp;
    cudaGetSymbolAddress(&tp, g_att);  float*  pATT  = (float*)tp;
    cudaGetSymbolAddress(&tp, g_msim); __half* pMSIM = (__half*)tp;
    cudaGetSymbolAddress(&tp, g_o);    float*  pO    = (float*)tp;
    cudaGetSymbolAddress(&tp, g_ff);   float*  pFF   = (float*)tp;
    cudaGetSymbolAddress(&tp, g_part); float*  pPart = (float*)tp;
    cudaGetSymbolAddress(&tp, g_mv);   float*  pMV   = (float*)tp;
    cudaGetSymbolAddress(&tp, g_mi);   int*    pMI   = (int*)tp;
    cudaGetSymbolAddress(&tp, g_feats);float*  pFeat = (float*)tp;
    cudaGetSymbolAddress(&tp, g_mu);   float*  pMu   = (float*)tp;
    cudaGetSymbolAddress(&tp, g_rs);   float*  pRs   = (float*)tp;

    cudaFuncSetAttribute(mmabf_k<false,false,false,false>, cudaFuncAttributeMaxDynamicSharedMemorySize, SMEM2);
    cudaFuncSetAttribute(mmabf_k<true, false,false,false>, cudaFuncAttributeMaxDynamicSharedMemorySize, SMEM2);
    cudaFuncSetAttribute(mmabf_k<false,false,true ,false>, cudaFuncAttributeMaxDynamicSharedMemorySize, SMEM2);
    cudaFuncSetAttribute(mmabf_k<false,true ,true ,false>, cudaFuncAttributeMaxDynamicSharedMemorySize, SMEM2);
    cudaFuncSetAttribute(mmabf_k<false,false,false,true >, cudaFuncAttributeMaxDynamicSharedMemorySize, SMEM2);
    cudaFuncSetAttribute(mmabf_k<false,false,false,false,true>, cudaFuncAttributeMaxDynamicSharedMemorySize, SMEM2);
    cudaFuncSetAttribute(mmasav_k, cudaFuncAttributeMaxDynamicSharedMemorySize, SMEM_AV);
    cudaFuncSetAttribute(msim2_k, cudaFuncAttributeMaxDynamicSharedMemorySize, M2_SMEM);

    const long sPart = (long)ROWS * DMODEL;

    // patch embed: fused gather (PATCHA) + split-K 6 -> reduce + ln1 stats
    mmabf_k<false,false,false,false,true><<<dim3(1, 98, 6), 256, SMEM2>>>(x, patch_w, nullptr, nullptr, pPart,
        ROWS, DMODEL, PDIM, 0, PDIM, 0, DMODEL, 0, DMODEL, 1.f, 1, 6, sPart,
        nullptr, nullptr, nullptr, nullptr, nullptr, nullptr);
    reduce_stats_k<<<ROWS, 128>>>(pPart, sPart, 6, patch_b, nullptr, pH, pMu, pRs);

    for (int i = 0; i < DEPTH; i++) {
        // qkv with inline ln1
        mmabf_k<false,false,true,false><<<dim3(3, 98, 1), 256, SMEM2>>>(pH, qkv_w + (long)i * DMODEL * 3 * DMODEL,
            qkv_b + i * 3 * DMODEL, nullptr, pQKV,
            ROWS, 3 * DMODEL, DMODEL, 0, DMODEL, 0, 3 * DMODEL, 0, 3 * DMODEL, 1.f, 1, 1, 0,
            pMu, pRs, ln1_g + i * DMODEL, ln1_b + i * DMODEL, nullptr, nullptr);
        // sim = q @ k^T * scale
        mmabf_k<true,false,false,false><<<dim3(2, 4, BATCH), 256, SMEM2>>>(pQKV, pQKV + 128, nullptr, nullptr, pATT,
            NTOK, NTOK, DMODEL,
            (long)NTOK * 384, 384, (long)NTOK * 384, 384, (long)NTOK * NTOK, NTOK, SCALE, BATCH, 1, 0,
            nullptr, nullptr, nullptr, nullptr, nullptr, nullptr);

        if (i == KNN_LAYER) {
            // msim (persistent-B, fp16 output)
            msim2_k<<<dim3(MKEYS / 128, 1, BATCH), 256, M2_SMEM>>>(pQKV, knn_k, pMSIM);
            topk_k<<<ROWS, 256>>>(pMSIM, pMV, pMI);
            knn_combine_k<<<ROWS, 128>>>(pATT, pMV, pMI, pQKV, knn_v, pO);
        } else {
            // fused softmax + av
            mmasav_k<<<dim3(1, 4, BATCH), 256, SMEM_AV>>>(pATT, pQKV + 256, pO, BATCH);
        }

        // h = h + o @ out_w + out_b ; epilogue emits ln2 stats
        mmabf_k<false,false,false,true><<<dim3(1, 98, 1), 256, SMEM2>>>(pO, out_w + (long)i * DMODEL * DMODEL,
            out_b + i * DMODEL, pH, pH,
            ROWS, DMODEL, DMODEL, 0, DMODEL, 0, DMODEL, 0, DMODEL, 1.f, 1, 1, 0,
            nullptr, nullptr, nullptr, nullptr, pMu, pRs);

        // ff1 + gelu with inline ln2
        mmabf_k<false,true,true,false><<<dim3(4, 98, 1), 256, SMEM2>>>(pH, ff1_w + (long)i * DMODEL * FFH,
            ff1_b + i * FFH, nullptr, pFF,
            ROWS, FFH, DMODEL, 0, DMODEL, 0, FFH, 0, FFH, 1.f, 1, 1, 0,
            pMu, pRs, ln2_g + i * DMODEL, ln2_b + i * DMODEL, nullptr, nullptr);
        // ff2: split-K 4, reduce adds bias + residual h, emits next ln1 stats
        mmabf_k<false,false,false,false><<<dim3(1, 98, 4), 256, SMEM2>>>(pFF, ff2_w + (long)i * FFH * DMODEL,
            nullptr, nullptr, pPart,
            ROWS, DMODEL, FFH, 0, FFH, 0, DMODEL, 0, DMODEL, 1.f, 1, 4, sPart,
            nullptr, nullptr, nullptr, nullptr, nullptr, nullptr);
        reduce_stats_k<<<ROWS, 128>>>(pPart, sPart, 4, ff2_b + i * DMODEL, pH, pH, pMu, pRs);
    }

    // final LN + mean pool, then head
    feats_k<<<BATCH, 128>>>(pH, pMu, pRs, lnf_g, lnf_b, pFeat);
    mmabf_k<false,false,false,false><<<dim3(8, 1, 1), 256, SMEM2>>>(pFeat, head_w, head_b, nullptr, out,
        BATCH, NCLS, DMODEL, 0, DMODEL, 0, NCLS, 0, NCLS, 1.f, 1, 1, 0,
        nullptr, nullptr, nullptr, nullptr, nullptr, nullptr);
}

// round 17
// speedup vs baseline: 1.1484x; 1.0417x over previous
#include <cuda_runtime.h>
#include <cuda_bf16.h>
#include <cuda_fp16.h>
#include <math.h>

// ---------------- problem constants ----------------
#define BATCH   32
#define NTOK    196
#define DMODEL  128
#define ROWS    (BATCH*NTOK) // 6272
#define PDIM    768
#define DEPTH   7
#define KNN_LAYER 6
#define MKEYS   8192
#define TOPK    32
#define FFH     512
#define NCLS    1000
#define SCALE   0.08838834764831845f
#define LNEPS   1e-5f

// ---------------- device scratch ----------------
__device__ float g_h   [ (long)ROWS*DMODEL ];
__device__ float g_qkv [ (long)ROWS*3*DMODEL ];
__device__ float g_att [ (long)BATCH*NTOK*NTOK ];
__device__ __half g_msim[ (long)BATCH*NTOK*MKEYS ];
__device__ float g_o   [ (long)ROWS*DMODEL ];
__device__ float g_ff  [ (long)ROWS*FFH ];
__device__ float g_part[ (long)6*ROWS*DMODEL ];
__device__ float g_mv  [ (long)ROWS*TOPK ];
__device__ int   g_mi  [ (long)ROWS*TOPK ];
__device__ float g_feats[ BATCH*DMODEL ];
__device__ float g_mu  [ ROWS ];
__device__ float g_rs  [ ROWS ];

// ---------------- helpers ----------------
__device__ __forceinline__ float gelu_tanh(float v) {
    const float c = 0.7978845608028654f;
    float t = tanhf(c * (v + 0.044715f * v * v * v));
    return 0.5f * v * (1.f + t);
}
__device__ __forceinline__ void split_bf16(float v, unsigned short& h, unsigned short& l) {
    __nv_bfloat16 hb = __float2bfloat16_rn(v);
    h = __bfloat16_as_ushort(hb);
    l = __bfloat16_as_ushort(__float2bfloat16_rn(v - __bfloat162float(hb)));
}
#define MMA_BF16(ACC, A, B)                                                 \
    asm volatile(                                                           \
        "mma.sync.aligned.m16n8k16.row.col.f32.bf16.bf16.f32 "              \
        "{%0,%1,%2,%3}, {%4,%5,%6,%7}, {%8,%9}, {%0,%1,%2,%3};"             \
        : "+f"((ACC)[0]), "+f"((ACC)[1]), "+f"((ACC)[2]), "+f"((ACC)[3])    \
        : "r"((A)[0]), "r"((A)[1]), "r"((A)[2]), "r"((A)[3]),               \
          "r"((B)[0]), "r"((B)[1]))
#define LDSM4(R0,R1,R2,R3, ADDR)                                            \
    asm volatile("ldmatrix.sync.aligned.m8n8.x4.shared.b16 {%0,%1,%2,%3}, [%4];" \
        : "=r"(R0), "=r"(R1), "=r"(R2), "=r"(R3) : "r"(ADDR))
#define LDSM4T(R0,R1,R2,R3, ADDR)                                           \
    asm volatile("ldmatrix.sync.aligned.m8n8.x4.trans.shared.b16 {%0,%1,%2,%3}, [%4];" \
        : "=r"(R0), "=r"(R1), "=r"(R2), "=r"(R3) : "r"(ADDR))

// ---------------- bf16 split-2 mma GEMM (R9/R12 core) ----------------
#define A_PITCH_B 80
#define BTB_PITCH_B 80
#define BNN_PITCH_B 272
#define AL_OFF 5120
#define BH_OFF 10240
#define BL_OFF 20480
#define STAGE_B 30720
#define SMEM2 (2*STAGE_B)

template<bool TB, bool DOGELU, bool LNA, bool STATS, bool PATCHA = false>
__global__ void __launch_bounds__(256, 2)
mmabf_k(const float* __restrict__ A, const float* __restrict__ Bm,
        const float* __restrict__ bias, const float* __restrict__ Res,
        float* __restrict__ C,
        int Mr, int Nc, int K,
        long sAb, int lda, long sBb, int ldb, long sCb, int ldc,
        float alpha, int nbatch, int kslices, long sPart,
        const float* __restrict__ muA, const float* __restrict__ rsA,
        const float* __restrict__ lngA, const float* __restrict__ lnbA,
        float* __restrict__ muO, float* __restrict__ rsO)
{
    extern __shared__ char smem_c[];
    unsigned sbase = (unsigned)__cvta_generic_to_shared(smem_c);

    int bz = blockIdx.z;
    int batch = bz % nbatch;
    int ksl   = bz / nbatch;
    int Kslice = K / kslices;
    int Klo = ksl * Kslice;
    int Khi = (ksl == kslices - 1) ? K : Klo + Kslice;

    const float* Ab = A + (PATCHA ? 0 : (long)batch * sAb);
    const float* Bb = Bm + (long)batch * sBb;
    float*       Cb;
    const float* Rb;
    if (kslices > 1) {
        Cb = C + (long)ksl * sPart + (long)batch * sCb;
        Rb = nullptr;
    } else {
        Cb = C + (long)batch * sCb;
        Rb = Res ? (Res + (long)batch * sCb) : nullptr;
    }

    int row0 = blockIdx.y * 64;
    int col0 = blockIdx.x * 128;
    int tid = threadIdx.x;
    int lane = tid & 31, warp = tid >> 5;
    int wm = warp >> 2, wn = warp & 3;
    int g = lane >> 2, tg = lane & 3;

    int ar = tid >> 3, ak = (tid & 7) * 4;
    int bkNN = tid >> 5, bnNN = (tid & 31) * 4;
    int bnTB = tid >> 3, bkTB = (tid & 7) * 4;

    float4 pa[2], pb[4];

    auto loadA = [&](int k0) {
        #pragma unroll
        for (int p = 0; p < 2; p++) {
            int gr = row0 + ar + p * 32, gk = k0 + ak;
            float4 v = make_float4(0.f, 0.f, 0.f, 0.f);
            if (PATCHA) {
                if (gr < Mr) {
                    int b  = gr / NTOK, n = gr % NTOK;
                    int i  = n / 14,    j = n % 14;
                    int ch = gk >> 8;
                    int r  = gk & 255;
                    int pi = r >> 4, pj = r & 15;
                    const float* xs = Ab + (((long)b * 3 + ch) * 224 + (i * 16 + pi)) * 224
                                         + (j * 16 + pj);
                    v = *(const float4*)xs;
                }
            } else if (gr < Mr) {
                if (gk + 3 < Khi) {
                    v = *(const float4*)&Ab[(long)gr * lda + gk];
                    if (LNA) {
                        float mu = __ldg(&muA[gr]);
                        float rs = __ldg(&rsA[gr]);
                        float4 gg = *(const float4*)&lngA[gk];
                        float4 bb = *(const float4*)&lnbA[gk];
                        v.x = (v.x - mu) * rs * gg.x + bb.x;
                        v.y = (v.y - mu) * rs * gg.y + bb.y;
                        v.z = (v.z - mu) * rs * gg.z + bb.z;
                        v.w = (v.w - mu) * rs * gg.w + bb.w;
                    }
                } else {
                    if (gk + 0 < Khi) v.x = Ab[(long)gr * lda + gk + 0];
                    if (gk + 1 < Khi) v.y = Ab[(long)gr * lda + gk + 1];
                    if (gk + 2 < Khi) v.z = Ab[(long)gr * lda + gk + 2];
                    if (gk + 3 < Khi) v.w = Ab[(long)gr * lda + gk + 3];
                }
            }
            pa[p] = v;
        }
    };
    auto loadB = [&](int k0) {
        if (TB) {
            #pragma unroll
            for (int p = 0; p < 4; p++) {
                int gn = col0 + bnTB + p * 32, gk = k0 + bkTB;
                float4 v = make_float4(0.f, 0.f, 0.f, 0.f);
                if (gn < Nc) {
                    if (gk + 3 < Khi) v = *(const float4*)&Bb[(long)gn * ldb + gk];
                    else {
                        if (gk + 0 < Khi) v.x = Bb[(long)gn * ldb + gk + 0];
                        if (gk + 1 < Khi) v.y = Bb[(long)gn * ldb + gk + 1];
                        if (gk + 2 < Khi) v.z = Bb[(long)gn * ldb + gk + 2];
                        if (gk + 3 < Khi) v.w = Bb[(long)gn * ldb + gk + 3];
                    }
                }
                pb[p] = v;
            }
        } else {
            #pragma unroll
            for (int p = 0; p < 4; p++) {
                int gk = k0 + bkNN + p * 8, gn = col0 + bnNN;
                float4 v = make_float4(0.f, 0.f, 0.f, 0.f);
                if (gk < Khi) {
                    if (gn + 3 < Nc) v = *(const float4*)&Bb[(long)gk * ldb + gn];
                    else {
                        if (gn + 0 < Nc) v.x = Bb[(long)gk * ldb + gn + 0];
                        if (gn + 1 < Nc) v.y = Bb[(long)gk * ldb + gn + 1];
                        if (gn + 2 < Nc) v.z = Bb[(long)gk * ldb + gn + 2];
                        if (gn + 3 < Nc) v.w = Bb[(long)gk * ldb + gn + 3];
                    }
                }
                pb[p] = v;
            }
        }
    };
    auto storeTiles = [&](int st) {
        char* sb = smem_c + st * STAGE_B;
        #pragma unroll
        for (int p = 0; p < 2; p++) {
            int r = ar + p * 32;
            float vv[4] = {pa[p].x, pa[p].y, pa[p].z, pa[p].w};
            unsigned short h[4], l[4];
            #pragma unroll
            for (int j = 0; j < 4; j++) split_bf16(vv[j], h[j], l[j]);
            *(uint2*)(sb + r * A_PITCH_B + ak * 2) =
                make_uint2(((unsigned)h[1] << 16) | h[0], ((unsigned)h[3] << 16) | h[2]);
            *(uint2*)(sb + AL_OFF + r * A_PITCH_B + ak * 2) =
                make_uint2(((unsigned)l[1] << 16) | l[0], ((unsigned)l[3] << 16) | l[2]);
        }
        if (TB) {
            #pragma unroll
            for (int p = 0; p < 4; p++) {
                int n = bnTB + p * 32;
                float vv[4] = {pb[p].x, pb[p].y, pb[p].z, pb[p].w};
                unsigned short h[4], l[4];
                #pragma unroll
                for (int j = 0; j < 4; j++) split_bf16(vv[j], h[j], l[j]);
                *(uint2*)(sb + BH_OFF + n * BTB_PITCH_B + bkTB * 2) =
                    make_uint2(((unsigned)h[1] << 16) | h[0], ((unsigned)h[3] << 16) | h[2]);
                *(uint2*)(sb + BL_OFF + n * BTB_PITCH_B + bkTB * 2) =
                    make_uint2(((unsigned)l[1] << 16) | l[0], ((unsigned)l[3] << 16) | l[2]);
            }
        } else {
            #pragma unroll
            for (int p = 0; p < 4; p++) {
                int k = bkNN + p * 8;
                float vv[4] = {pb[p].x, pb[p].y, pb[p].z, pb[p].w};
                unsigned short h[4], l[4];
                #pragma unroll
                for (int j = 0; j < 4; j++) split_bf16(vv[j], h[j], l[j]);
                *(uint2*)(sb + BH_OFF + k * BNN_PITCH_B + bnNN * 2) =
                    make_uint2(((unsigned)h[1] << 16) | h[0], ((unsigned)h[3] << 16) | h[2]);
                *(uint2*)(sb + BL_OFF + k * BNN_PITCH_B + bnNN * 2) =
                    make_uint2(((unsigned)l[1] << 16) | l[0], ((unsigned)l[3] << 16) | l[2]);
            }
        }
    };

    float acc[2][4][4];
    #pragma unroll
    for (int im = 0; im < 2; im++)
        #pragma unroll
        for (int jn = 0; jn < 4; jn++)
            #pragma unroll
            for (int c = 0; c < 4; c++) acc[im][jn][c] = 0.f;

    int nch = (Khi - Klo + 31) / 32;
    int stage = 0;

    loadA(Klo); loadB(Klo);
    storeTiles(0);
    __syncthreads();

    for (int c = 0; c < nch; c++) {
        if (c + 1 < nch) { loadA(Klo + (c + 1) * 32); loadB(Klo + (c + 1) * 32); }

        unsigned stb = sbase + stage * STAGE_B;
        #pragma unroll
        for (int ks2 = 0; ks2 < 2; ks2++) {
            int ksb = ks2 * 32;
            unsigned ah[2][4], al_[2][4];
            #pragma unroll
            for (int im = 0; im < 2; im++) {
                unsigned aaddr = stb
                    + (unsigned)((wm * 32 + im * 16 + (lane & 15)) * A_PITCH_B
                                 + ((lane >> 4) * 16) + ksb);
                LDSM4(ah[im][0], ah[im][1], ah[im][2], ah[im][3], aaddr);
                LDSM4(al_[im][0], al_[im][1], al_[im][2], al_[im][3], aaddr + AL_OFF);
            }
            unsigned bh[4][2], bl_[4][2];
            #pragma unroll
            for (int pr = 0; pr < 2; pr++) {
                int nb2 = wn * 32 + pr * 16;
                unsigned baddr;
                if (TB) {
                    baddr = stb + BH_OFF
                        + (unsigned)((nb2 + ((lane >> 4) << 3) + (lane & 7)) * BTB_PITCH_B
                                     + (((lane >> 3) & 1) * 16) + ksb);
                } else {
                    baddr = stb + BH_OFF
                        + (unsigned)((ks2 * 16 + ((lane >> 3) & 1) * 8 + (lane & 7)) * BNN_PITCH_B
                                     + (nb2 + (lane >> 4) * 8) * 2);
                }
                unsigned r0, r1, r2, r3;
                if (TB) { LDSM4(r0, r1, r2, r3, baddr); }
                else    { LDSM4T(r0, r1, r2, r3, baddr); }
                bh[2*pr][0] = r0; bh[2*pr][1] = r1; bh[2*pr+1][0] = r2; bh[2*pr+1][1] = r3;
                unsigned laddr = baddr + (BL_OFF - BH_OFF);
                if (TB) { LDSM4(r0, r1, r2, r3, laddr); }
                else    { LDSM4T(r0, r1, r2, r3, laddr); }
                bl_[2*pr][0] = r0; bl_[2*pr][1] = r1; bl_[2*pr+1][0] = r2; bl_[2*pr+1][1] = r3;
            }
            #pragma unroll
            for (int im = 0; im < 2; im++)
                #pragma unroll
                for (int jn = 0; jn < 4; jn++) {
                    MMA_BF16(acc[im][jn], ah[im], bl_[jn]);
                    MMA_BF16(acc[im][jn], al_[im], bh[jn]);
                    MMA_BF16(acc[im][jn], ah[im], bh[jn]);
                }
        }

        if (c + 1 < nch) {
            storeTiles(stage ^ 1);
            __syncthreads();
            stage ^= 1;
        }
    }

    // ---- epilogue
    float st1[2][2], st2[2][2];
    if (STATS) {
        #pragma unroll
        for (int im = 0; im < 2; im++)
            #pragma unroll
            for (int hh = 0; hh < 2; hh++) { st1[im][hh] = 0.f; st2[im][hh] = 0.f; }
    }
    #pragma unroll
    for (int im = 0; im < 2; im++) {
        #pragma unroll
        for (int jn = 0; jn < 4; jn++) {
            int r0 = row0 + wm * 32 + im * 16 + g;
            int c0 = col0 + wn * 32 + jn * 8 + 2 * tg;
            #pragma unroll
            for (int half = 0; half < 2; half++) {
                int gr = r0 + half * 8;
                if (gr >= Mr) continue;
                #pragma unroll
                for (int cc = 0; cc < 2; cc++) {
                    int gn = c0 + cc;
                    if (gn >= Nc) continue;
                    float v = acc[im][jn][half * 2 + cc] * alpha;
                    if (kslices == 1) {
                        if (bias) v += bias[gn];
                        if (Rb)   v += Rb[(long)gr * ldc + gn];
                        if (DOGELU) v = gelu_tanh(v);
                    }
                    if (STATS) { st1[im][half] += v; st2[im][half] += v * v; }
                    Cb[(long)gr * ldc + gn] = v;
                }
            }
        }
    }
    if (STATS) {
        __syncthreads();
        float* s1 = (float*)smem_c;
        float* s2 = s1 + 256;
        #pragma unroll
        for (int im = 0; im < 2; im++)
            #pragma unroll
            for (int hh = 0; hh < 2; hh++) {
                float x1 = st1[im][hh], x2 = st2[im][hh];
                x1 += __shfl_xor_sync(0xffffffffu, x1, 1);
                x1 += __shfl_xor_sync(0xffffffffu, x1, 2);
                x2 += __shfl_xor_sync(0xffffffffu, x2, 1);
                x2 += __shfl_xor_sync(0xffffffffu, x2, 2);
                if (tg == 0) {
                    int lr = wm * 32 + im * 16 + g + hh * 8;
                    s1[wn * 64 + lr] = x1;
                    s2[wn * 64 + lr] = x2;
                }
            }
        __syncthreads();
        if (tid < 64) {
            float t1 = s1[tid] + s1[64 + tid] + s1[128 + tid] + s1[192 + tid];
            float t2 = s2[tid] + s2[64 + tid] + s2[128 + tid] + s2[192 + tid];
            float mu = t1 * (1.f / 128.f);
            float var = t2 * (1.f / 128.f) - mu * mu;
            muO[row0 + tid] = mu;
            rsO[row0 + tid] = rsqrtf(var + LNEPS);
        }
    }
}

// ============================================================================
// msim2: persistent-B, fp16 output (R15/R16-verified). grid (64, 1, BATCH).
// ============================================================================
#define M2_ASTG 10240
#define M2_BH   20480
#define M2_BLD  34816
#define M2_BPITCH 272
#define M2_SMEM 90112

__global__ void __launch_bounds__(256, 2)
msim2_k(const float* __restrict__ qkv, const float* __restrict__ knnk,
        __half* __restrict__ msim)
{
    extern __shared__ char smem_c[];
    unsigned sbase = (unsigned)__cvta_generic_to_shared(smem_c);

    int batch = blockIdx.z;
    int col0 = blockIdx.x * 128;
    const float* Aq = qkv + (long)batch * NTOK * 384;
    const float* Bk = knnk + (long)batch * MKEYS * DMODEL;
    __half*      Cb = msim + (long)batch * NTOK * MKEYS;

    int tid = threadIdx.x;
    int lane = tid & 31, warp = tid >> 5;
    int wm = warp >> 2, wn = warp & 3;
    int g = lane >> 2, tg = lane & 3;

    int ar = tid >> 3, ak = (tid & 7) * 4;
    int bnTB = tid >> 3, bkTB = (tid & 7) * 4;

    #pragma unroll
    for (int kh = 0; kh < 4; kh++) {
        #pragma unroll
        for (int p = 0; p < 4; p++) {
            int n = bnTB + p * 32;
            int kg = kh * 32 + bkTB;
            float4 v = *(const float4*)&Bk[(long)(col0 + n) * DMODEL + kg];
            float vv[4] = {v.x, v.y, v.z, v.w};
            unsigned short h[4], l[4];
            #pragma unroll
            for (int j = 0; j < 4; j++) split_bf16(vv[j], h[j], l[j]);
            *(uint2*)(smem_c + M2_BH + n * M2_BPITCH + kg * 2) =
                make_uint2(((unsigned)h[1] << 16) | h[0], ((unsigned)h[3] << 16) | h[2]);
            *(uint2*)(smem_c + M2_BH + M2_BLD + n * M2_BPITCH + kg * 2) =
                make_uint2(((unsigned)l[1] << 16) | l[0], ((unsigned)l[3] << 16) | l[2]);
        }
    }

    float4 pa[2];
    auto loadA = [&](int row0, int k0) {
        #pragma unroll
        for (int p = 0; p < 2; p++) {
            int gr = row0 + ar + p * 32, gk = k0 + ak;
            float4 v = make_float4(0.f, 0.f, 0.f, 0.f);
            if (gr < NTOK) v = *(const float4*)&Aq[(long)gr * 384 + gk];
            pa[p] = v;
        }
    };
    auto storeA = [&](int st) {
        char* sb = smem_c + st * M2_ASTG;
        #pragma unroll
        for (int p = 0; p < 2; p++) {
            int r = ar + p * 32;
            float vv[4] = {pa[p].x, pa[p].y, pa[p].z, pa[p].w};
            unsigned short h[4], l[4];
            #pragma unroll
            for (int j = 0; j < 4; j++) split_bf16(vv[j], h[j], l[j]);
            *(uint2*)(sb + r * A_PITCH_B + ak * 2) =
                make_uint2(((unsigned)h[1] << 16) | h[0], ((unsigned)h[3] << 16) | h[2]);
            *(uint2*)(sb + AL_OFF + r * A_PITCH_B + ak * 2) =
                make_uint2(((unsigned)l[1] << 16) | l[0], ((unsigned)l[3] << 16) | l[2]);
        }
    };

    for (int y = 0; y < 4; y++) {
        int row0 = y * 64;

        float acc[2][4][4];
        #pragma unroll
        for (int im = 0; im < 2; im++)
            #pragma unroll
            for (int jn = 0; jn < 4; jn++)
                #pragma unroll
                for (int c = 0; c < 4; c++) acc[im][jn][c] = 0.f;

        loadA(row0, 0);
        __syncthreads();
        storeA(0);
        __syncthreads();

        int stage = 0;
        #pragma unroll
        for (int c = 0; c < 4; c++) {
            if (c + 1 < 4) loadA(row0, (c + 1) * 32);

            unsigned stb = sbase + stage * M2_ASTG;
            #pragma unroll
            for (int ks2 = 0; ks2 < 2; ks2++) {
                int ksb = ks2 * 32;
                int kbyte = c * 64 + ks2 * 32;
                unsigned ah[2][4], al_[2][4];
                #pragma unroll
                for (int im = 0; im < 2; im++) {
                    unsigned aaddr = stb
                        + (unsigned)((wm * 32 + im * 16 + (lane & 15)) * A_PITCH_B
                                     + ((lane >> 4) * 16) + ksb);
                    LDSM4(ah[im][0], ah[im][1], ah[im][2], ah[im][3], aaddr);
                    LDSM4(al_[im][0], al_[im][1], al_[im][2], al_[im][3], aaddr + AL_OFF);
                }
                unsigned bh[4][2], bl_[4][2];
                #pragma unroll
                for (int pr = 0; pr < 2; pr++) {
                    int nb2 = wn * 32 + pr * 16;
                    unsigned baddr = sbase + M2_BH
                        + (unsigned)((nb2 + ((lane >> 4) << 3) + (lane & 7)) * M2_BPITCH
                                     + (((lane >> 3) & 1) * 16) + kbyte);
                    unsigned r0, r1, r2, r3;
                    LDSM4(r0, r1, r2, r3, baddr);
                    bh[2*pr][0] = r0; bh[2*pr][1] = r1; bh[2*pr+1][0] = r2; bh[2*pr+1][1] = r3;
                    LDSM4(r0, r1, r2, r3, baddr + M2_BLD);
                    bl_[2*pr][0] = r0; bl_[2*pr][1] = r1; bl_[2*pr+1][0] = r2; bl_[2*pr+1][1] = r3;
                }
                #pragma unroll
                for (int im = 0; im < 2; im++)
                    #pragma unroll
                    for (int jn = 0; jn < 4; jn++) {
                        MMA_BF16(acc[im][jn], ah[im], bl_[jn]);
                        MMA_BF16(acc[im][jn], al_[im], bh[jn]);
                        MMA_BF16(acc[im][jn], ah[im], bh[jn]);
                    }
            }

            if (c + 1 < 4) {
                storeA(stage ^ 1);
                __syncthreads();
                stage ^= 1;
            }
        }

        #pragma unroll
        for (int im = 0; im < 2; im++) {
            #pragma unroll
            for (int jn = 0; jn < 4; jn++) {
                int r0 = row0 + wm * 32 + im * 16 + g;
                int c0 = col0 + wn * 32 + jn * 8 + 2 * tg;
                #pragma unroll
                for (int half = 0; half < 2; half++) {
                    int gr = r0 + half * 8;
                    if (gr >= NTOK) continue;
                    __half2 hv = __floats2half2_rn(acc[im][jn][half * 2 + 0] * SCALE,
                                                   acc[im][jn][half * 2 + 1] * SCALE);
                    *(__half2*)&Cb[(long)gr * MKEYS + c0] = hv;
                }
            }
        }
    }
}

// ============================================================================
// Fused local attention: sim (QK^T) -> softmax -> av, one kernel.
// grid (1, 4, BATCH), 256 threads. Layers 0..5 (non-kNN).
// smem: [0, SMEM2) pipeline stages; satt @ SMEM2 (64 x 204 fp32).
// ============================================================================
#define SATT_PITCH 204
#define SMEM_AV (SMEM2 + 64*SATT_PITCH*4)

__global__ void __launch_bounds__(256)
attn_k(const float* __restrict__ qkv, float* __restrict__ C, int nbatch)
{
    extern __shared__ char smem_c[];
    unsigned sbase = (unsigned)__cvta_generic_to_shared(smem_c);
    float* satt = (float*)(smem_c + SMEM2);

    int batch = blockIdx.z % nbatch;
    const float* Qb = qkv + (long)batch * NTOK * 384;
    const float* Kb = Qb + 128;
    const float* Vb = Qb + 256;
    float*       Cb = C + (long)batch * NTOK * DMODEL;

    int row0 = blockIdx.y * 64;
    int tid = threadIdx.x;
    int lane = tid & 31, warp = tid >> 5;
    int wm = warp >> 2, wn = warp & 3;
    int g = lane >> 2, tg = lane & 3;

    int ar = tid >> 3, ak = (tid & 7) * 4;
    int bnTB = tid >> 3, bkTB = (tid & 7) * 4;
    int bkNN = tid >> 5, bnNN = (tid & 31) * 4;

    float4 pa[2], pb[4];

    // ================= Phase 1: logits = q @ k^T * SCALE (2 column passes)
    for (int pass = 0; pass < 2; pass++) {
        int col0 = pass * 128;

        auto loadAq = [&](int k0) {
            #pragma unroll
            for (int p = 0; p < 2; p++) {
                int gr = row0 + ar + p * 32, gk = k0 + ak;
                float4 v = make_float4(0.f, 0.f, 0.f, 0.f);
                if (gr < NTOK) v = *(const float4*)&Qb[(long)gr * 384 + gk];
                pa[p] = v;
            }
        };
        auto loadBk = [&](int k0) {
            #pragma unroll
            for (int p = 0; p < 4; p++) {
                int gn = col0 + bnTB + p * 32, gk = k0 + bkTB;
                float4 v = make_float4(0.f, 0.f, 0.f, 0.f);
                if (gn < NTOK) v = *(const float4*)&Kb[(long)gn * 384 + gk];
                pb[p] = v;
            }
        };
        auto storeQK = [&](int st) {
            char* sb = smem_c + st * STAGE_B;
            #pragma unroll
            for (int p = 0; p < 2; p++) {
                int r = ar + p * 32;
                float vv[4] = {pa[p].x, pa[p].y, pa[p].z, pa[p].w};
                unsigned short h[4], l[4];
                #pragma unroll
                for (int j = 0; j < 4; j++) split_bf16(vv[j], h[j], l[j]);
                *(uint2*)(sb + r * A_PITCH_B + ak * 2) =
                    make_uint2(((unsigned)h[1] << 16) | h[0], ((unsigned)h[3] << 16) | h[2]);
                *(uint2*)(sb + AL_OFF + r * A_PITCH_B + ak * 2) =
                    make_uint2(((unsigned)l[1] << 16) | l[0], ((unsigned)l[3] << 16) | l[2]);
            }
            #pragma unroll
            for (int p = 0; p < 4; p++) {
                int n = bnTB + p * 32;
                float vv[4] = {pb[p].x, pb[p].y, pb[p].z, pb[p].w};
                unsigned short h[4], l[4];
                #pragma unroll
                for (int j = 0; j < 4; j++) split_bf16(vv[j], h[j], l[j]);
                *(uint2*)(sb + BH_OFF + n * BTB_PITCH_B + bkTB * 2) =
                    make_uint2(((unsigned)h[1] << 16) | h[0], ((unsigned)h[3] << 16) | h[2]);
                *(uint2*)(sb + BL_OFF + n * BTB_PITCH_B + bkTB * 2) =
                    make_uint2(((unsigned)l[1] << 16) | l[0], ((unsigned)l[3] << 16) | l[2]);
            }
        };

        float acc[2][4][4];
        #pragma unroll
        for (int im = 0; im < 2; im++)
            #pragma unroll
            for (int jn = 0; jn < 4; jn++)
                #pragma unroll
                for (int c = 0; c < 4; c++) acc[im][jn][c] = 0.f;

        __syncthreads();    // stages free from previous pass
        loadAq(0); loadBk(0);
        storeQK(0);
        __syncthreads();

        int stage = 0;
        #pragma unroll
        for (int c = 0; c < 4; c++) {
            if (c + 1 < 4) { loadAq((c + 1) * 32); loadBk((c + 1) * 32); }

            unsigned stb = sbase + stage * STAGE_B;
            #pragma unroll
            for (int ks2 = 0; ks2 < 2; ks2++) {
                int ksb = ks2 * 32;
                unsigned ah[2][4], al_[2][4];
                #pragma unroll
                for (int im = 0; im < 2; im++) {
                    unsigned aaddr = stb
                        + (unsigned)((wm * 32 + im * 16 + (lane & 15)) * A_PITCH_B
                                     + ((lane >> 4) * 16) + ksb);
                    LDSM4(ah[im][0], ah[im][1], ah[im][2], ah[im][3], aaddr);
                    LDSM4(al_[im][0], al_[im][1], al_[im][2], al_[im][3], aaddr + AL_OFF);
                }
                unsigned bh[4][2], bl_[4][2];
                #pragma unroll
                for (int pr = 0; pr < 2; pr++) {
                    int nb2 = wn * 32 + pr * 16;
                    unsigned baddr = stb + BH_OFF
                        + (unsigned)((nb2 + ((lane >> 4) << 3) + (lane & 7)) * BTB_PITCH_B
                                     + (((lane >> 3) & 1) * 16) + ksb);
                    unsigned r0, r1, r2, r3;
                    LDSM4(r0, r1, r2, r3, baddr);
                    bh[2*pr][0] = r0; bh[2*pr][1] = r1; bh[2*pr+1][0] = r2; bh[2*pr+1][1] = r3;
                    LDSM4(r0, r1, r2, r3, baddr + (BL_OFF - BH_OFF));
                    bl_[2*pr][0] = r0; bl_[2*pr][1] = r1; bl_[2*pr+1][0] = r2; bl_[2*pr+1][1] = r3;
                }
                #pragma unroll
                for (int im = 0; im < 2; im++)
                    #pragma unroll
                    for (int jn = 0; jn < 4; jn++) {
                        MMA_BF16(acc[im][jn], ah[im], bl_[jn]);
                        MMA_BF16(acc[im][jn], al_[im], bh[jn]);
                        MMA_BF16(acc[im][jn], ah[im], bh[jn]);
                    }
            }

            if (c + 1 < 4) {
                storeQK(stage ^ 1);
                __syncthreads();
                stage ^= 1;
            }
        }

        // write logits into satt (local rows 0..63); OOB rows -> 0; cols >=196 skipped
        #pragma unroll
        for (int im = 0; im < 2; im++) {
            #pragma unroll
            for (int jn = 0; jn < 4; jn++) {
                int lr0 = wm * 32 + im * 16 + g;
                int c0 = col0 + wn * 32 + jn * 8 + 2 * tg;
                #pragma unroll
                for (int half = 0; half < 2; half++) {
                    int lr = lr0 + half * 8;
                    #pragma unroll
                    for (int cc = 0; cc < 2; cc++) {
                        int c = c0 + cc;
                        if (c >= NTOK) continue;
                        float v = (row0 + lr < NTOK) ? acc[im][jn][half * 2 + cc] * SCALE : 0.f;
                        satt[lr * SATT_PITCH + c] = v;
                    }
                }
            }
        }
    }
    __syncthreads();

    // ================= Phase 2: softmax (4 threads per row)
    {
        int r = tid >> 2, part = tid & 3;
        float* rowp = satt + r * SATT_PITCH;
        float mx = -3.4e38f;
        for (int c = part; c < NTOK; c += 4) mx = fmaxf(mx, rowp[c]);
        mx = fmaxf(mx, __shfl_xor_sync(0xffffffffu, mx, 1));
        mx = fmaxf(mx, __shfl_xor_sync(0xffffffffu, mx, 2));
        float sum = 0.f;
        for (int c = part; c < NTOK; c += 4) {
            float e = expf(rowp[c] - mx);
            rowp[c] = e;
            sum += e;
        }
        sum += __shfl_xor_sync(0xffffffffu, sum, 1);
        sum += __shfl_xor_sync(0xffffffffu, sum, 2);
        float inv = 1.f / sum;
        for (int c = part; c < NTOK; c += 4) rowp[c] *= inv;
    }
    __syncthreads();

    // ================= Phase 3: o = attn @ v  (K=196, NN)
    const int K = NTOK, Nc = DMODEL;

    auto loadAs = [&](int k0) {
        #pragma unroll
        for (int p = 0; p < 2; p++) {
            int r = ar + p * 32, gk = k0 + ak;
            float4 v = make_float4(0.f, 0.f, 0.f, 0.f);
            if (gk + 3 < K) {
                v = *(const float4*)&satt[r * SATT_PITCH + gk];
            } else {
                if (gk + 0 < K) v.x = satt[r * SATT_PITCH + gk + 0];
                if (gk + 1 < K) v.y = satt[r * SATT_PITCH + gk + 1];
                if (gk + 2 < K) v.z = satt[r * SATT_PITCH + gk + 2];
                if (gk + 3 < K) v.w = satt[r * SATT_PITCH + gk + 3];
            }
            pa[p] = v;
        }
    };
    auto loadBv = [&](int k0) {
        #pragma unroll
        for (int p = 0; p < 4; p++) {
            int gk = k0 + bkNN + p * 8, gn = bnNN;
            float4 v = make_float4(0.f, 0.f, 0.f, 0.f);
            if (gk < K && gn + 3 < Nc)
                v = *(const float4*)&Vb[(long)gk * 384 + gn];
            pb[p] = v;
        }
    };
    auto storeAV = [&](int st) {
        char* sb = smem_c + st * STAGE_B;
        #pragma unroll
        for (int p = 0; p < 2; p++) {
            int r = ar + p * 32;
            float vv[4] = {pa[p].x, pa[p].y, pa[p].z, pa[p].w};
            unsigned short h[4], l[4];
            #pragma unroll
            for (int j = 0; j < 4; j++) split_bf16(vv[j], h[j], l[j]);
            *(uint2*)(sb + r * A_PITCH_B + ak * 2) =
                make_uint2(((unsigned)h[1] << 16) | h[0], ((unsigned)h[3] << 16) | h[2]);
            *(uint2*)(sb + AL_OFF + r * A_PITCH_B + ak * 2) =
                make_uint2(((unsigned)l[1] << 16) | l[0], ((unsigned)l[3] << 16) | l[2]);
        }
        #pragma unroll
        for (int p = 0; p < 4; p++) {
            int k = bkNN + p * 8;
            float vv[4] = {pb[p].x, pb[p].y, pb[p].z, pb[p].w};
            unsigned short h[4], l[4];
            #pragma unroll
            for (int j = 0; j < 4; j++) split_bf16(vv[j], h[j], l[j]);
            *(uint2*)(sb + BH_OFF + k * BNN_PITCH_B + bnNN * 2) =
                make_uint2(((unsigned)h[1] << 16) | h[0], ((unsigned)h[3] << 16) | h[2]);
            *(uint2*)(sb + BL_OFF + k * BNN_PITCH_B + bnNN * 2) =
                make_uint2(((unsigned)l[1] << 16) | l[0], ((unsigned)l[3] << 16) | l[2]);
        }
    };

    float acc[2][4][4];
    #pragma unroll
    for (int im = 0; im < 2; im++)
        #pragma unroll
        for (int jn = 0; jn < 4; jn++)
            #pragma unroll
            for (int c = 0; c < 4; c++) acc[im][jn][c] = 0.f;

    int nch = (K + 31) / 32;
    int stage = 0;

    loadAs(0); loadBv(0);
    storeAV(0);
    __syncthreads();

    for (int c = 0; c < nch; c++) {
        if (c + 1 < nch) { loadAs((c + 1) * 32); loadBv((c + 1) * 32); }

        unsigned stb = sbase + stage * STAGE_B;
        #pragma unroll
        for (int ks2 = 0; ks2 < 2; ks2++) {
            int ksb = ks2 * 32;
            unsigned ah[2][4], al_[2][4];
            #pragma unroll
            for (int im = 0; im < 2; im++) {
                unsigned aaddr = stb
                    + (unsigned)((wm * 32 + im * 16 + (lane & 15)) * A_PITCH_B
                                 + ((lane >> 4) * 16) + ksb);
                LDSM4(ah[im][0], ah[im][1], ah[im][2], ah[im][3], aaddr);
                LDSM4(al_[im][0], al_[im][1], al_[im][2], al_[im][3], aaddr + AL_OFF);
            }
            unsigned bh[4][2], bl_[4][2];
            #pragma unroll
            for (int pr = 0; pr < 2; pr++) {
                int nb2 = wn * 32 + pr * 16;
                unsigned baddr = stb + BH_OFF
                    + (unsigned)((ks2 * 16 + ((lane >> 3) & 1) * 8 + (lane & 7)) * BNN_PITCH_B
                                 + (nb2 + (lane >> 4) * 8) * 2);
                unsigned r0, r1, r2, r3;
                LDSM4T(r0, r1, r2, r3, baddr);
                bh[2*pr][0] = r0; bh[2*pr][1] = r1; bh[2*pr+1][0] = r2; bh[2*pr+1][1] = r3;
                LDSM4T(r0, r1, r2, r3, baddr + (BL_OFF - BH_OFF));
                bl_[2*pr][0] = r0; bl_[2*pr][1] = r1; bl_[2*pr+1][0] = r2; bl_[2*pr+1][1] = r3;
            }
            #pragma unroll
            for (int im = 0; im < 2; im++)
                #pragma unroll
                for (int jn = 0; jn < 4; jn++) {
                    MMA_BF16(acc[im][jn], ah[im], bl_[jn]);
                    MMA_BF16(acc[im][jn], al_[im], bh[jn]);
                    MMA_BF16(acc[im][jn], ah[im], bh[jn]);
                }
        }

        if (c + 1 < nch) {
            storeAV(stage ^ 1);
            __syncthreads();
            stage ^= 1;
        }
    }

    #pragma unroll
    for (int im = 0; im < 2; im++) {
        #pragma unroll
        for (int jn = 0; jn < 4; jn++) {
            int r0 = row0 + wm * 32 + im * 16 + g;
            int c0 = wn * 32 + jn * 8 + 2 * tg;
            #pragma unroll
            for (int half = 0; half < 2; half++) {
                int gr = r0 + half * 8;
                if (gr >= NTOK) continue;
                #pragma unroll
                for (int cc = 0; cc < 2; cc++) {
                    int gn = c0 + cc;
                    Cb[(long)gr * DMODEL + gn] = acc[im][jn][half * 2 + cc];
                }
            }
        }
    }
}

// ---------------- split-K reduce + LN stats ----------------
__global__ void reduce_stats_k(const float* __restrict__ part, long sstride, int ns,
                               const float* __restrict__ bias, const float* __restrict__ res,
                               float* __restrict__ out,
                               float* __restrict__ mu, float* __restrict__ rstd)
{
    long row = blockIdx.x;
    int d = threadIdx.x;
    long idx = row * DMODEL + d;
    float s = 0.f;
    for (int k = 0; k < ns; k++) s += part[(long)k * sstride + idx];
    s += bias[d];
    if (res) s += res[idx];
    out[idx] = s;
    __shared__ float r1[4], r2[4];
    float v1 = s, v2 = s * s;
    #pragma unroll
    for (int o = 16; o > 0; o >>= 1) {
        v1 += __shfl_xor_sync(0xffffffffu, v1, o);
        v2 += __shfl_xor_sync(0xffffffffu, v2, o);
    }
    if ((d & 31) == 0) { r1[d >> 5] = v1; r2[d >> 5] = v2; }
    __syncthreads();
    if (d == 0) {
        float t1 = r1[0] + r1[1] + r1[2] + r1[3];
        float t2 = r2[0] + r2[1] + r2[2] + r2[3];
        float m = t1 * (1.f / 128.f);
        float var = t2 * (1.f / 128.f) - m * m;
        mu[row] = m;
        rstd[row] = rsqrtf(var + LNEPS);
    }
}

// ---------------- final LN + mean pool fused ----------------
__global__ void feats_k(const float* __restrict__ h, const float* __restrict__ mu,
                        const float* __restrict__ rstd,
                        const float* __restrict__ g, const float* __restrict__ b,
                        float* __restrict__ feats)
{
    int bb = blockIdx.x, d = threadIdx.x;
    float gd = g[d], bd = b[d];
    float s = 0.f;
    for (int n = 0; n < NTOK; n++) {
        long row = (long)bb * NTOK + n;
        s += (h[row * DMODEL + d] - mu[row]) * rstd[row] * gd + bd;
    }
    feats[bb * DMODEL + d] = s * (1.f / 196.f);
}

// ---------------- top-32: register-resident incremental argmax (fp16 src) ----
__global__ void __launch_bounds__(256) topk_k(const __half* __restrict__ msim,
                       float* __restrict__ mvals, int* __restrict__ midx)
{
    long row = blockIdx.x;
    int tid = threadIdx.x;
    int lane = tid & 31, wid = tid >> 5;
    const __half* src = msim + row * MKEYS;

    float v[32];
    const uint4* s4 = (const uint4*)(src + tid * 32);
    #pragma unroll
    for (int i = 0; i < 4; i++) {
        uint4 t = s4[i];
        unsigned w[4] = {t.x, t.y, t.z, t.w};
        #pragma unroll
        for (int j = 0; j < 4; j++) {
            __half2 h2 = *(__half2*)&w[j];
            float2 f2 = __half22float2(h2);
            v[i*8 + j*2 + 0] = f2.x;
            v[i*8 + j*2 + 1] = f2.y;
        }
    }

    unsigned long long p = 0ull;
    #pragma unroll
    for (int i = 0; i < 32; i++) {
        unsigned u = __float_as_uint(v[i]);
        u = (u & 0x80000000u) ? ~u : (u | 0x80000000u);
        unsigned long long key = ((unsigned long long)u << 32) | (unsigned)(MKEYS - 1 - (tid * 32 + i));
        if (key > p) p = key;
    }

    __shared__ unsigned long long wmax[2][8];

    for (int it = 0; it < TOPK; it++) {
        unsigned long long q = p;
        #pragma unroll
        for (int o = 16; o > 0; o >>= 1) {
            unsigned long long other = __shfl_xor_sync(0xffffffffu, q, o);
            if (other > q) q = other;
        }
        if (lane == 0) wmax[it & 1][wid] = q;
        __syncthreads();
        unsigned long long best = wmax[it & 1][0];
        #pragma unroll
        for (int w = 1; w < 8; w++) {
            unsigned long long o2 = wmax[it & 1][w];
            if (o2 > best) best = o2;
        }
        int gidx = MKEYS - 1 - (int)(best & 0xffffffffu);
        if (tid == (gidx >> 5)) {
            int sub = gidx & 31;
            float bv = 0.f;
            #pragma unroll
            for (int i = 0; i < 32; i++)
                if (i == sub) { bv = v[i]; v[i] = -3.4e38f; }
            mvals[row * TOPK + it] = bv;
            midx [row * TOPK + it] = gidx;
            unsigned long long np = 0ull;
            #pragma unroll
            for (int i = 0; i < 32; i++) {
                unsigned u = __float_as_uint(v[i]);
                u = (u & 0x80000000u) ? ~u : (u | 0x80000000u);
                unsigned long long key = ((unsigned long long)u << 32) | (unsigned)(MKEYS - 1 - (tid * 32 + i));
                if (key > np) np = key;
            }
            p = np;
        }
    }
}

// ---------------- kNN combine ----------------
__global__ void knn_combine_k(const float* __restrict__ att,
                              const float* __restrict__ mvals, const int* __restrict__ midx,
                              const float* __restrict__ qkv, const float* __restrict__ knn_v,
                              float* __restrict__ out)
{
    long row = blockIdx.x;
    int b = (int)(row / NTOK);
    int tid = threadIdx.x;
    __shared__ float w[TOPK + NTOK];
    __shared__ int   sidx[TOPK];
    __shared__ float red[4];

    if (tid < TOPK) {
        w[tid]    = mvals[row * TOPK + tid];
        sidx[tid] = midx [row * TOPK + tid];
    }
    for (int m = tid; m < NTOK; m += 128) w[TOPK + m] = att[row * NTOK + m];
    __syncthreads();

    float l0 = w[tid];
    float l1 = (tid < (TOPK + NTOK - 128)) ? w[tid + 128] : -3.4e38f;
    float m = fmaxf(l0, l1);
    #pragma unroll
    for (int o = 16; o > 0; o >>= 1) m = fmaxf(m, __shfl_xor_sync(0xffffffffu, m, o));
    if ((tid & 31) == 0) red[tid >> 5] = m;
    __syncthreads();
    m = fmaxf(fmaxf(red[0], red[1]), fmaxf(red[2], red[3]));
    float e0 = expf(l0 - m);
    float e1 = (tid < (TOPK + NTOK - 128)) ? expf(l1 - m) : 0.f;
    float s = e0 + e1;
    __syncthreads();
    #pragma unroll
    for (int o = 16; o > 0; o >>= 1) s += __shfl_xor_sync(0xffffffffu, s, o);
    if ((tid & 31) == 0) red[tid >> 5] = s;
    __syncthreads();
    s = red[0] + red[1] + red[2] + red[3];
    float inv = 1.f / s;
    w[tid] = e0 * inv;
    if (tid < (TOPK + NTOK - 128)) w[tid + 128] = e1 * inv;
    __syncthreads();

    float acc = 0.f;
    const float* kv = knn_v + (long)b * MKEYS * DMODEL;
    #pragma unroll 4
    for (int j = 0; j < TOPK; j++)
        acc += w[j] * kv[(long)sidx[j] * DMODEL + tid];
    const float* vbase = qkv + ((long)b * NTOK) * 384 + 256;
    for (int mm = 0; mm < NTOK; mm++)
        acc += w[TOPK + mm] * vbase[(long)mm * 384 + tid];
    out[row * DMODEL + tid] = acc;
}

// ---------------- launch ----------------
extern "C" void kernel_launch(void* const* d_in, const int* in_sizes, int n_in,
                              void* d_out, int out_size)
{
    const float* x       = (const float*)d_in[0];
    const float* patch_w = (const float*)d_in[1];
    const float* patch_b = (const float*)d_in[2];
    const float* ln1_g   = (const float*)d_in[3];
    const float* ln1_b   = (const float*)d_in[4];
    const float* qkv_w   = (const float*)d_in[5];
    const float* qkv_b   = (const float*)d_in[6];
    const float* out_w   = (const float*)d_in[7];
    const float* out_b   = (const float*)d_in[8];
    const float* ln2_g   = (const float*)d_in[9];
    const float* ln2_b   = (const float*)d_in[10];
    const float* ff1_w   = (const float*)d_in[11];
    const float* ff1_b   = (const float*)d_in[12];
    const float* ff2_w   = (const float*)d_in[13];
    const float* ff2_b   = (const float*)d_in[14];
    const float* lnf_g   = (const float*)d_in[15];
    const float* lnf_b   = (const float*)d_in[16];
    const float* knn_k   = (const float*)d_in[17];
    const float* knn_v   = (const float*)d_in[18];
    const float* head_w  = (const float*)d_in[19];
    const float* head_b  = (const float*)d_in[20];
    float* out = (float*)d_out;

    void* tp;
    cudaGetSymbolAddress(&tp, g_h);    float*  pH    = (float*)tp;
    cudaGetSymbolAddress(&tp, g_qkv);  float*  pQKV  = (float*)tp;
    cudaGetSymbolAddress(&tp, g_att);  float*  pATT  = (float*)tp;
    cudaGetSymbolAddress(&tp, g_msim); __half* pMSIM = (__half*)tp;
    cudaGetSymbolAddress(&tp, g_o);    float*  pO    = (float*)tp;
    cudaGetSymbolAddress(&tp, g_ff);   float*  pFF   = (float*)tp;
    cudaGetSymbolAddress(&tp, g_part); float*  pPart = (float*)tp;
    cudaGetSymbolAddress(&tp, g_mv);   float*  pMV   = (float*)tp;
    cudaGetSymbolAddress(&tp, g_mi);   int*    pMI   = (int*)tp;
    cudaGetSymbolAddress(&tp, g_feats);float*  pFeat = (float*)tp;
    cudaGetSymbolAddress(&tp, g_mu);   float*  pMu   = (float*)tp;
    cudaGetSymbolAddress(&tp, g_rs);   float*  pRs   = (float*)tp;

    cudaFuncSetAttribute(mmabf_k<false,false,false,false>, cudaFuncAttributeMaxDynamicSharedMemorySize, SMEM2);
    cudaFuncSetAttribute(mmabf_k<true, false,false,false>, cudaFuncAttributeMaxDynamicSharedMemorySize, SMEM2);
    cudaFuncSetAttribute(mmabf_k<false,false,true ,false>, cudaFuncAttributeMaxDynamicSharedMemorySize, SMEM2);
    cudaFuncSetAttribute(mmabf_k<false,true ,true ,false>, cudaFuncAttributeMaxDynamicSharedMemorySize, SMEM2);
    cudaFuncSetAttribute(mmabf_k<false,false,false,true >, cudaFuncAttributeMaxDynamicSharedMemorySize, SMEM2);
    cudaFuncSetAttribute(mmabf_k<false,false,false,false,true>, cudaFuncAttributeMaxDynamicSharedMemorySize, SMEM2);
    cudaFuncSetAttribute(attn_k, cudaFuncAttributeMaxDynamicSharedMemorySize, SMEM_AV);
    cudaFuncSetAttribute(msim2_k, cudaFuncAttributeMaxDynamicSharedMemorySize, M2_SMEM);

    const long sPart = (long)ROWS * DMODEL;

    // patch embed: fused gather (PATCHA) + split-K 3 (Kslice=256) -> reduce + ln1 stats
    mmabf_k<false,false,false,false,true><<<dim3(1, 98, 3), 256, SMEM2>>>(x, patch_w, nullptr, nullptr, pPart,
        ROWS, DMODEL, PDIM, 0, PDIM, 0, DMODEL, 0, DMODEL, 1.f, 1, 3, sPart,
        nullptr, nullptr, nullptr, nullptr, nullptr, nullptr);
    reduce_stats_k<<<ROWS, 128>>>(pPart, sPart, 3, patch_b, nullptr, pH, pMu, pRs);

    for (int i = 0; i < DEPTH; i++) {
        // qkv with inline ln1
        mmabf_k<false,false,true,false><<<dim3(3, 98, 1), 256, SMEM2>>>(pH, qkv_w + (long)i * DMODEL * 3 * DMODEL,
            qkv_b + i * 3 * DMODEL, nullptr, pQKV,
            ROWS, 3 * DMODEL, DMODEL, 0, DMODEL, 0, 3 * DMODEL, 0, 3 * DMODEL, 1.f, 1, 1, 0,
            pMu, pRs, ln1_g + i * DMODEL, ln1_b + i * DMODEL, nullptr, nullptr);

        if (i == KNN_LAYER) {
            // sim (raw logits for knn_combine)
            mmabf_k<true,false,false,false><<<dim3(2, 4, BATCH), 256, SMEM2>>>(pQKV, pQKV + 128, nullptr, nullptr, pATT,
                NTOK, NTOK, DMODEL,
                (long)NTOK * 384, 384, (long)NTOK * 384, 384, (long)NTOK * NTOK, NTOK, SCALE, BATCH, 1, 0,
                nullptr, nullptr, nullptr, nullptr, nullptr, nullptr);
            // msim (persistent-B, fp16 output)
            msim2_k<<<dim3(MKEYS / 128, 1, BATCH), 256, M2_SMEM>>>(pQKV, knn_k, pMSIM);
            topk_k<<<ROWS, 256>>>(pMSIM, pMV, pMI);
            knn_combine_k<<<ROWS, 128>>>(pATT, pMV, pMI, pQKV, knn_v, pO);
        } else {
            // fused sim + softmax + av
            attn_k<<<dim3(1, 4, BATCH), 256, SMEM_AV>>>(pQKV, pO, BATCH);
        }

        // h = h + o @ out_w + out_b ; epilogue emits ln2 stats
        mmabf_k<false,false,false,true><<<dim3(1, 98, 1), 256, SMEM2>>>(pO, out_w + (long)i * DMODEL * DMODEL,
            out_b + i * DMODEL, pH, pH,
            ROWS, DMODEL, DMODEL, 0, DMODEL, 0, DMODEL, 0, DMODEL, 1.f, 1, 1, 0,
            nullptr, nullptr, nullptr, nullptr, pMu, pRs);

        // ff1 + gelu with inline ln2
        mmabf_k<false,true,true,false><<<dim3(4, 98, 1), 256, SMEM2>>>(pH, ff1_w + (long)i * DMODEL * FFH,
            ff1_b + i * FFH, nullptr, pFF,
            ROWS, FFH, DMODEL, 0, DMODEL, 0, FFH, 0, FFH, 1.f, 1, 1, 0,
            pMu, pRs, ln2_g + i * DMODEL, ln2_b + i * DMODEL, nullptr, nullptr);
        // ff2: split-K 4, reduce adds bias + residual h, emits next ln1 stats
        mmabf_k<false,false,false,false><<<dim3(1, 98, 4), 256, SMEM2>>>(pFF, ff2_w + (long)i * FFH * DMODEL,
            nullptr, nullptr, pPart,
            ROWS, DMODEL, FFH, 0, FFH, 0, DMODEL, 0, DMODEL, 1.f, 1, 4, sPart,
            nullptr, nullptr, nullptr, nullptr, nullptr, nullptr);
        reduce_stats_k<<<ROWS, 128>>>(pPart, sPart, 4, ff2_b + i * DMODEL, pH, pH, pMu, pRs);
    }

    // final LN + mean pool, then head
    feats_k<<<BATCH, 128>>>(pH, pMu, pRs, lnf_g, lnf_b, pFeat);
    mmabf_k<false,false,false,false><<<dim3(8, 1, 1), 256, SMEM2>>>(pFeat, head_w, head_b, nullptr, out,
        BATCH, NCLS, DMODEL, 0, DMODEL, 0, NCLS, 0, NCLS, 1.f, 1, 1, 0,
        nullptr, nullptr, nullptr, nullptr, nullptr, nullptr);
}